// round 3
// baseline (speedup 1.0000x reference)
#include <cuda_runtime.h>
#include <math.h>

#define BB  32
#define MM  2048
#define QSd 1024
#define KSd 1024
#define Hd  1024
#define CSd 128
#define RR  (BB*MM)     // 65536 rows
#define G3  384

// ---- scratch (static device globals: no allocations allowed) ----
static __device__ float g_q[BB*Hd];                 // query@Wq + bq + bk + bc
static __device__ float g_qc[BB*Hd];                // query@Wqc + bqc + bkc + bcc + bac
static __device__ float g_big[(size_t)RR*Hd];       // t, then reused for cu
static __device__ float g_GX[(size_t)RR*G3];
static __device__ float g_GH[(size_t)RR*G3];
static __device__ float g_scores[RR];

// ============================================================
// K0: q / qc projections, biases folded in. One warp per (b,h).
// ============================================================
__global__ void qprep(const float* __restrict__ query,
                      const float* __restrict__ Wq,  const float* __restrict__ bq,
                      const float* __restrict__ bk,  const float* __restrict__ bc,
                      const float* __restrict__ Wqc, const float* __restrict__ bqc,
                      const float* __restrict__ bkc, const float* __restrict__ bcc,
                      const float* __restrict__ bac)
{
    int gw   = (blockIdx.x * blockDim.x + threadIdx.x) >> 5;
    int lane = threadIdx.x & 31;
    if (gw >= BB*Hd) return;
    int b = gw >> 10, h = gw & 1023;
    const float* q  = query + (size_t)b * QSd;
    const float* w1 = Wq  + (size_t)h * QSd;
    const float* w2 = Wqc + (size_t)h * QSd;
    float a1 = 0.f, a2 = 0.f;
    for (int k = lane; k < QSd; k += 32) {
        float qv = q[k];
        a1 += qv * w1[k];
        a2 += qv * w2[k];
    }
    #pragma unroll
    for (int o = 16; o; o >>= 1) {
        a1 += __shfl_xor_sync(0xffffffffu, a1, o);
        a2 += __shfl_xor_sync(0xffffffffu, a2, o);
    }
    if (!lane) {
        g_q[gw]  = a1 + bq[h]  + bk[h]  + bc[h];
        g_qc[gw] = a2 + bqc[h] + bkc[h] + bcc[h] + bac[h];
    }
}

// ============================================================
// Generic concat-K GEMM: C[r][c] = sum_k A(r,k) * W(c,k)
//   k <  K1 : A1 (stride sa1), W1 (stride sw1)
//   k >= K1 : A2 (stride sa2), W2 (stride sw2)
// 128x128 block tile, BK=8, 256 threads, 8x8 per thread.
// MODE 0: C = tanh(acc + g_q[b][c])            -> g_big   (t)
// MODE 1: C = acc + g_qc[b][c] + w[r]*Wac[c]   -> g_big   (cu)
// MODE 2: A = g_big (cu), C = acc + bias[c]    -> g_GX
// MODE 3: C = acc + bias[c]                    -> g_GH
// ============================================================
template<int MODE>
__global__ __launch_bounds__(256)
void gemm_k(const float* __restrict__ A1, int sa1,
            const float* __restrict__ A2, int sa2,
            const float* __restrict__ W1, int sw1,
            const float* __restrict__ W2, int sw2,
            int K1, int Ktot,
            const float* __restrict__ vecScale,   // MODE 1: Wac [H]
            const float* __restrict__ rowScale,   // MODE 1: weights [R]
            const float* __restrict__ bias)       // MODE 2/3
{
    __shared__ float as[8][132];
    __shared__ float bs[8][132];
    const int tid = threadIdx.x;
    const int tx  = tid & 15;
    const int ty  = tid >> 4;
    const int row0 = blockIdx.y * 128;
    const int col0 = blockIdx.x * 128;
    const int lr = tid >> 1;          // 0..127
    const int lk = (tid & 1) * 4;     // 0 or 4

    const float* Abase = (MODE == 2) ? (const float*)g_big : A1;

    float acc[8][8];
    #pragma unroll
    for (int i = 0; i < 8; ++i)
        #pragma unroll
        for (int j = 0; j < 8; ++j) acc[i][j] = 0.f;

    for (int k0 = 0; k0 < Ktot; k0 += 8) {
        float4 av, wv;
        if (k0 < K1) {
            av = *(const float4*)(Abase + (size_t)(row0 + lr) * sa1 + (k0 + lk));
            wv = *(const float4*)(W1    + (size_t)(col0 + lr) * sw1 + (k0 + lk));
        } else {
            av = *(const float4*)(A2 + (size_t)(row0 + lr) * sa2 + (k0 - K1 + lk));
            wv = *(const float4*)(W2 + (size_t)(col0 + lr) * sw2 + (k0 - K1 + lk));
        }
        __syncthreads();
        as[lk+0][lr] = av.x; as[lk+1][lr] = av.y; as[lk+2][lr] = av.z; as[lk+3][lr] = av.w;
        bs[lk+0][lr] = wv.x; bs[lk+1][lr] = wv.y; bs[lk+2][lr] = wv.z; bs[lk+3][lr] = wv.w;
        __syncthreads();
        #pragma unroll
        for (int kk = 0; kk < 8; ++kk) {
            float4 a0 = *(const float4*)&as[kk][ty*4];
            float4 a1 = *(const float4*)&as[kk][64 + ty*4];
            float4 b0 = *(const float4*)&bs[kk][tx*4];
            float4 b1 = *(const float4*)&bs[kk][64 + tx*4];
            float ar[8] = {a0.x,a0.y,a0.z,a0.w,a1.x,a1.y,a1.z,a1.w};
            float br[8] = {b0.x,b0.y,b0.z,b0.w,b1.x,b1.y,b1.z,b1.w};
            #pragma unroll
            for (int i = 0; i < 8; ++i)
                #pragma unroll
                for (int j = 0; j < 8; ++j)
                    acc[i][j] += ar[i] * br[j];
        }
    }

    const int ldc = (MODE <= 1) ? Hd : G3;
    float* Cp = (MODE <= 1) ? g_big : (MODE == 2 ? g_GX : g_GH);
    #pragma unroll
    for (int i = 0; i < 8; ++i) {
        int r = row0 + ((i < 4) ? (ty*4 + i) : (64 + ty*4 + (i - 4)));
        #pragma unroll
        for (int jh = 0; jh < 2; ++jh) {
            int cbase = col0 + jh*64 + tx*4;
            float4 v;
            float* vp = &v.x;
            #pragma unroll
            for (int j = 0; j < 4; ++j) {
                float x = acc[i][jh*4 + j];
                int c = cbase + j;
                if (MODE == 0) {
                    int b = r >> 11;                       // r / M
                    x = tanhf(x + g_q[b*Hd + c]);
                } else if (MODE == 1) {
                    int b = r >> 11;
                    x = x + g_qc[b*Hd + c] + rowScale[r] * vecScale[c];
                } else {
                    x = x + bias[c];
                }
                vp[j] = x;
            }
            *(float4*)(Cp + (size_t)r * ldc + cbase) = v;
        }
    }
}

// ============================================================
// scores[r] = sum_h t[r][h]*Wl[h] + bl   (one warp per row)
// ============================================================
__global__ void score_reduce(const float* __restrict__ Wl, const float* __restrict__ bl)
{
    int g    = blockIdx.x * (blockDim.x >> 5) + (threadIdx.x >> 5);
    int lane = threadIdx.x & 31;
    if (g >= RR) return;
    const float* t = g_big + (size_t)g * Hd;
    float a = 0.f;
    for (int h = lane; h < Hd; h += 32) a += t[h] * Wl[h];
    #pragma unroll
    for (int o = 16; o; o >>= 1) a += __shfl_xor_sync(0xffffffffu, a, o);
    if (!lane) g_scores[g] = a + bl[0];
}

// ============================================================
// masked softmax over M per batch. Mask dtype auto-detected:
// if every byte at offset %4 != 0 within the first 64KB is zero,
// the buffer is int32; else it is 1-byte bool.
// ============================================================
__global__ void softmax_k(const void* __restrict__ maskp, float* __restrict__ wout)
{
    __shared__ float sv[MM];
    __shared__ float red[256];
    __shared__ unsigned int ured[256];
    const int b = blockIdx.x;
    const int tid = threadIdx.x;

    const unsigned char* mb = (const unsigned char*)maskp;
    unsigned int orr = 0;
    for (int i = tid; i < BB*MM; i += 256)
        if (i & 3) orr |= mb[i];
    ured[tid] = orr;
    __syncthreads();
    for (int s = 128; s; s >>= 1) { if (tid < s) ured[tid] |= ured[tid + s]; __syncthreads(); }
    const bool isI32 = (ured[0] == 0);
    __syncthreads();

    for (int m = tid; m < MM; m += 256) {
        bool pad = isI32 ? (((const int*)maskp)[b*MM + m] != 0)
                         : (mb[b*MM + m] != 0);
        sv[m] = pad ? -1e30f : g_scores[b*MM + m];
    }
    __syncthreads();

    float mx = -3.4e38f;
    for (int m = tid; m < MM; m += 256) mx = fmaxf(mx, sv[m]);
    red[tid] = mx;
    __syncthreads();
    for (int s = 128; s; s >>= 1) { if (tid < s) red[tid] = fmaxf(red[tid], red[tid + s]); __syncthreads(); }
    mx = red[0];
    __syncthreads();

    float sum = 0.f;
    for (int m = tid; m < MM; m += 256) { float e = expf(sv[m] - mx); sv[m] = e; sum += e; }
    red[tid] = sum;
    __syncthreads();
    for (int s = 128; s; s >>= 1) { if (tid < s) red[tid] += red[tid + s]; __syncthreads(); }
    float inv = 1.f / red[0];
    __syncthreads();

    for (int m = tid; m < MM; m += 256) wout[b*MM + m] = sv[m] * inv;
}

// ============================================================
// attns[b][k] = sum_m w[b][m] * memory[b][m][k]
// ============================================================
__global__ void attns_k(const float* __restrict__ memory,
                        const float* __restrict__ w,
                        float* __restrict__ out)
{
    __shared__ float ws[MM];
    const int b = blockIdx.x;
    const int k = blockIdx.y * 256 + threadIdx.x;
    for (int i = threadIdx.x; i < MM; i += 256) ws[i] = w[b*MM + i];
    __syncthreads();
    const float* mp = memory + (size_t)b * MM * KSd + k;
    float a0 = 0.f, a1 = 0.f, a2 = 0.f, a3 = 0.f;
    for (int m = 0; m < MM; m += 4) {
        a0 += ws[m+0] * mp[(size_t)(m+0) * KSd];
        a1 += ws[m+1] * mp[(size_t)(m+1) * KSd];
        a2 += ws[m+2] * mp[(size_t)(m+2) * KSd];
        a3 += ws[m+3] * mp[(size_t)(m+3) * KSd];
    }
    out[b*KSd + k] = (a0 + a1) + (a2 + a3);
}

// ============================================================
// GRU elementwise: new_cov = (1-z)*n + z*cov
// gates ordered r,z,n in the 384-wide gx/gh
// ============================================================
__global__ void gru_k(const float* __restrict__ coverage, float* __restrict__ outc)
{
    size_t idx = (size_t)blockIdx.x * 256 + threadIdx.x;  // < RR*CSd
    int r = (int)(idx >> 7);
    int c = (int)(idx & 127);
    size_t gi = (size_t)r * G3 + c;
    float xr = g_GX[gi],       hr = g_GH[gi];
    float xz = g_GX[gi + 128], hz = g_GH[gi + 128];
    float xn = g_GX[gi + 256], hn = g_GH[gi + 256];
    float rg = 1.f / (1.f + expf(-(xr + hr)));
    float z  = 1.f / (1.f + expf(-(xz + hz)));
    float n  = tanhf(xn + rg * hn);
    outc[idx] = (1.f - z) * n + z * coverage[idx];
}

// ============================================================
extern "C" void kernel_launch(void* const* d_in, const int* in_sizes, int n_in,
                              void* d_out, int out_size)
{
    const float* query   = (const float*)d_in[0];
    const float* memory  = (const float*)d_in[1];
    const float* coverage= (const float*)d_in[2];
    const float* Wq  = (const float*)d_in[3];  const float* bq  = (const float*)d_in[4];
    const float* Wk  = (const float*)d_in[5];  const float* bk  = (const float*)d_in[6];
    const float* Wc  = (const float*)d_in[7];  const float* bc  = (const float*)d_in[8];
    const float* Wcc = (const float*)d_in[9];  const float* bcc = (const float*)d_in[10];
    const float* Wqc = (const float*)d_in[11]; const float* bqc = (const float*)d_in[12];
    const float* Wkc = (const float*)d_in[13]; const float* bkc = (const float*)d_in[14];
    const float* Wac = (const float*)d_in[15]; const float* bac = (const float*)d_in[16];
    const float* Wl  = (const float*)d_in[17]; const float* bl  = (const float*)d_in[18];
    const float* gwih= (const float*)d_in[19]; const float* gbih= (const float*)d_in[20];
    const float* gwhh= (const float*)d_in[21]; const float* gbhh= (const float*)d_in[22];
    const void*  maskp = d_in[23];

    float* out      = (float*)d_out;
    float* out_attn = out;                       // [32,1024]
    float* out_w    = out + BB*KSd;              // [32,2048]
    float* out_cov  = out + BB*KSd + BB*MM;      // [32,2048,128]

    // 1) q/qc projections with folded biases
    qprep<<<(BB*Hd)/8, 256>>>(query, Wq, bq, bk, bc, Wqc, bqc, bkc, bcc, bac);

    // 2) t = tanh([memory|coverage] @ [Wk|Wc]^T + g_q)   -> g_big
    dim3 gA(Hd/128, RR/128);
    gemm_k<0><<<gA, 256>>>(memory, KSd, coverage, CSd,
                           Wk, KSd, Wc, CSd,
                           KSd, KSd + CSd, nullptr, nullptr, nullptr);

    // 3) scores
    score_reduce<<<RR/8, 256>>>(Wl, bl);

    // 4) masked softmax -> weights (written to d_out slice)
    softmax_k<<<BB, 256>>>(maskp, out_w);

    // 5) attns
    attns_k<<<dim3(BB, KSd/256), 256>>>(memory, out_w, out_attn);

    // 6) cu = [memory|coverage] @ [Wkc|Wcc]^T + g_qc + w*Wac  -> g_big
    gemm_k<1><<<gA, 256>>>(memory, KSd, coverage, CSd,
                           Wkc, KSd, Wcc, CSd,
                           KSd, KSd + CSd, Wac, out_w, nullptr);

    // 7) gx = cu @ gru_wih^T + bih ; gh = coverage @ gru_whh^T + bhh
    dim3 gG(G3/128, RR/128);
    gemm_k<2><<<gG, 256>>>(nullptr, Hd, nullptr, 0,
                           gwih, Hd, nullptr, 0,
                           Hd, Hd, nullptr, nullptr, gbih);
    gemm_k<3><<<gG, 256>>>(coverage, CSd, nullptr, 0,
                           gwhh, CSd, nullptr, 0,
                           CSd, CSd, nullptr, nullptr, gbhh);

    // 8) GRU elementwise -> new_coverage
    gru_k<<<(RR*CSd)/256, 256>>>(coverage, out_cov);
}

// round 4
// speedup vs baseline: 1.5995x; 1.5995x over previous
#include <cuda_runtime.h>
#include <math.h>

#define BB  32
#define MM  2048
#define QSd 1024
#define KSd 1024
#define Hd  1024
#define CSd 128
#define RR  (BB*MM)     // 65536 rows
#define G3  384
#define KC  1152        // concat K = KS + CS

typedef unsigned long long ull;

// ---- scratch (static device globals) ----
static __device__ float g_q[BB*Hd];                 // q@Wq + bq+bk+bc
static __device__ float g_qc[BB*Hd];                // q@Wqc + bqc+bkc+bcc+bac
static __device__ float g_qg2[BB*G3];               // g_qc @ wih^T + bih
static __device__ float g_av[G3];                   // Wac @ wih^T
static __device__ float g_Wf[(size_t)G3*KC];        // wih @ [Wkc|Wcc]  (fused weight)
static __device__ float g_part[(size_t)RR*8];       // per-coltile score partials
static __device__ float g_GX[(size_t)RR*G3];
static __device__ float g_GH[(size_t)RR*G3];

// ---- packed f32x2 helpers ----
__device__ __forceinline__ ull dup2(float x){
    ull r; asm("mov.b64 %0, {%1, %1};" : "=l"(r) : "f"(x)); return r;
}
__device__ __forceinline__ ull ffma2(ull a, ull b, ull c){
    ull d; asm("fma.rn.f32x2 %0, %1, %2, %3;" : "=l"(d) : "l"(a), "l"(b), "l"(c)); return d;
}
__device__ __forceinline__ void unpk(ull v, float& lo, float& hi){
    asm("mov.b64 {%0, %1}, %2;" : "=f"(lo), "=f"(hi) : "l"(v));
}

// shared inner-product core: 128x128 tile, BK=8, 8x8/thread as 8x4 packed pairs
#define COMPUTE8                                                        \
    _Pragma("unroll")                                                   \
    for (int kk = 0; kk < 8; ++kk) {                                    \
        float4 a0 = *(const float4*)&as[kk][ty*4];                      \
        float4 a1 = *(const float4*)&as[kk][64 + ty*4];                 \
        ulonglong2 bp0 = *(const ulonglong2*)&bs[kk][tx*4];             \
        ulonglong2 bp1 = *(const ulonglong2*)&bs[kk][64 + tx*4];        \
        float afr[8] = {a0.x,a0.y,a0.z,a0.w,a1.x,a1.y,a1.z,a1.w};       \
        _Pragma("unroll")                                               \
        for (int i = 0; i < 8; ++i) {                                   \
            ull Ai = dup2(afr[i]);                                      \
            acc[i][0] = ffma2(Ai, bp0.x, acc[i][0]);                    \
            acc[i][1] = ffma2(Ai, bp0.y, acc[i][1]);                    \
            acc[i][2] = ffma2(Ai, bp1.x, acc[i][2]);                    \
            acc[i][3] = ffma2(Ai, bp1.y, acc[i][3]);                    \
        }                                                               \
    }

// ============================================================
// K0: q / qc projections, biases folded. One warp per (b,h).
// ============================================================
__global__ void qprep(const float* __restrict__ query,
                      const float* __restrict__ Wq,  const float* __restrict__ bq,
                      const float* __restrict__ bk,  const float* __restrict__ bc,
                      const float* __restrict__ Wqc, const float* __restrict__ bqc,
                      const float* __restrict__ bkc, const float* __restrict__ bcc,
                      const float* __restrict__ bac)
{
    int gw   = (blockIdx.x * blockDim.x + threadIdx.x) >> 5;
    int lane = threadIdx.x & 31;
    if (gw >= BB*Hd) return;
    int b = gw >> 10, h = gw & 1023;
    const float* q  = query + (size_t)b * QSd;
    const float* w1 = Wq  + (size_t)h * QSd;
    const float* w2 = Wqc + (size_t)h * QSd;
    float a1 = 0.f, a2 = 0.f;
    for (int k = lane; k < QSd; k += 32) {
        float qv = q[k];
        a1 += qv * w1[k];
        a2 += qv * w2[k];
    }
    #pragma unroll
    for (int o = 16; o; o >>= 1) {
        a1 += __shfl_xor_sync(0xffffffffu, a1, o);
        a2 += __shfl_xor_sync(0xffffffffu, a2, o);
    }
    if (!lane) {
        g_q[gw]  = a1 + bq[h]  + bk[h]  + bc[h];
        g_qc[gw] = a2 + bqc[h] + bkc[h] + bcc[h] + bac[h];
    }
}

// ============================================================
// prep2: qg2[b][g] = g_qc[b]·wih[g] + bih[g] ;  av[g] = Wac·wih[g]
// warp per output; 33*384 outputs.
// ============================================================
__global__ void prep2(const float* __restrict__ wih, const float* __restrict__ bih,
                      const float* __restrict__ Wac)
{
    int gw   = (blockIdx.x * blockDim.x + threadIdx.x) >> 5;
    int lane = threadIdx.x & 31;
    if (gw >= 33*G3) return;
    if (gw < 32*G3) {
        int b = gw / G3, g = gw % G3;
        const float* x  = g_qc + (size_t)b * Hd;
        const float* wr = wih  + (size_t)g * Hd;
        float a = 0.f;
        for (int h = lane; h < Hd; h += 32) a += x[h] * wr[h];
        #pragma unroll
        for (int o = 16; o; o >>= 1) a += __shfl_xor_sync(0xffffffffu, a, o);
        if (!lane) g_qg2[gw] = a + bih[g];
    } else {
        int g = gw - 32*G3;
        const float* wr = wih + (size_t)g * Hd;
        float a = 0.f;
        for (int h = lane; h < Hd; h += 32) a += Wac[h] * wr[h];
        #pragma unroll
        for (int o = 16; o; o >>= 1) a += __shfl_xor_sync(0xffffffffu, a, o);
        if (!lane) g_av[g] = a;
    }
}

// ============================================================
// kernelA: blocks [0,27): Wfuse = wih @ [Wkc|Wcc]  (transposed-W access)
//          blocks [27, 27+4096): scores GEMM with fused tanh·Wl epilogue
// ============================================================
__global__ __launch_bounds__(256)
void kernelA(const float* __restrict__ memory, const float* __restrict__ coverage,
             const float* __restrict__ Wk,  const float* __restrict__ Wc,
             const float* __restrict__ Wkc, const float* __restrict__ Wcc,
             const float* __restrict__ wih, const float* __restrict__ Wl)
{
    __shared__ __align__(16) float as[8][132];
    __shared__ __align__(16) float bs[8][132];
    const int tid = threadIdx.x;
    const int tx = tid & 15, ty = tid >> 4;
    const int lr = tid >> 1, lk = (tid & 1) * 4;

    ull acc[8][4];
    #pragma unroll
    for (int i = 0; i < 8; ++i)
        #pragma unroll
        for (int j = 0; j < 4; ++j) acc[i][j] = 0ull;

    int bid = blockIdx.x;
    if (bid < 27) {
        // ---- Wfuse[g][k_out] = sum_h wih[g][h] * Wcat[h][k_out] ----
        const int row0 = (bid / 9) * 128;   // g
        const int col0 = (bid % 9) * 128;   // k_out (0..1151)
        const int kk8 = tid >> 5, c4 = (tid & 31) * 4;
        for (int k0 = 0; k0 < Hd; k0 += 8) {
            float4 av4 = *(const float4*)(wih + (size_t)(row0 + lr) * Hd + k0 + lk);
            float4 wv;
            if (col0 < KSd)
                wv = *(const float4*)(Wkc + (size_t)(k0 + kk8) * KSd + col0 + c4);
            else
                wv = *(const float4*)(Wcc + (size_t)(k0 + kk8) * CSd + (col0 - KSd) + c4);
            __syncthreads();
            as[lk+0][lr] = av4.x; as[lk+1][lr] = av4.y;
            as[lk+2][lr] = av4.z; as[lk+3][lr] = av4.w;
            *(float4*)&bs[kk8][c4] = wv;
            __syncthreads();
            COMPUTE8;
        }
        #pragma unroll
        for (int i = 0; i < 8; ++i) {
            int r = row0 + ((i < 4) ? (ty*4 + i) : (64 + ty*4 + i - 4));
            ulonglong2 v0; v0.x = acc[i][0]; v0.y = acc[i][1];
            ulonglong2 v1; v1.x = acc[i][2]; v1.y = acc[i][3];
            *(ulonglong2*)(g_Wf + (size_t)r * KC + col0 + tx*4)      = v0;
            *(ulonglong2*)(g_Wf + (size_t)r * KC + col0 + 64 + tx*4) = v1;
        }
    } else {
        // ---- scores GEMM: [mem|cov] @ [Wk|Wc]^T, epilogue tanh(.+g_q)·Wl ----
        bid -= 27;
        const int cb   = bid & 7;
        const int col0 = cb * 128;
        const int row0 = (bid >> 3) * 128;
        const int b    = row0 >> 11;
        for (int k0 = 0; k0 < KC; k0 += 8) {
            float4 av4, wv;
            if (k0 < KSd) {
                av4 = *(const float4*)(memory + (size_t)(row0 + lr) * KSd + k0 + lk);
                wv  = *(const float4*)(Wk     + (size_t)(col0 + lr) * KSd + k0 + lk);
            } else {
                av4 = *(const float4*)(coverage + (size_t)(row0 + lr) * CSd + (k0 - KSd) + lk);
                wv  = *(const float4*)(Wc       + (size_t)(col0 + lr) * CSd + (k0 - KSd) + lk);
            }
            __syncthreads();
            as[lk+0][lr] = av4.x; as[lk+1][lr] = av4.y;
            as[lk+2][lr] = av4.z; as[lk+3][lr] = av4.w;
            bs[lk+0][lr] = wv.x;  bs[lk+1][lr] = wv.y;
            bs[lk+2][lr] = wv.z;  bs[lk+3][lr] = wv.w;
            __syncthreads();
            COMPUTE8;
        }
        #pragma unroll
        for (int i = 0; i < 8; ++i) {
            int r = row0 + ((i < 4) ? (ty*4 + i) : (64 + ty*4 + i - 4));
            float s = 0.f;
            #pragma unroll
            for (int jp = 0; jp < 4; ++jp) {
                float x0, x1; unpk(acc[i][jp], x0, x1);
                int c = col0 + ((jp >> 1) * 64) + tx*4 + (jp & 1) * 2;
                s += tanhf(x0 + g_q[b*Hd + c    ]) * Wl[c    ];
                s += tanhf(x1 + g_q[b*Hd + c + 1]) * Wl[c + 1];
            }
            #pragma unroll
            for (int o = 1; o < 16; o <<= 1) s += __shfl_xor_sync(0xffffffffu, s, o);
            if (tx == 0) g_part[(size_t)r * 8 + cb] = s;
        }
    }
}

// ============================================================
// kernelB: blocks [0,1536): gx = [mem|cov]@Wfuse^T + qg2 + w·av -> g_GX
//          blocks [1536,3072): gh = cov@gwhh^T + bhh            -> g_GH
// ============================================================
__global__ __launch_bounds__(256)
void kernelB(const float* __restrict__ memory, const float* __restrict__ coverage,
             const float* __restrict__ gwhh, const float* __restrict__ gbhh,
             const float* __restrict__ w)
{
    __shared__ __align__(16) float as[8][132];
    __shared__ __align__(16) float bs[8][132];
    const int tid = threadIdx.x;
    const int tx = tid & 15, ty = tid >> 4;
    const int lr = tid >> 1, lk = (tid & 1) * 4;

    ull acc[8][4];
    #pragma unroll
    for (int i = 0; i < 8; ++i)
        #pragma unroll
        for (int j = 0; j < 4; ++j) acc[i][j] = 0ull;

    int bid = blockIdx.x;
    const bool isGX = bid < 1536;
    if (!isGX) bid -= 1536;
    const int col0 = (bid % 3) * 128;
    const int row0 = (bid / 3) * 128;

    if (isGX) {
        for (int k0 = 0; k0 < KC; k0 += 8) {
            float4 av4;
            if (k0 < KSd)
                av4 = *(const float4*)(memory + (size_t)(row0 + lr) * KSd + k0 + lk);
            else
                av4 = *(const float4*)(coverage + (size_t)(row0 + lr) * CSd + (k0 - KSd) + lk);
            float4 wv = *(const float4*)(g_Wf + (size_t)(col0 + lr) * KC + k0 + lk);
            __syncthreads();
            as[lk+0][lr] = av4.x; as[lk+1][lr] = av4.y;
            as[lk+2][lr] = av4.z; as[lk+3][lr] = av4.w;
            bs[lk+0][lr] = wv.x;  bs[lk+1][lr] = wv.y;
            bs[lk+2][lr] = wv.z;  bs[lk+3][lr] = wv.w;
            __syncthreads();
            COMPUTE8;
        }
        const int b = row0 >> 11;
        #pragma unroll
        for (int i = 0; i < 8; ++i) {
            int r = row0 + ((i < 4) ? (ty*4 + i) : (64 + ty*4 + i - 4));
            float wr = w[r];
            #pragma unroll
            for (int jh = 0; jh < 2; ++jh) {
                int cbase = col0 + jh*64 + tx*4;
                float x0, x1, x2, x3;
                unpk(acc[i][jh*2],   x0, x1);
                unpk(acc[i][jh*2+1], x2, x3);
                float4 v;
                v.x = x0 + g_qg2[b*G3 + cbase+0] + wr * g_av[cbase+0];
                v.y = x1 + g_qg2[b*G3 + cbase+1] + wr * g_av[cbase+1];
                v.z = x2 + g_qg2[b*G3 + cbase+2] + wr * g_av[cbase+2];
                v.w = x3 + g_qg2[b*G3 + cbase+3] + wr * g_av[cbase+3];
                *(float4*)(g_GX + (size_t)r * G3 + cbase) = v;
            }
        }
    } else {
        for (int k0 = 0; k0 < CSd; k0 += 8) {
            float4 av4 = *(const float4*)(coverage + (size_t)(row0 + lr) * CSd + k0 + lk);
            float4 wv  = *(const float4*)(gwhh     + (size_t)(col0 + lr) * CSd + k0 + lk);
            __syncthreads();
            as[lk+0][lr] = av4.x; as[lk+1][lr] = av4.y;
            as[lk+2][lr] = av4.z; as[lk+3][lr] = av4.w;
            bs[lk+0][lr] = wv.x;  bs[lk+1][lr] = wv.y;
            bs[lk+2][lr] = wv.z;  bs[lk+3][lr] = wv.w;
            __syncthreads();
            COMPUTE8;
        }
        #pragma unroll
        for (int i = 0; i < 8; ++i) {
            int r = row0 + ((i < 4) ? (ty*4 + i) : (64 + ty*4 + i - 4));
            #pragma unroll
            for (int jh = 0; jh < 2; ++jh) {
                int cbase = col0 + jh*64 + tx*4;
                float x0, x1, x2, x3;
                unpk(acc[i][jh*2],   x0, x1);
                unpk(acc[i][jh*2+1], x2, x3);
                float4 v;
                v.x = x0 + gbhh[cbase+0];
                v.y = x1 + gbhh[cbase+1];
                v.z = x2 + gbhh[cbase+2];
                v.w = x3 + gbhh[cbase+3];
                *(float4*)(g_GH + (size_t)r * G3 + cbase) = v;
            }
        }
    }
}

// ============================================================
// masked softmax; scores assembled from 8 fixed-order partials + bl.
// mask dtype auto-detected (i32 vs u8) as before.
// ============================================================
__global__ void softmax_k(const void* __restrict__ maskp, const float* __restrict__ bl,
                          float* __restrict__ wout)
{
    __shared__ float sv[MM];
    __shared__ float red[256];
    __shared__ unsigned int ured[256];
    const int b = blockIdx.x;
    const int tid = threadIdx.x;

    const unsigned char* mb = (const unsigned char*)maskp;
    unsigned int orr = 0;
    for (int i = tid; i < BB*MM; i += 256)
        if (i & 3) orr |= mb[i];
    ured[tid] = orr;
    __syncthreads();
    for (int s = 128; s; s >>= 1) { if (tid < s) ured[tid] |= ured[tid + s]; __syncthreads(); }
    const bool isI32 = (ured[0] == 0);
    __syncthreads();

    const float blv = bl[0];
    for (int m = tid; m < MM; m += 256) {
        bool pad = isI32 ? (((const int*)maskp)[b*MM + m] != 0)
                         : (mb[b*MM + m] != 0);
        if (pad) sv[m] = -1e30f;
        else {
            const float* p = g_part + (size_t)(b*MM + m) * 8;
            sv[m] = ((p[0]+p[1]) + (p[2]+p[3])) + ((p[4]+p[5]) + (p[6]+p[7])) + blv;
        }
    }
    __syncthreads();

    float mx = -3.4e38f;
    for (int m = tid; m < MM; m += 256) mx = fmaxf(mx, sv[m]);
    red[tid] = mx;
    __syncthreads();
    for (int s = 128; s; s >>= 1) { if (tid < s) red[tid] = fmaxf(red[tid], red[tid + s]); __syncthreads(); }
    mx = red[0];
    __syncthreads();

    float sum = 0.f;
    for (int m = tid; m < MM; m += 256) { float e = expf(sv[m] - mx); sv[m] = e; sum += e; }
    red[tid] = sum;
    __syncthreads();
    for (int s = 128; s; s >>= 1) { if (tid < s) red[tid] += red[tid + s]; __syncthreads(); }
    float inv = 1.f / red[0];
    __syncthreads();

    for (int m = tid; m < MM; m += 256) wout[b*MM + m] = sv[m] * inv;
}

// ============================================================
// attns[b][k] = sum_m w[b][m] * memory[b][m][k]
// ============================================================
__global__ void attns_k(const float* __restrict__ memory,
                        const float* __restrict__ w,
                        float* __restrict__ out)
{
    __shared__ float ws[MM];
    const int b = blockIdx.x;
    const int k = blockIdx.y * 256 + threadIdx.x;
    for (int i = threadIdx.x; i < MM; i += 256) ws[i] = w[b*MM + i];
    __syncthreads();
    const float* mp = memory + (size_t)b * MM * KSd + k;
    float a0 = 0.f, a1 = 0.f, a2 = 0.f, a3 = 0.f;
    for (int m = 0; m < MM; m += 4) {
        a0 += ws[m+0] * mp[(size_t)(m+0) * KSd];
        a1 += ws[m+1] * mp[(size_t)(m+1) * KSd];
        a2 += ws[m+2] * mp[(size_t)(m+2) * KSd];
        a3 += ws[m+3] * mp[(size_t)(m+3) * KSd];
    }
    out[b*KSd + k] = (a0 + a1) + (a2 + a3);
}

// ============================================================
// GRU elementwise: new_cov = (1-z)*n + z*cov  (gates r,z,n)
// ============================================================
__global__ void gru_k(const float* __restrict__ coverage, float* __restrict__ outc)
{
    size_t idx = (size_t)blockIdx.x * 256 + threadIdx.x;
    int r = (int)(idx >> 7);
    int c = (int)(idx & 127);
    size_t gi = (size_t)r * G3 + c;
    float xr = g_GX[gi],       hr = g_GH[gi];
    float xz = g_GX[gi + 128], hz = g_GH[gi + 128];
    float xn = g_GX[gi + 256], hn = g_GH[gi + 256];
    float rg = 1.f / (1.f + expf(-(xr + hr)));
    float z  = 1.f / (1.f + expf(-(xz + hz)));
    float n  = tanhf(xn + rg * hn);
    outc[idx] = (1.f - z) * n + z * coverage[idx];
}

// ============================================================
extern "C" void kernel_launch(void* const* d_in, const int* in_sizes, int n_in,
                              void* d_out, int out_size)
{
    const float* query   = (const float*)d_in[0];
    const float* memory  = (const float*)d_in[1];
    const float* coverage= (const float*)d_in[2];
    const float* Wq  = (const float*)d_in[3];  const float* bq  = (const float*)d_in[4];
    const float* Wk  = (const float*)d_in[5];  const float* bk  = (const float*)d_in[6];
    const float* Wc  = (const float*)d_in[7];  const float* bc  = (const float*)d_in[8];
    const float* Wcc = (const float*)d_in[9];  const float* bcc = (const float*)d_in[10];
    const float* Wqc = (const float*)d_in[11]; const float* bqc = (const float*)d_in[12];
    const float* Wkc = (const float*)d_in[13]; const float* bkc = (const float*)d_in[14];
    const float* Wac = (const float*)d_in[15]; const float* bac = (const float*)d_in[16];
    const float* Wl  = (const float*)d_in[17]; const float* bl  = (const float*)d_in[18];
    const float* gwih= (const float*)d_in[19]; const float* gbih= (const float*)d_in[20];
    const float* gwhh= (const float*)d_in[21]; const float* gbhh= (const float*)d_in[22];
    const void*  maskp = d_in[23];

    float* out      = (float*)d_out;
    float* out_attn = out;                       // [32,1024]
    float* out_w    = out + BB*KSd;              // [32,2048]
    float* out_cov  = out + BB*KSd + BB*MM;      // [32,2048,128]

    // 1) q/qc projections with folded biases
    qprep<<<(BB*Hd)/8, 256>>>(query, Wq, bq, bk, bc, Wqc, bqc, bkc, bcc, bac);

    // 2) qg2 / av precontractions (needs g_qc)
    prep2<<<(33*G3*32 + 255)/256, 256>>>(gwih, gbih, Wac);

    // 3) fused: Wfuse (27 blocks) + scores GEMM w/ tanh·Wl epilogue (4096 blocks)
    kernelA<<<27 + (RR/128)*(Hd/128), 256>>>(memory, coverage, Wk, Wc, Wkc, Wcc, gwih, Wl);

    // 4) masked softmax -> weights (d_out slice)
    softmax_k<<<BB, 256>>>(maskp, bl, out_w);

    // 5) attns
    attns_k<<<dim3(BB, KSd/256), 256>>>(memory, out_w, out_attn);

    // 6) fused: gx (1536 blocks) + gh (1536 blocks)
    kernelB<<<3072, 256>>>(memory, coverage, gwhh, gbhh, out_w);

    // 7) GRU elementwise -> new_coverage
    gru_k<<<(RR*CSd)/256, 256>>>(coverage, out_cov);
}

// round 6
// speedup vs baseline: 2.7789x; 1.7373x over previous
#include <cuda_runtime.h>
#include <cuda_bf16.h>
#include <math.h>
#include <stdint.h>

#define BB  32
#define MM  2048
#define QSd 1024
#define KSd 1024
#define Hd  1024
#define CSd 128
#define RR  (BB*MM)     // 65536 rows
#define G3  384
#define KC  1152        // concat K = KS + CS

// ---------------- scratch (static device globals) ----------------
static __device__ float g_q[BB*Hd];
static __device__ float g_qc[BB*Hd];
static __device__ float g_qg2[BB*G3];
static __device__ float g_av[G3];
static __device__ float g_Wf[(size_t)G3*KC];
static __device__ float g_part[(size_t)RR*8];
static __device__ float g_GX[(size_t)RR*G3];
static __device__ float g_GH[(size_t)RR*G3];
// bf16 hi/lo split operands
static __device__ __nv_bfloat16 g_Ahi[(size_t)RR*KC];
static __device__ __nv_bfloat16 g_Alo[(size_t)RR*KC];
static __device__ __nv_bfloat16 g_WBhi[(size_t)1024*KC];
static __device__ __nv_bfloat16 g_WBlo[(size_t)1024*KC];
static __device__ __nv_bfloat16 g_WFhi[(size_t)G3*KC];
static __device__ __nv_bfloat16 g_WFlo[(size_t)G3*KC];
static __device__ __nv_bfloat16 g_WHhi[(size_t)G3*CSd];
static __device__ __nv_bfloat16 g_WHlo[(size_t)G3*CSd];

// ---------------- PTX helpers (base ISA only: sm_80+) ----------------
__device__ __forceinline__ uint32_t s2u(const void* p){
    uint32_t a;
    asm("{ .reg .u64 t; cvta.to.shared.u64 t, %1; cvt.u32.u64 %0, t; }" : "=r"(a) : "l"(p));
    return a;
}
#define CP16(dst, gsrc) \
    asm volatile("cp.async.cg.shared.global [%0], [%1], 16;" \
                 :: "r"(dst), "l"(__cvta_generic_to_global(gsrc)) : "memory")
#define CPCOMMIT() asm volatile("cp.async.commit_group;" ::: "memory")
#define CPWAIT1()  asm volatile("cp.async.wait_group 1;" ::: "memory")
#define CPWAIT0()  asm volatile("cp.async.wait_group 0;" ::: "memory")

__device__ __forceinline__ void ldsm4(uint32_t* r, uint32_t addr){
    asm volatile("ldmatrix.sync.aligned.m8n8.x4.shared.b16 {%0,%1,%2,%3}, [%4];"
        : "=r"(r[0]), "=r"(r[1]), "=r"(r[2]), "=r"(r[3]) : "r"(addr));
}
__device__ __forceinline__ void ldsm2(uint32_t* r, uint32_t addr){
    asm volatile("ldmatrix.sync.aligned.m8n8.x2.shared.b16 {%0,%1}, [%2];"
        : "=r"(r[0]), "=r"(r[1]) : "r"(addr));
}
__device__ __forceinline__ void mma16816(float* d, const uint32_t* a, const uint32_t* b){
    asm volatile("mma.sync.aligned.m16n8k16.row.col.f32.bf16.bf16.f32 "
        "{%0,%1,%2,%3}, {%4,%5,%6,%7}, {%8,%9}, {%0,%1,%2,%3};"
        : "+f"(d[0]), "+f"(d[1]), "+f"(d[2]), "+f"(d[3])
        : "r"(a[0]), "r"(a[1]), "r"(a[2]), "r"(a[3]), "r"(b[0]), "r"(b[1]));
}

// smem stage layout (bytes): row stride 80 (64B data + 16B pad, conflict-free)
#define SROW   80
#define TILE_B (128*SROW)          // 10240
#define STAGE_B (4*TILE_B)         // 40960
#define AHI_O  0
#define ALO_O  TILE_B
#define BHI_O  (2*TILE_B)
#define BLO_O  (3*TILE_B)
#define DSMB   (2*STAGE_B)         // 81920

// ============================================================
// qprep: q / qc projections, biases folded. Warp per (b,h).
// ============================================================
__global__ void qprep(const float* __restrict__ query,
                      const float* __restrict__ Wq,  const float* __restrict__ bq,
                      const float* __restrict__ bk,  const float* __restrict__ bc,
                      const float* __restrict__ Wqc, const float* __restrict__ bqc,
                      const float* __restrict__ bkc, const float* __restrict__ bcc,
                      const float* __restrict__ bac)
{
    int gw   = (blockIdx.x * blockDim.x + threadIdx.x) >> 5;
    int lane = threadIdx.x & 31;
    if (gw >= BB*Hd) return;
    int b = gw >> 10, h = gw & 1023;
    const float* q  = query + (size_t)b * QSd;
    const float* w1 = Wq  + (size_t)h * QSd;
    const float* w2 = Wqc + (size_t)h * QSd;
    float a1 = 0.f, a2 = 0.f;
    for (int k = lane; k < QSd; k += 32) {
        float qv = q[k];
        a1 += qv * w1[k];
        a2 += qv * w2[k];
    }
    #pragma unroll
    for (int o = 16; o; o >>= 1) {
        a1 += __shfl_xor_sync(0xffffffffu, a1, o);
        a2 += __shfl_xor_sync(0xffffffffu, a2, o);
    }
    if (!lane) {
        g_q[gw]  = a1 + bq[h]  + bk[h]  + bc[h];
        g_qc[gw] = a2 + bqc[h] + bkc[h] + bcc[h] + bac[h];
    }
}

// ============================================================
// prep2: qg2[b][g] = g_qc[b]·wih[g] + bih[g] ; av[g] = Wac·wih[g]
// ============================================================
__global__ void prep2(const float* __restrict__ wih, const float* __restrict__ bih,
                      const float* __restrict__ Wac)
{
    int gw   = (blockIdx.x * blockDim.x + threadIdx.x) >> 5;
    int lane = threadIdx.x & 31;
    if (gw >= 33*G3) return;
    if (gw < 32*G3) {
        int b = gw / G3, g = gw % G3;
        const float* x  = g_qc + (size_t)b * Hd;
        const float* wr = wih  + (size_t)g * Hd;
        float a = 0.f;
        for (int h = lane; h < Hd; h += 32) a += x[h] * wr[h];
        #pragma unroll
        for (int o = 16; o; o >>= 1) a += __shfl_xor_sync(0xffffffffu, a, o);
        if (!lane) g_qg2[gw] = a + bih[g];
    } else {
        int g = gw - 32*G3;
        const float* wr = wih + (size_t)g * Hd;
        float a = 0.f;
        for (int h = lane; h < Hd; h += 32) a += Wac[h] * wr[h];
        #pragma unroll
        for (int o = 16; o; o >>= 1) a += __shfl_xor_sync(0xffffffffu, a, o);
        if (!lane) g_av[g] = a;
    }
}

// ============================================================
// wfuse_k: g_Wf = wih @ [Wkc|Wcc]  (fp32 SIMT, 27 blocks, tiny)
// ============================================================
__global__ __launch_bounds__(256)
void wfuse_k(const float* __restrict__ Wkc, const float* __restrict__ Wcc,
             const float* __restrict__ wih)
{
    __shared__ __align__(16) float as[8][132];
    __shared__ __align__(16) float bs[8][132];
    const int tid = threadIdx.x;
    const int tx = tid & 15, ty = tid >> 4;
    const int lr = tid >> 1, lk = (tid & 1) * 4;
    const int row0 = (blockIdx.x / 9) * 128;   // g
    const int col0 = (blockIdx.x % 9) * 128;   // k_out
    const int kk8 = tid >> 5, c4 = (tid & 31) * 4;

    float acc[8][8];
    #pragma unroll
    for (int i = 0; i < 8; ++i)
        #pragma unroll
        for (int j = 0; j < 8; ++j) acc[i][j] = 0.f;

    for (int k0 = 0; k0 < Hd; k0 += 8) {
        float4 av4 = *(const float4*)(wih + (size_t)(row0 + lr) * Hd + k0 + lk);
        float4 wv;
        if (col0 < KSd)
            wv = *(const float4*)(Wkc + (size_t)(k0 + kk8) * KSd + col0 + c4);
        else
            wv = *(const float4*)(Wcc + (size_t)(k0 + kk8) * CSd + (col0 - KSd) + c4);
        __syncthreads();
        as[lk+0][lr] = av4.x; as[lk+1][lr] = av4.y;
        as[lk+2][lr] = av4.z; as[lk+3][lr] = av4.w;
        *(float4*)&bs[kk8][c4] = wv;
        __syncthreads();
        #pragma unroll
        for (int kk = 0; kk < 8; ++kk) {
            float ar[8], br[8];
            #pragma unroll
            for (int i = 0; i < 4; ++i) { ar[i] = as[kk][ty*4+i]; ar[4+i] = as[kk][64+ty*4+i]; }
            #pragma unroll
            for (int j = 0; j < 4; ++j) { br[j] = bs[kk][tx*4+j]; br[4+j] = bs[kk][64+tx*4+j]; }
            #pragma unroll
            for (int i = 0; i < 8; ++i)
                #pragma unroll
                for (int j = 0; j < 8; ++j)
                    acc[i][j] += ar[i] * br[j];
        }
    }
    #pragma unroll
    for (int i = 0; i < 8; ++i) {
        int r = row0 + ((i < 4) ? (ty*4 + i) : (64 + ty*4 + i - 4));
        #pragma unroll
        for (int jh = 0; jh < 2; ++jh) {
            int cb = col0 + jh*64 + tx*4;
            float4 v; v.x = acc[i][jh*4+0]; v.y = acc[i][jh*4+1];
            v.z = acc[i][jh*4+2]; v.w = acc[i][jh*4+3];
            *(float4*)(g_Wf + (size_t)r * KC + cb) = v;
        }
    }
}

// ============================================================
// convsplit<T>: fp32 -> bf16 hi/lo split, 8 elems/thread
// ============================================================
template<int T>
__global__ void convsplit(const float* __restrict__ s0, const float* __restrict__ s1)
{
    constexpr int COLS  = (T==3) ? CSd : KC;
    constexpr int COLS0 = (T==0) ? KSd : (T==1) ? KSd : (T==2) ? KC : CSd;
    constexpr long long ROWS = (T==0) ? (long long)RR : (T==1) ? 1024LL : (long long)G3;
    __nv_bfloat16* hi = (T==0) ? g_Ahi : (T==1) ? g_WBhi : (T==2) ? g_WFhi : g_WHhi;
    __nv_bfloat16* lo = (T==0) ? g_Alo : (T==1) ? g_WBlo : (T==2) ? g_WFlo : g_WHlo;
    const float* sp0 = (T==2) ? (const float*)g_Wf : s0;

    long long t = (long long)blockIdx.x * 256 + threadIdx.x;
    if (t >= ROWS * COLS / 8) return;
    long long e = t * 8;
    int c = (int)(e % COLS);
    long long r = e / COLS;

    float4 v0, v1;
    if (c < COLS0) {
        const float4* p = (const float4*)(sp0 + r * COLS0 + c);
        v0 = p[0]; v1 = p[1];
    } else {
        const float4* p = (const float4*)(s1 + r * (COLS - COLS0) + (c - COLS0));
        v0 = p[0]; v1 = p[1];
    }
    float v[8] = {v0.x, v0.y, v0.z, v0.w, v1.x, v1.y, v1.z, v1.w};
    __align__(16) __nv_bfloat16 hv[8];
    __align__(16) __nv_bfloat16 lv[8];
    #pragma unroll
    for (int j = 0; j < 8; ++j) {
        __nv_bfloat16 h = __float2bfloat16(v[j]);
        hv[j] = h;
        lv[j] = __float2bfloat16(v[j] - __bfloat162float(h));
    }
    *(uint4*)(hi + r * COLS + c) = *(uint4*)hv;
    *(uint4*)(lo + r * COLS + c) = *(uint4*)lv;
}

// ============================================================
// tgemm<EPI>: HMMA bf16-split GEMM (mma.sync m16n8k16), 128x128 CTA tile,
// K chunks of 32, 2-stage cp.async double buffer, 8 warps (2m x 4n), 64x32/warp.
// EPI0: scores — A x [Wk|Wc]^T,  epi tanh(.+g_q)·Wl -> g_part
// EPI1: gx     — A x Wfuse^T,    epi +qg2 + w·av    -> g_GX
// EPI2: gh     — cov x gwhh^T,   epi +gbhh          -> g_GH
// ============================================================
template<int EPI>
__global__ __launch_bounds__(256)
void tgemm(const float* __restrict__ p0)
{
    constexpr int NCT  = (EPI==0) ? 8 : 3;
    constexpr int KTOT = (EPI==2) ? CSd : KC;
    constexpr int NST  = KTOT / 32;
    constexpr int BSTR = (EPI==2) ? CSd : KC;
    constexpr int AOFF = (EPI==2) ? KSd : 0;

    const __nv_bfloat16* Bh = (EPI==0) ? g_WBhi : (EPI==1) ? g_WFhi : g_WHhi;
    const __nv_bfloat16* Bl = (EPI==0) ? g_WBlo : (EPI==1) ? g_WFlo : g_WHlo;

    extern __shared__ __align__(16) char dsm[];
    const uint32_t sbase = s2u(dsm);

    const int tid = threadIdx.x;
    const int wid = tid >> 5, lane = tid & 31;
    const int ct = blockIdx.x % NCT, rt = blockIdx.x / NCT;
    const int row0 = rt * 128, col0 = ct * 128;
    const int wm = (wid & 1) * 64;      // warp m offset
    const int wn = (wid >> 1) * 32;     // warp n offset

    // per-thread cp.async chunk ids: 512 16B-chunks per tile, 2 per thread
    const int id0 = tid * 2, id1 = tid * 2 + 1;
    const int cr0 = id0 >> 2, cu0 = id0 & 3;
    const int cr1 = id1 >> 2, cu1 = id1 & 3;

    auto load_stage = [&](int s, int stg) {
        const uint32_t sb = sbase + (uint32_t)stg * STAGE_B;
        const int kc = s * 32;
        size_t a0 = (size_t)(row0 + cr0) * KC + AOFF + kc + cu0 * 8;
        size_t a1 = (size_t)(row0 + cr1) * KC + AOFF + kc + cu1 * 8;
        size_t b0 = (size_t)(col0 + cr0) * BSTR + kc + cu0 * 8;
        size_t b1 = (size_t)(col0 + cr1) * BSTR + kc + cu1 * 8;
        uint32_t sa0 = sb + (uint32_t)(cr0 * SROW + cu0 * 16);
        uint32_t sa1 = sb + (uint32_t)(cr1 * SROW + cu1 * 16);
        CP16(sa0 + AHI_O, g_Ahi + a0);  CP16(sa1 + AHI_O, g_Ahi + a1);
        CP16(sa0 + ALO_O, g_Alo + a0);  CP16(sa1 + ALO_O, g_Alo + a1);
        CP16(sa0 + BHI_O, Bh + b0);     CP16(sa1 + BHI_O, Bh + b1);
        CP16(sa0 + BLO_O, Bl + b0);     CP16(sa1 + BLO_O, Bl + b1);
    };

    float acc[4][4][4];
    #pragma unroll
    for (int i = 0; i < 4; ++i)
        #pragma unroll
        for (int j = 0; j < 4; ++j)
            #pragma unroll
            for (int k = 0; k < 4; ++k) acc[i][j][k] = 0.f;

    // ldmatrix per-lane addresses (within a stage, before k-offset)
    const int arow = wm + (lane & 7) + ((lane >> 3) & 1) * 8;
    const uint32_t akb = (uint32_t)(((lane >> 4) & 1) * 16);
    const int brow = wn + (lane & 7);
    const uint32_t bkb = (uint32_t)(((lane >> 3) & 1) * 16);

    load_stage(0, 0); CPCOMMIT();

    for (int s = 0; s < NST; ++s) {
        if (s + 1 < NST) { load_stage(s + 1, (s + 1) & 1); CPCOMMIT(); CPWAIT1(); }
        else             { CPWAIT0(); }
        __syncthreads();

        const uint32_t sb = sbase + (uint32_t)(s & 1) * STAGE_B;
        #pragma unroll
        for (int kh = 0; kh < 2; ++kh) {
            const uint32_t ko = (uint32_t)(kh * 32);
            uint32_t ah[4][4], al[4][4], bh[4][2], bl[4][2];
            #pragma unroll
            for (int mi = 0; mi < 4; ++mi) {
                uint32_t ad = sb + (uint32_t)((arow + mi*16) * SROW) + ko + akb;
                ldsm4(ah[mi], ad + AHI_O);
                ldsm4(al[mi], ad + ALO_O);
            }
            #pragma unroll
            for (int ni = 0; ni < 4; ++ni) {
                uint32_t bd = sb + (uint32_t)((brow + ni*8) * SROW) + ko + bkb;
                ldsm2(bh[ni], bd + BHI_O);
                ldsm2(bl[ni], bd + BLO_O);
            }
            #pragma unroll
            for (int mi = 0; mi < 4; ++mi)
                #pragma unroll
                for (int ni = 0; ni < 4; ++ni) {
                    mma16816(acc[mi][ni], ah[mi], bh[ni]);
                    mma16816(acc[mi][ni], ah[mi], bl[ni]);
                    mma16816(acc[mi][ni], al[mi], bh[ni]);
                }
        }
        __syncthreads();
    }

    // -------- epilogues (fragment layout: d0,d1 = row g, cols 2q,2q+1; d2,d3 = row g+8) --------
    const int gq4 = lane >> 2;      // row within 8-group
    const int q   = lane & 3;       // col quad
    const int bIdx = row0 >> 11;

    if (EPI == 0) {
        // per-row partial of tanh(v + g_q)*Wl over this CTA's 128 cols
        float* red = (float*)dsm;   // [4 ncols][128 rows]
        float rowsum[4][2];
        #pragma unroll
        for (int mi = 0; mi < 4; ++mi)
            #pragma unroll
            for (int hf = 0; hf < 2; ++hf) {
                float s = 0.f;
                #pragma unroll
                for (int ni = 0; ni < 4; ++ni) {
                    int c = col0 + wn + ni*8 + q*2;
                    int r = row0 + wm + mi*16 + gq4 + hf*8;
                    float v0 = acc[mi][ni][hf*2+0] + g_q[bIdx*Hd + c];
                    float v1 = acc[mi][ni][hf*2+1] + g_q[bIdx*Hd + c + 1];
                    s += tanhf(v0) * p0[c] + tanhf(v1) * p0[c+1];
                    (void)r;
                }
                s += __shfl_xor_sync(0xffffffffu, s, 1);
                s += __shfl_xor_sync(0xffffffffu, s, 2);
                rowsum[mi][hf] = s;
            }
        if (q == 0) {
            #pragma unroll
            for (int mi = 0; mi < 4; ++mi)
                #pragma unroll
                for (int hf = 0; hf < 2; ++hf) {
                    int lr = wm + mi*16 + gq4 + hf*8;
                    red[(wid >> 1) * 128 + lr] = rowsum[mi][hf];
                }
        }
        __syncthreads();
        if (tid < 128) {
            float s = red[tid] + red[128 + tid] + red[256 + tid] + red[384 + tid];
            g_part[(size_t)(row0 + tid) * 8 + ct] = s;
        }
    } else if (EPI == 1) {
        #pragma unroll
        for (int mi = 0; mi < 4; ++mi)
            #pragma unroll
            for (int hf = 0; hf < 2; ++hf) {
                int r = row0 + wm + mi*16 + gq4 + hf*8;
                float wr = p0[r];
                #pragma unroll
                for (int ni = 0; ni < 4; ++ni) {
                    int c = col0 + wn + ni*8 + q*2;
                    float2 v;
                    v.x = acc[mi][ni][hf*2+0] + g_qg2[bIdx*G3 + c  ] + wr * g_av[c  ];
                    v.y = acc[mi][ni][hf*2+1] + g_qg2[bIdx*G3 + c+1] + wr * g_av[c+1];
                    *(float2*)(g_GX + (size_t)r * G3 + c) = v;
                }
            }
    } else {
        #pragma unroll
        for (int mi = 0; mi < 4; ++mi)
            #pragma unroll
            for (int hf = 0; hf < 2; ++hf) {
                int r = row0 + wm + mi*16 + gq4 + hf*8;
                #pragma unroll
                for (int ni = 0; ni < 4; ++ni) {
                    int c = col0 + wn + ni*8 + q*2;
                    float2 v;
                    v.x = acc[mi][ni][hf*2+0] + p0[c  ];
                    v.y = acc[mi][ni][hf*2+1] + p0[c+1];
                    *(float2*)(g_GH + (size_t)r * G3 + c) = v;
                }
            }
    }
}

// ============================================================
// masked softmax from 8 fixed-order partials + bl (mask dtype autodetect)
// ============================================================
__global__ void softmax_k(const void* __restrict__ maskp, const float* __restrict__ bl,
                          float* __restrict__ wout)
{
    __shared__ float sv[MM];
    __shared__ float red[256];
    __shared__ unsigned int ured[256];
    const int b = blockIdx.x;
    const int tid = threadIdx.x;

    const unsigned char* mbp = (const unsigned char*)maskp;
    unsigned int orr = 0;
    for (int i = tid; i < BB*MM; i += 256)
        if (i & 3) orr |= mbp[i];
    ured[tid] = orr;
    __syncthreads();
    for (int s = 128; s; s >>= 1) { if (tid < s) ured[tid] |= ured[tid + s]; __syncthreads(); }
    const bool isI32 = (ured[0] == 0);
    __syncthreads();

    const float blv = bl[0];
    for (int m = tid; m < MM; m += 256) {
        bool pad = isI32 ? (((const int*)maskp)[b*MM + m] != 0)
                         : (mbp[b*MM + m] != 0);
        if (pad) sv[m] = -1e30f;
        else {
            const float* p = g_part + (size_t)(b*MM + m) * 8;
            sv[m] = ((p[0]+p[1]) + (p[2]+p[3])) + ((p[4]+p[5]) + (p[6]+p[7])) + blv;
        }
    }
    __syncthreads();

    float mx = -3.4e38f;
    for (int m = tid; m < MM; m += 256) mx = fmaxf(mx, sv[m]);
    red[tid] = mx;
    __syncthreads();
    for (int s = 128; s; s >>= 1) { if (tid < s) red[tid] = fmaxf(red[tid], red[tid + s]); __syncthreads(); }
    mx = red[0];
    __syncthreads();

    float sum = 0.f;
    for (int m = tid; m < MM; m += 256) { float e = expf(sv[m] - mx); sv[m] = e; sum += e; }
    red[tid] = sum;
    __syncthreads();
    for (int s = 128; s; s >>= 1) { if (tid < s) red[tid] += red[tid + s]; __syncthreads(); }
    float inv = 1.f / red[0];
    __syncthreads();

    for (int m = tid; m < MM; m += 256) wout[b*MM + m] = sv[m] * inv;
}

// ============================================================
// attns[b][k] = sum_m w[b][m] * memory[b][m][k]
// ============================================================
__global__ void attns_k(const float* __restrict__ memory,
                        const float* __restrict__ w,
                        float* __restrict__ out)
{
    __shared__ float ws[MM];
    const int b = blockIdx.x;
    const int k = blockIdx.y * 256 + threadIdx.x;
    for (int i = threadIdx.x; i < MM; i += 256) ws[i] = w[b*MM + i];
    __syncthreads();
    const float* mp = memory + (size_t)b * MM * KSd + k;
    float a0 = 0.f, a1 = 0.f, a2 = 0.f, a3 = 0.f;
    for (int m = 0; m < MM; m += 4) {
        a0 += ws[m+0] * mp[(size_t)(m+0) * KSd];
        a1 += ws[m+1] * mp[(size_t)(m+1) * KSd];
        a2 += ws[m+2] * mp[(size_t)(m+2) * KSd];
        a3 += ws[m+3] * mp[(size_t)(m+3) * KSd];
    }
    out[b*KSd + k] = (a0 + a1) + (a2 + a3);
}

// ============================================================
// GRU elementwise
// ============================================================
__global__ void gru_k(const float* __restrict__ coverage, float* __restrict__ outc)
{
    size_t idx = (size_t)blockIdx.x * 256 + threadIdx.x;
    int r = (int)(idx >> 7);
    int c = (int)(idx & 127);
    size_t gi = (size_t)r * G3 + c;
    float xr = g_GX[gi],       hr = g_GH[gi];
    float xz = g_GX[gi + 128], hz = g_GH[gi + 128];
    float xn = g_GX[gi + 256], hn = g_GH[gi + 256];
    float rg = 1.f / (1.f + expf(-(xr + hr)));
    float z  = 1.f / (1.f + expf(-(xz + hz)));
    float n  = tanhf(xn + rg * hn);
    outc[idx] = (1.f - z) * n + z * coverage[idx];
}

// ============================================================
extern "C" void kernel_launch(void* const* d_in, const int* in_sizes, int n_in,
                              void* d_out, int out_size)
{
    const float* query   = (const float*)d_in[0];
    const float* memory  = (const float*)d_in[1];
    const float* coverage= (const float*)d_in[2];
    const float* Wq  = (const float*)d_in[3];  const float* bq  = (const float*)d_in[4];
    const float* Wk  = (const float*)d_in[5];  const float* bk  = (const float*)d_in[6];
    const float* Wc  = (const float*)d_in[7];  const float* bc  = (const float*)d_in[8];
    const float* Wcc = (const float*)d_in[9];  const float* bcc = (const float*)d_in[10];
    const float* Wqc = (const float*)d_in[11]; const float* bqc = (const float*)d_in[12];
    const float* Wkc = (const float*)d_in[13]; const float* bkc = (const float*)d_in[14];
    const float* Wac = (const float*)d_in[15]; const float* bac = (const float*)d_in[16];
    const float* Wl  = (const float*)d_in[17]; const float* bl  = (const float*)d_in[18];
    const float* gwih= (const float*)d_in[19]; const float* gbih= (const float*)d_in[20];
    const float* gwhh= (const float*)d_in[21]; const float* gbhh= (const float*)d_in[22];
    const void*  maskp = d_in[23];

    float* out      = (float*)d_out;
    float* out_attn = out;
    float* out_w    = out + BB*KSd;
    float* out_cov  = out + BB*KSd + BB*MM;

    static int attr_done = 0;
    if (!attr_done) {
        cudaFuncSetAttribute(tgemm<0>, cudaFuncAttributeMaxDynamicSharedMemorySize, DSMB);
        cudaFuncSetAttribute(tgemm<1>, cudaFuncAttributeMaxDynamicSharedMemorySize, DSMB);
        cudaFuncSetAttribute(tgemm<2>, cudaFuncAttributeMaxDynamicSharedMemorySize, DSMB);
        attr_done = 1;
    }

    // prep
    qprep<<<(BB*Hd)/8, 256>>>(query, Wq, bq, bk, bc, Wqc, bqc, bkc, bcc, bac);
    prep2<<<(33*G3*32 + 255)/256, 256>>>(gwih, gbih, Wac);
    wfuse_k<<<27, 256>>>(Wkc, Wcc, gwih);

    // bf16 hi/lo splits
    convsplit<0><<<36864, 256>>>(memory, coverage);   // A = [memory|coverage]
    convsplit<1><<<576,   256>>>(Wk, Wc);             // [Wk|Wc]
    convsplit<2><<<216,   256>>>(nullptr, nullptr);   // Wfuse
    convsplit<3><<<24,    256>>>(gwhh, nullptr);      // gwhh

    // scores (HMMA) -> partials
    tgemm<0><<<(RR/128)*8, 256, DSMB>>>(Wl);

    // softmax -> weights
    softmax_k<<<BB, 256>>>(maskp, bl, out_w);

    // attns
    attns_k<<<dim3(BB, KSd/256), 256>>>(memory, out_w, out_attn);

    // gx / gh (HMMA)
    tgemm<1><<<(RR/128)*3, 256, DSMB>>>(out_w);
    tgemm<2><<<(RR/128)*3, 256, DSMB>>>(gbhh);

    // GRU elementwise -> new_coverage
    gru_k<<<(RR*CSd)/256, 256>>>(coverage, out_cov);
}

// round 8
// speedup vs baseline: 3.1806x; 1.1445x over previous
#include <cuda_runtime.h>
#include <cuda_bf16.h>
#include <math.h>
#include <stdint.h>

#define BB  32
#define MM  2048
#define QSd 1024
#define KSd 1024
#define Hd  1024
#define CSd 128
#define RR  (BB*MM)     // 65536 rows
#define G3  384
#define KC  1152        // concat K = KS + CS

// ---------------- scratch (static device globals) ----------------
static __device__ float g_q[BB*Hd];
static __device__ float g_qc[BB*Hd];
static __device__ float g_qg2[BB*G3];
static __device__ float g_av[G3];
static __device__ float g_Wf[(size_t)G3*KC];
static __device__ float g_part[(size_t)RR*4];
static __device__ float g_GX[(size_t)RR*G3];
static __device__ float g_GH[(size_t)RR*G3];
// bf16 hi/lo split operands
static __device__ __nv_bfloat16 g_Ahi[(size_t)RR*KC];
static __device__ __nv_bfloat16 g_Alo[(size_t)RR*KC];
static __device__ __nv_bfloat16 g_WBhi[(size_t)1024*KC];
static __device__ __nv_bfloat16 g_WBlo[(size_t)1024*KC];
static __device__ __nv_bfloat16 g_WFhi[(size_t)G3*KC];
static __device__ __nv_bfloat16 g_WFlo[(size_t)G3*KC];
static __device__ __nv_bfloat16 g_WHhi[(size_t)G3*CSd];
static __device__ __nv_bfloat16 g_WHlo[(size_t)G3*CSd];

// ---------------- PTX helpers (base ISA, sm_80+) ----------------
__device__ __forceinline__ uint32_t s2u(const void* p){
    uint32_t a;
    asm("{ .reg .u64 t; cvta.to.shared.u64 t, %1; cvt.u32.u64 %0, t; }" : "=r"(a) : "l"(p));
    return a;
}
#define CP16(dst, gsrc) \
    asm volatile("cp.async.cg.shared.global [%0], [%1], 16;" \
                 :: "r"(dst), "l"(__cvta_generic_to_global(gsrc)) : "memory")
#define CPCOMMIT() asm volatile("cp.async.commit_group;" ::: "memory")
#define CPWAIT2()  asm volatile("cp.async.wait_group 2;" ::: "memory")
#define CPWAIT1()  asm volatile("cp.async.wait_group 1;" ::: "memory")
#define CPWAIT0()  asm volatile("cp.async.wait_group 0;" ::: "memory")

__device__ __forceinline__ void ldsm4(uint32_t* r, uint32_t addr){
    asm volatile("ldmatrix.sync.aligned.m8n8.x4.shared.b16 {%0,%1,%2,%3}, [%4];"
        : "=r"(r[0]), "=r"(r[1]), "=r"(r[2]), "=r"(r[3]) : "r"(addr));
}
__device__ __forceinline__ void mma16816(float* d, const uint32_t* a, const uint32_t* b){
    asm volatile("mma.sync.aligned.m16n8k16.row.col.f32.bf16.bf16.f32 "
        "{%0,%1,%2,%3}, {%4,%5,%6,%7}, {%8,%9}, {%0,%1,%2,%3};"
        : "+f"(d[0]), "+f"(d[1]), "+f"(d[2]), "+f"(d[3])
        : "r"(a[0]), "r"(a[1]), "r"(a[2]), "r"(a[3]), "r"(b[0]), "r"(b[1]));
}

#define SROW   80
#define ATILE  (128*SROW)          // 10240
#define BOFF   (2*ATILE)           // 20480 (Ahi + Alo)

// ============================================================
// qprep: q / qc projections, biases folded. Warp per (b,h).
// ============================================================
__global__ void qprep(const float* __restrict__ query,
                      const float* __restrict__ Wq,  const float* __restrict__ bq,
                      const float* __restrict__ bk,  const float* __restrict__ bc,
                      const float* __restrict__ Wqc, const float* __restrict__ bqc,
                      const float* __restrict__ bkc, const float* __restrict__ bcc,
                      const float* __restrict__ bac)
{
    int gw   = (blockIdx.x * blockDim.x + threadIdx.x) >> 5;
    int lane = threadIdx.x & 31;
    if (gw >= BB*Hd) return;
    int b = gw >> 10, h = gw & 1023;
    const float* q  = query + (size_t)b * QSd;
    const float* w1 = Wq  + (size_t)h * QSd;
    const float* w2 = Wqc + (size_t)h * QSd;
    float a1 = 0.f, a2 = 0.f;
    for (int k = lane; k < QSd; k += 32) {
        float qv = q[k];
        a1 += qv * w1[k];
        a2 += qv * w2[k];
    }
    #pragma unroll
    for (int o = 16; o; o >>= 1) {
        a1 += __shfl_xor_sync(0xffffffffu, a1, o);
        a2 += __shfl_xor_sync(0xffffffffu, a2, o);
    }
    if (!lane) {
        g_q[gw]  = a1 + bq[h]  + bk[h]  + bc[h];
        g_qc[gw] = a2 + bqc[h] + bkc[h] + bcc[h] + bac[h];
    }
}

// ============================================================
// prep2: qg2[b][g] = g_qc[b]·wih[g] + bih[g] ; av[g] = Wac·wih[g]
// ============================================================
__global__ void prep2(const float* __restrict__ wih, const float* __restrict__ bih,
                      const float* __restrict__ Wac)
{
    int gw   = (blockIdx.x * blockDim.x + threadIdx.x) >> 5;
    int lane = threadIdx.x & 31;
    if (gw >= 33*G3) return;
    if (gw < 32*G3) {
        int b = gw / G3, g = gw % G3;
        const float* x  = g_qc + (size_t)b * Hd;
        const float* wr = wih  + (size_t)g * Hd;
        float a = 0.f;
        for (int h = lane; h < Hd; h += 32) a += x[h] * wr[h];
        #pragma unroll
        for (int o = 16; o; o >>= 1) a += __shfl_xor_sync(0xffffffffu, a, o);
        if (!lane) g_qg2[gw] = a + bih[g];
    } else {
        int g = gw - 32*G3;
        const float* wr = wih + (size_t)g * Hd;
        float a = 0.f;
        for (int h = lane; h < Hd; h += 32) a += Wac[h] * wr[h];
        #pragma unroll
        for (int o = 16; o; o >>= 1) a += __shfl_xor_sync(0xffffffffu, a, o);
        if (!lane) g_av[g] = a;
    }
}

// ============================================================
// wfuse_k: g_Wf = wih @ [Wkc|Wcc]  (fp32 SIMT, 27 blocks, tiny)
// ============================================================
__global__ __launch_bounds__(256)
void wfuse_k(const float* __restrict__ Wkc, const float* __restrict__ Wcc,
             const float* __restrict__ wih)
{
    __shared__ __align__(16) float as[8][132];
    __shared__ __align__(16) float bs[8][132];
    const int tid = threadIdx.x;
    const int tx = tid & 15, ty = tid >> 4;
    const int lr = tid >> 1, lk = (tid & 1) * 4;
    const int row0 = (blockIdx.x / 9) * 128;   // g
    const int col0 = (blockIdx.x % 9) * 128;   // k_out
    const int kk8 = tid >> 5, c4 = (tid & 31) * 4;

    float acc[8][8];
    #pragma unroll
    for (int i = 0; i < 8; ++i)
        #pragma unroll
        for (int j = 0; j < 8; ++j) acc[i][j] = 0.f;

    for (int k0 = 0; k0 < Hd; k0 += 8) {
        float4 av4 = *(const float4*)(wih + (size_t)(row0 + lr) * Hd + k0 + lk);
        float4 wv;
        if (col0 < KSd)
            wv = *(const float4*)(Wkc + (size_t)(k0 + kk8) * KSd + col0 + c4);
        else
            wv = *(const float4*)(Wcc + (size_t)(k0 + kk8) * CSd + (col0 - KSd) + c4);
        __syncthreads();
        as[lk+0][lr] = av4.x; as[lk+1][lr] = av4.y;
        as[lk+2][lr] = av4.z; as[lk+3][lr] = av4.w;
        *(float4*)&bs[kk8][c4] = wv;
        __syncthreads();
        #pragma unroll
        for (int kk = 0; kk < 8; ++kk) {
            float ar[8], br[8];
            #pragma unroll
            for (int i = 0; i < 4; ++i) { ar[i] = as[kk][ty*4+i]; ar[4+i] = as[kk][64+ty*4+i]; }
            #pragma unroll
            for (int j = 0; j < 4; ++j) { br[j] = bs[kk][tx*4+j]; br[4+j] = bs[kk][64+tx*4+j]; }
            #pragma unroll
            for (int i = 0; i < 8; ++i)
                #pragma unroll
                for (int j = 0; j < 8; ++j)
                    acc[i][j] += ar[i] * br[j];
        }
    }
    #pragma unroll
    for (int i = 0; i < 8; ++i) {
        int r = row0 + ((i < 4) ? (ty*4 + i) : (64 + ty*4 + i - 4));
        #pragma unroll
        for (int jh = 0; jh < 2; ++jh) {
            int cb = col0 + jh*64 + tx*4;
            float4 v; v.x = acc[i][jh*4+0]; v.y = acc[i][jh*4+1];
            v.z = acc[i][jh*4+2]; v.w = acc[i][jh*4+3];
            *(float4*)(g_Wf + (size_t)r * KC + cb) = v;
        }
    }
}

// ============================================================
// convsplit<T>: fp32 -> bf16 hi/lo split, 8 elems/thread
// ============================================================
template<int T>
__global__ void convsplit(const float* __restrict__ s0, const float* __restrict__ s1)
{
    constexpr int COLS  = (T==3) ? CSd : KC;
    constexpr int COLS0 = (T==0) ? KSd : (T==1) ? KSd : (T==2) ? KC : CSd;
    constexpr long long ROWS = (T==0) ? (long long)RR : (T==1) ? 1024LL : (long long)G3;
    __nv_bfloat16* hi = (T==0) ? g_Ahi : (T==1) ? g_WBhi : (T==2) ? g_WFhi : g_WHhi;
    __nv_bfloat16* lo = (T==0) ? g_Alo : (T==1) ? g_WBlo : (T==2) ? g_WFlo : g_WHlo;
    const float* sp0 = (T==2) ? (const float*)g_Wf : s0;

    long long t = (long long)blockIdx.x * 256 + threadIdx.x;
    if (t >= ROWS * COLS / 8) return;
    long long e = t * 8;
    int c = (int)(e % COLS);
    long long r = e / COLS;

    float4 v0, v1;
    if (c < COLS0) {
        const float4* p = (const float4*)(sp0 + r * COLS0 + c);
        v0 = p[0]; v1 = p[1];
    } else {
        const float4* p = (const float4*)(s1 + r * (COLS - COLS0) + (c - COLS0));
        v0 = p[0]; v1 = p[1];
    }
    float v[8] = {v0.x, v0.y, v0.z, v0.w, v1.x, v1.y, v1.z, v1.w};
    __align__(16) __nv_bfloat16 hv[8];
    __align__(16) __nv_bfloat16 lv[8];
    #pragma unroll
    for (int j = 0; j < 8; ++j) {
        __nv_bfloat16 h = __float2bfloat16(v[j]);
        hv[j] = h;
        lv[j] = __float2bfloat16(v[j] - __bfloat162float(h));
    }
    *(uint4*)(hi + r * COLS + c) = *(uint4*)hv;
    *(uint4*)(lo + r * COLS + c) = *(uint4*)lv;
}

// ============================================================
// tgemm<EPI, NT, NSTG>: HMMA bf16-split GEMM, 128 x NT CTA tile, 256 thr,
// 8 warps as 2(m) x 4(n), warp tile 64 x NT/4, K chunks of 32, NSTG-stage
// cp.async pipeline.
// EPI0: scores (NT=256, NCT=4) — epi tanh(.+g_q)·Wl -> g_part
// EPI1: gx     (NT=192, NCT=2) — epi +qg2 + w·av    -> g_GX
// EPI2: gh     (NT=128, NCT=3) — epi +gbhh          -> g_GH
// ============================================================
template<int EPI, int NT, int NSTG>
__global__ __launch_bounds__(256)
void tgemm(const float* __restrict__ p0)
{
    constexpr int NCT  = (EPI==0) ? 4 : (EPI==1) ? 2 : 3;
    constexpr int KTOT = (EPI==2) ? CSd : KC;
    constexpr int NST  = KTOT / 32;
    constexpr int BSTR = (EPI==2) ? CSd : KC;
    constexpr int AOFF = (EPI==2) ? KSd : 0;
    constexpr int NF   = NT / 32;         // n-frags per warp
    constexpr int WNS  = NT / 4;          // warp n span
    constexpr uint32_t STAGEB = (uint32_t)(BOFF + NT*SROW*2);

    const __nv_bfloat16* Bh = (EPI==0) ? g_WBhi : (EPI==1) ? g_WFhi : g_WHhi;
    const __nv_bfloat16* Bl = (EPI==0) ? g_WBlo : (EPI==1) ? g_WFlo : g_WHlo;

    extern __shared__ __align__(16) char dsm[];
    const uint32_t sbase = s2u(dsm);

    const int tid = threadIdx.x;
    const int wid = tid >> 5, lane = tid & 31;
    const int ct = blockIdx.x % NCT, rt = blockIdx.x / NCT;
    const int row0 = rt * 128, col0 = ct * NT;
    const int wm = (wid & 1) * 64;
    const int wn = (wid >> 1) * WNS;

    auto load_stage = [&](int s, int stg) {
        const uint32_t sb = sbase + (uint32_t)stg * STAGEB;
        const int kc = s * 32;
        #pragma unroll
        for (int j = 0; j < 2; ++j) {               // A: 512 chunks hi + lo
            int idx = tid + j*256;
            int r = idx >> 2, cu = idx & 3;
            size_t ao = (size_t)(row0 + r) * KC + AOFF + kc + cu*8;
            uint32_t sa = sb + (uint32_t)(r*SROW + cu*16);
            CP16(sa,         g_Ahi + ao);
            CP16(sa + ATILE, g_Alo + ao);
        }
        #pragma unroll
        for (int j = 0; j < NT/64; ++j) {           // B: NT*4 chunks hi + lo
            int idx = tid + j*256;
            int r = idx >> 2, cu = idx & 3;
            size_t bo = (size_t)(col0 + r) * BSTR + kc + cu*8;
            uint32_t sa = sb + BOFF + (uint32_t)(r*SROW + cu*16);
            CP16(sa,                        Bh + bo);
            CP16(sa + (uint32_t)(NT*SROW), Bl + bo);
        }
    };

    float acc[4][NF][4];
    #pragma unroll
    for (int i = 0; i < 4; ++i)
        #pragma unroll
        for (int j = 0; j < NF; ++j)
            #pragma unroll
            for (int k = 0; k < 4; ++k) acc[i][j][k] = 0.f;

    // ldmatrix per-lane addressing
    const int arow = wm + (lane & 7) + ((lane >> 3) & 1) * 8;
    const uint32_t akb = (uint32_t)(((lane >> 4) & 1) * 16);
    const int brow = wn + (lane & 7) + ((lane >> 4) & 1) * 8;
    const uint32_t bkb = (uint32_t)(((lane >> 3) & 1) * 16);

    #pragma unroll
    for (int i = 0; i < NSTG-1; ++i) { load_stage(i, i); CPCOMMIT(); }

    for (int s = 0; s < NST; ++s) {
        if (s + NSTG - 1 < NST) {
            load_stage(s + NSTG - 1, (s + NSTG - 1) % NSTG);
            CPCOMMIT();
            if (NSTG == 3) CPWAIT2(); else CPWAIT1();
        } else {
            CPWAIT0();
        }
        __syncthreads();

        const uint32_t sb = sbase + (uint32_t)(s % NSTG) * STAGEB;
        #pragma unroll
        for (int kh = 0; kh < 2; ++kh) {
            const uint32_t ko = (uint32_t)(kh * 32);
            uint32_t ah[4][4], al[4][4], bh[NF][2], bl[NF][2];
            #pragma unroll
            for (int mi = 0; mi < 4; ++mi) {
                uint32_t ad = sb + (uint32_t)((arow + mi*16) * SROW) + ko + akb;
                ldsm4(ah[mi], ad);
                ldsm4(al[mi], ad + ATILE);
            }
            #pragma unroll
            for (int ni = 0; ni < NF; ni += 2) {
                uint32_t bd = sb + BOFF + (uint32_t)((brow + ni*8) * SROW) + ko + bkb;
                ldsm4(&bh[ni][0], bd);
                ldsm4(&bl[ni][0], bd + (uint32_t)(NT*SROW));
            }
            #pragma unroll
            for (int mi = 0; mi < 4; ++mi)
                #pragma unroll
                for (int ni = 0; ni < NF; ++ni) {
                    mma16816(acc[mi][ni], ah[mi], bh[ni]);
                    mma16816(acc[mi][ni], ah[mi], bl[ni]);
                    mma16816(acc[mi][ni], al[mi], bh[ni]);
                }
        }
        __syncthreads();
    }

    // -------- epilogues --------
    const int gq4 = lane >> 2;
    const int q   = lane & 3;
    const int bIdx = row0 >> 11;

    if (EPI == 0) {
        float* red = (float*)dsm;      // [4 ngroups][128 rows]
        float rowsum[4][2];
        #pragma unroll
        for (int mi = 0; mi < 4; ++mi)
            #pragma unroll
            for (int hf = 0; hf < 2; ++hf) {
                float s = 0.f;
                #pragma unroll
                for (int ni = 0; ni < NF; ++ni) {
                    int c = col0 + wn + ni*8 + q*2;
                    float v0 = acc[mi][ni][hf*2+0] + g_q[bIdx*Hd + c];
                    float v1 = acc[mi][ni][hf*2+1] + g_q[bIdx*Hd + c + 1];
                    s += tanhf(v0) * p0[c] + tanhf(v1) * p0[c+1];
                }
                s += __shfl_xor_sync(0xffffffffu, s, 1);
                s += __shfl_xor_sync(0xffffffffu, s, 2);
                rowsum[mi][hf] = s;
            }
        if (q == 0) {
            #pragma unroll
            for (int mi = 0; mi < 4; ++mi)
                #pragma unroll
                for (int hf = 0; hf < 2; ++hf) {
                    int lr = wm + mi*16 + gq4 + hf*8;
                    red[(wid >> 1) * 128 + lr] = rowsum[mi][hf];
                }
        }
        __syncthreads();
        if (tid < 128) {
            float s = red[tid] + red[128 + tid] + red[256 + tid] + red[384 + tid];
            g_part[(size_t)(row0 + tid) * 4 + ct] = s;
        }
    } else if (EPI == 1) {
        #pragma unroll
        for (int mi = 0; mi < 4; ++mi)
            #pragma unroll
            for (int hf = 0; hf < 2; ++hf) {
                int r = row0 + wm + mi*16 + gq4 + hf*8;
                float wr = p0[r];
                #pragma unroll
                for (int ni = 0; ni < NF; ++ni) {
                    int c = col0 + wn + ni*8 + q*2;
                    float2 v;
                    v.x = acc[mi][ni][hf*2+0] + g_qg2[bIdx*G3 + c  ] + wr * g_av[c  ];
                    v.y = acc[mi][ni][hf*2+1] + g_qg2[bIdx*G3 + c+1] + wr * g_av[c+1];
                    *(float2*)(g_GX + (size_t)r * G3 + c) = v;
                }
            }
    } else {
        #pragma unroll
        for (int mi = 0; mi < 4; ++mi)
            #pragma unroll
            for (int hf = 0; hf < 2; ++hf) {
                int r = row0 + wm + mi*16 + gq4 + hf*8;
                #pragma unroll
                for (int ni = 0; ni < NF; ++ni) {
                    int c = col0 + wn + ni*8 + q*2;
                    float2 v;
                    v.x = acc[mi][ni][hf*2+0] + p0[c  ];
                    v.y = acc[mi][ni][hf*2+1] + p0[c+1];
                    *(float2*)(g_GH + (size_t)r * G3 + c) = v;
                }
            }
    }
}

// ============================================================
// masked softmax from 4 fixed-order partials + bl (mask dtype autodetect)
// ============================================================
__global__ void softmax_k(const void* __restrict__ maskp, const float* __restrict__ bl,
                          float* __restrict__ wout)
{
    __shared__ float sv[MM];
    __shared__ float red[256];
    __shared__ unsigned int ured[256];
    const int b = blockIdx.x;
    const int tid = threadIdx.x;

    const unsigned char* mbp = (const unsigned char*)maskp;
    unsigned int orr = 0;
    for (int i = tid; i < BB*MM; i += 256)
        if (i & 3) orr |= mbp[i];
    ured[tid] = orr;
    __syncthreads();
    for (int s = 128; s; s >>= 1) { if (tid < s) ured[tid] |= ured[tid + s]; __syncthreads(); }
    const bool isI32 = (ured[0] == 0);
    __syncthreads();

    const float blv = bl[0];
    for (int m = tid; m < MM; m += 256) {
        bool pad = isI32 ? (((const int*)maskp)[b*MM + m] != 0)
                         : (mbp[b*MM + m] != 0);
        if (pad) sv[m] = -1e30f;
        else {
            const float* p = g_part + (size_t)(b*MM + m) * 4;
            sv[m] = (p[0] + p[1]) + (p[2] + p[3]) + blv;
        }
    }
    __syncthreads();

    float mx = -3.4e38f;
    for (int m = tid; m < MM; m += 256) mx = fmaxf(mx, sv[m]);
    red[tid] = mx;
    __syncthreads();
    for (int s = 128; s; s >>= 1) { if (tid < s) red[tid] = fmaxf(red[tid], red[tid + s]); __syncthreads(); }
    mx = red[0];
    __syncthreads();

    float sum = 0.f;
    for (int m = tid; m < MM; m += 256) { float e = expf(sv[m] - mx); sv[m] = e; sum += e; }
    red[tid] = sum;
    __syncthreads();
    for (int s = 128; s; s >>= 1) { if (tid < s) red[tid] += red[tid + s]; __syncthreads(); }
    float inv = 1.f / red[0];
    __syncthreads();

    for (int m = tid; m < MM; m += 256) wout[b*MM + m] = sv[m] * inv;
}

// ============================================================
// attns[b][k] = sum_m w[b][m] * memory[b][m][k]
// ============================================================
__global__ void attns_k(const float* __restrict__ memory,
                        const float* __restrict__ w,
                        float* __restrict__ out)
{
    __shared__ float ws[MM];
    const int b = blockIdx.x;
    const int k = blockIdx.y * 256 + threadIdx.x;
    for (int i = threadIdx.x; i < MM; i += 256) ws[i] = w[b*MM + i];
    __syncthreads();
    const float* mp = memory + (size_t)b * MM * KSd + k;
    float a0 = 0.f, a1 = 0.f, a2 = 0.f, a3 = 0.f;
    for (int m = 0; m < MM; m += 4) {
        a0 += ws[m+0] * mp[(size_t)(m+0) * KSd];
        a1 += ws[m+1] * mp[(size_t)(m+1) * KSd];
        a2 += ws[m+2] * mp[(size_t)(m+2) * KSd];
        a3 += ws[m+3] * mp[(size_t)(m+3) * KSd];
    }
    out[b*KSd + k] = (a0 + a1) + (a2 + a3);
}

// ============================================================
// GRU elementwise
// ============================================================
__global__ void gru_k(const float* __restrict__ coverage, float* __restrict__ outc)
{
    size_t idx = (size_t)blockIdx.x * 256 + threadIdx.x;
    int r = (int)(idx >> 7);
    int c = (int)(idx & 127);
    size_t gi = (size_t)r * G3 + c;
    float xr = g_GX[gi],       hr = g_GH[gi];
    float xz = g_GX[gi + 128], hz = g_GH[gi + 128];
    float xn = g_GX[gi + 256], hn = g_GH[gi + 256];
    float rg = 1.f / (1.f + expf(-(xr + hr)));
    float z  = 1.f / (1.f + expf(-(xz + hz)));
    float n  = tanhf(xn + rg * hn);
    outc[idx] = (1.f - z) * n + z * coverage[idx];
}

// ============================================================
extern "C" void kernel_launch(void* const* d_in, const int* in_sizes, int n_in,
                              void* d_out, int out_size)
{
    const float* query   = (const float*)d_in[0];
    const float* memory  = (const float*)d_in[1];
    const float* coverage= (const float*)d_in[2];
    const float* Wq  = (const float*)d_in[3];  const float* bq  = (const float*)d_in[4];
    const float* Wk  = (const float*)d_in[5];  const float* bk  = (const float*)d_in[6];
    const float* Wc  = (const float*)d_in[7];  const float* bc  = (const float*)d_in[8];
    const float* Wcc = (const float*)d_in[9];  const float* bcc = (const float*)d_in[10];
    const float* Wqc = (const float*)d_in[11]; const float* bqc = (const float*)d_in[12];
    const float* Wkc = (const float*)d_in[13]; const float* bkc = (const float*)d_in[14];
    const float* Wac = (const float*)d_in[15]; const float* bac = (const float*)d_in[16];
    const float* Wl  = (const float*)d_in[17]; const float* bl  = (const float*)d_in[18];
    const float* gwih= (const float*)d_in[19]; const float* gbih= (const float*)d_in[20];
    const float* gwhh= (const float*)d_in[21]; const float* gbhh= (const float*)d_in[22];
    const void*  maskp = d_in[23];

    float* out      = (float*)d_out;
    float* out_attn = out;
    float* out_w    = out + BB*KSd;
    float* out_cov  = out + BB*KSd + BB*MM;

    const int DSM0 = 3 * (BOFF + 256*SROW*2);   // 184320
    const int DSM1 = 3 * (BOFF + 192*SROW*2);   // 153600
    const int DSM2 = 2 * (BOFF + 128*SROW*2);   // 81920

    static int attr_done = 0;
    if (!attr_done) {
        cudaFuncSetAttribute((const void*)tgemm<0,256,3>, cudaFuncAttributeMaxDynamicSharedMemorySize, DSM0);
        cudaFuncSetAttribute((const void*)tgemm<1,192,3>, cudaFuncAttributeMaxDynamicSharedMemorySize, DSM1);
        cudaFuncSetAttribute((const void*)tgemm<2,128,2>, cudaFuncAttributeMaxDynamicSharedMemorySize, DSM2);
        attr_done = 1;
    }

    // prep
    qprep<<<(BB*Hd)/8, 256>>>(query, Wq, bq, bk, bc, Wqc, bqc, bkc, bcc, bac);
    prep2<<<(33*G3*32 + 255)/256, 256>>>(gwih, gbih, Wac);
    wfuse_k<<<27, 256>>>(Wkc, Wcc, gwih);

    // bf16 hi/lo splits
    convsplit<0><<<36864, 256>>>(memory, coverage);   // A = [memory|coverage]
    convsplit<1><<<576,   256>>>(Wk, Wc);             // [Wk|Wc]
    convsplit<2><<<216,   256>>>(nullptr, nullptr);   // Wfuse
    convsplit<3><<<24,    256>>>(gwhh, nullptr);      // gwhh

    // scores (HMMA, 128x256 tiles) -> partials
    tgemm<0,256,3><<<(RR/128)*4, 256, DSM0>>>(Wl);

    // softmax -> weights
    softmax_k<<<BB, 256>>>(maskp, bl, out_w);

    // attns
    attns_k<<<dim3(BB, KSd/256), 256>>>(memory, out_w, out_attn);

    // gx (128x192) / gh (128x128)
    tgemm<1,192,3><<<(RR/128)*2, 256, DSM1>>>(out_w);
    tgemm<2,128,2><<<(RR/128)*3, 256, DSM2>>>(gbhh);

    // GRU elementwise -> new_coverage
    gru_k<<<(RR*CSd)/256, 256>>>(coverage, out_cov);
}

// round 9
// speedup vs baseline: 3.7592x; 1.1819x over previous
#include <cuda_runtime.h>
#include <cuda_bf16.h>
#include <math.h>
#include <stdint.h>

#define BB  32
#define MM  2048
#define QSd 1024
#define KSd 1024
#define Hd  1024
#define CSd 128
#define RR  (BB*MM)     // 65536 rows
#define G3  384
#define KC  1152        // concat K = KS + CS

// ---------------- scratch (static device globals) ----------------
static __device__ float g_q[BB*Hd];
static __device__ float g_qc[BB*Hd];
static __device__ float g_qg2[BB*G3];
static __device__ float g_av[G3];
static __device__ float g_Wf[(size_t)G3*KC];
static __device__ float g_part[(size_t)RR*4];
static __device__ float g_GX[(size_t)RR*G3];
static __device__ float g_GH[(size_t)RR*G3];
// bf16 hi/lo split operands (gx / gh path)
static __device__ __nv_bfloat16 g_Ahi[(size_t)RR*KC];
static __device__ __nv_bfloat16 g_Alo[(size_t)RR*KC];
static __device__ __nv_bfloat16 g_WFhi[(size_t)G3*KC];
static __device__ __nv_bfloat16 g_WFlo[(size_t)G3*KC];
static __device__ __nv_bfloat16 g_WHhi[(size_t)G3*CSd];
static __device__ __nv_bfloat16 g_WHlo[(size_t)G3*CSd];
// tf32-rounded fp32 operands (scores path)
static __device__ float g_Atf[(size_t)RR*KC];
static __device__ float g_WBtf[(size_t)1024*KC];

// ---------------- PTX helpers (base ISA, sm_80+) ----------------
__device__ __forceinline__ uint32_t s2u(const void* p){
    uint32_t a;
    asm("{ .reg .u64 t; cvta.to.shared.u64 t, %1; cvt.u32.u64 %0, t; }" : "=r"(a) : "l"(p));
    return a;
}
__device__ __forceinline__ uint32_t f2tf32(float x){
    uint32_t r; asm("cvt.rna.tf32.f32 %0, %1;" : "=r"(r) : "f"(x)); return r;
}
#define CP16(dst, gsrc) \
    asm volatile("cp.async.cg.shared.global [%0], [%1], 16;" \
                 :: "r"(dst), "l"(__cvta_generic_to_global(gsrc)) : "memory")
#define CPCOMMIT() asm volatile("cp.async.commit_group;" ::: "memory")
#define CPWAIT2()  asm volatile("cp.async.wait_group 2;" ::: "memory")
#define CPWAIT1()  asm volatile("cp.async.wait_group 1;" ::: "memory")
#define CPWAIT0()  asm volatile("cp.async.wait_group 0;" ::: "memory")

__device__ __forceinline__ void ldsm4(uint32_t* r, uint32_t addr){
    asm volatile("ldmatrix.sync.aligned.m8n8.x4.shared.b16 {%0,%1,%2,%3}, [%4];"
        : "=r"(r[0]), "=r"(r[1]), "=r"(r[2]), "=r"(r[3]) : "r"(addr));
}
__device__ __forceinline__ void mma16816(float* d, const uint32_t* a, const uint32_t* b){
    asm volatile("mma.sync.aligned.m16n8k16.row.col.f32.bf16.bf16.f32 "
        "{%0,%1,%2,%3}, {%4,%5,%6,%7}, {%8,%9}, {%0,%1,%2,%3};"
        : "+f"(d[0]), "+f"(d[1]), "+f"(d[2]), "+f"(d[3])
        : "r"(a[0]), "r"(a[1]), "r"(a[2]), "r"(a[3]), "r"(b[0]), "r"(b[1]));
}
__device__ __forceinline__ void mmatf32(float* d, const uint32_t* a, const uint32_t* b){
    asm volatile("mma.sync.aligned.m16n8k8.row.col.f32.tf32.tf32.f32 "
        "{%0,%1,%2,%3}, {%4,%5,%6,%7}, {%8,%9}, {%0,%1,%2,%3};"
        : "+f"(d[0]), "+f"(d[1]), "+f"(d[2]), "+f"(d[3])
        : "r"(a[0]), "r"(a[1]), "r"(a[2]), "r"(a[3]), "r"(b[0]), "r"(b[1]));
}

#define SROW   80
#define ATILE  (128*SROW)          // 10240
#define BOFF   (2*ATILE)           // 20480 (Ahi + Alo)

// ============================================================
// qprep: q / qc projections, biases folded. Warp per (b,h).
// ============================================================
__global__ void qprep(const float* __restrict__ query,
                      const float* __restrict__ Wq,  const float* __restrict__ bq,
                      const float* __restrict__ bk,  const float* __restrict__ bc,
                      const float* __restrict__ Wqc, const float* __restrict__ bqc,
                      const float* __restrict__ bkc, const float* __restrict__ bcc,
                      const float* __restrict__ bac)
{
    int gw   = (blockIdx.x * blockDim.x + threadIdx.x) >> 5;
    int lane = threadIdx.x & 31;
    if (gw >= BB*Hd) return;
    int b = gw >> 10, h = gw & 1023;
    const float* q  = query + (size_t)b * QSd;
    const float* w1 = Wq  + (size_t)h * QSd;
    const float* w2 = Wqc + (size_t)h * QSd;
    float a1 = 0.f, a2 = 0.f;
    for (int k = lane; k < QSd; k += 32) {
        float qv = q[k];
        a1 += qv * w1[k];
        a2 += qv * w2[k];
    }
    #pragma unroll
    for (int o = 16; o; o >>= 1) {
        a1 += __shfl_xor_sync(0xffffffffu, a1, o);
        a2 += __shfl_xor_sync(0xffffffffu, a2, o);
    }
    if (!lane) {
        g_q[gw]  = a1 + bq[h]  + bk[h]  + bc[h];
        g_qc[gw] = a2 + bqc[h] + bkc[h] + bcc[h] + bac[h];
    }
}

// ============================================================
// prep2: qg2[b][g] = g_qc[b]·wih[g] + bih[g] ; av[g] = Wac·wih[g]
// ============================================================
__global__ void prep2(const float* __restrict__ wih, const float* __restrict__ bih,
                      const float* __restrict__ Wac)
{
    int gw   = (blockIdx.x * blockDim.x + threadIdx.x) >> 5;
    int lane = threadIdx.x & 31;
    if (gw >= 33*G3) return;
    if (gw < 32*G3) {
        int b = gw / G3, g = gw % G3;
        const float* x  = g_qc + (size_t)b * Hd;
        const float* wr = wih  + (size_t)g * Hd;
        float a = 0.f;
        for (int h = lane; h < Hd; h += 32) a += x[h] * wr[h];
        #pragma unroll
        for (int o = 16; o; o >>= 1) a += __shfl_xor_sync(0xffffffffu, a, o);
        if (!lane) g_qg2[gw] = a + bih[g];
    } else {
        int g = gw - 32*G3;
        const float* wr = wih + (size_t)g * Hd;
        float a = 0.f;
        for (int h = lane; h < Hd; h += 32) a += Wac[h] * wr[h];
        #pragma unroll
        for (int o = 16; o; o >>= 1) a += __shfl_xor_sync(0xffffffffu, a, o);
        if (!lane) g_av[g] = a;
    }
}

// ============================================================
// wfuse_k: g_Wf = wih @ [Wkc|Wcc]  (fp32 SIMT, 27 blocks, tiny)
// ============================================================
__global__ __launch_bounds__(256)
void wfuse_k(const float* __restrict__ Wkc, const float* __restrict__ Wcc,
             const float* __restrict__ wih)
{
    __shared__ __align__(16) float as[8][132];
    __shared__ __align__(16) float bs[8][132];
    const int tid = threadIdx.x;
    const int tx = tid & 15, ty = tid >> 4;
    const int lr = tid >> 1, lk = (tid & 1) * 4;
    const int row0 = (blockIdx.x / 9) * 128;   // g
    const int col0 = (blockIdx.x % 9) * 128;   // k_out
    const int kk8 = tid >> 5, c4 = (tid & 31) * 4;

    float acc[8][8];
    #pragma unroll
    for (int i = 0; i < 8; ++i)
        #pragma unroll
        for (int j = 0; j < 8; ++j) acc[i][j] = 0.f;

    for (int k0 = 0; k0 < Hd; k0 += 8) {
        float4 av4 = *(const float4*)(wih + (size_t)(row0 + lr) * Hd + k0 + lk);
        float4 wv;
        if (col0 < KSd)
            wv = *(const float4*)(Wkc + (size_t)(k0 + kk8) * KSd + col0 + c4);
        else
            wv = *(const float4*)(Wcc + (size_t)(k0 + kk8) * CSd + (col0 - KSd) + c4);
        __syncthreads();
        as[lk+0][lr] = av4.x; as[lk+1][lr] = av4.y;
        as[lk+2][lr] = av4.z; as[lk+3][lr] = av4.w;
        *(float4*)&bs[kk8][c4] = wv;
        __syncthreads();
        #pragma unroll
        for (int kk = 0; kk < 8; ++kk) {
            float ar[8], br[8];
            #pragma unroll
            for (int i = 0; i < 4; ++i) { ar[i] = as[kk][ty*4+i]; ar[4+i] = as[kk][64+ty*4+i]; }
            #pragma unroll
            for (int j = 0; j < 4; ++j) { br[j] = bs[kk][tx*4+j]; br[4+j] = bs[kk][64+tx*4+j]; }
            #pragma unroll
            for (int i = 0; i < 8; ++i)
                #pragma unroll
                for (int j = 0; j < 8; ++j)
                    acc[i][j] += ar[i] * br[j];
        }
    }
    #pragma unroll
    for (int i = 0; i < 8; ++i) {
        int r = row0 + ((i < 4) ? (ty*4 + i) : (64 + ty*4 + i - 4));
        #pragma unroll
        for (int jh = 0; jh < 2; ++jh) {
            int cb = col0 + jh*64 + tx*4;
            float4 v; v.x = acc[i][jh*4+0]; v.y = acc[i][jh*4+1];
            v.z = acc[i][jh*4+2]; v.w = acc[i][jh*4+3];
            *(float4*)(g_Wf + (size_t)r * KC + cb) = v;
        }
    }
}

// ============================================================
// convsplit<T>: fp32 -> bf16 hi/lo split (+ tf32-rounded copy for T=0,1)
// T0: [memory|coverage] -> g_Ahi/Alo + g_Atf   (RR x 1152)
// T1: [Wk|Wc]           -> g_WBtf only         (1024 x 1152)
// T2: g_Wf              -> g_WFhi/WFlo         (384 x 1152)
// T3: gwhh              -> g_WHhi/WHlo         (384 x 128)
// ============================================================
template<int T>
__global__ void convsplit(const float* __restrict__ s0, const float* __restrict__ s1)
{
    constexpr int COLS  = (T==3) ? CSd : KC;
    constexpr int COLS0 = (T==0) ? KSd : (T==1) ? KSd : (T==2) ? KC : CSd;
    constexpr long long ROWS = (T==0) ? (long long)RR : (T==1) ? 1024LL : (long long)G3;
    const float* sp0 = (T==2) ? (const float*)g_Wf : s0;

    long long t = (long long)blockIdx.x * 256 + threadIdx.x;
    if (t >= ROWS * COLS / 8) return;
    long long e = t * 8;
    int c = (int)(e % COLS);
    long long r = e / COLS;

    float4 v0, v1;
    if (c < COLS0) {
        const float4* p = (const float4*)(sp0 + r * COLS0 + c);
        v0 = p[0]; v1 = p[1];
    } else {
        const float4* p = (const float4*)(s1 + r * (COLS - COLS0) + (c - COLS0));
        v0 = p[0]; v1 = p[1];
    }
    float v[8] = {v0.x, v0.y, v0.z, v0.w, v1.x, v1.y, v1.z, v1.w};

    if (T == 1) {
        __align__(16) uint32_t tv[8];
        #pragma unroll
        for (int j = 0; j < 8; ++j) tv[j] = f2tf32(v[j]);
        uint32_t* dst = (uint32_t*)g_WBtf + r * COLS + c;
        *(uint4*)dst = *(uint4*)tv;
        *(uint4*)(dst + 4) = *(uint4*)(tv + 4);
        return;
    }

    __nv_bfloat16* hi = (T==0) ? g_Ahi : (T==2) ? g_WFhi : g_WHhi;
    __nv_bfloat16* lo = (T==0) ? g_Alo : (T==2) ? g_WFlo : g_WHlo;
    __align__(16) __nv_bfloat16 hv[8];
    __align__(16) __nv_bfloat16 lv[8];
    #pragma unroll
    for (int j = 0; j < 8; ++j) {
        __nv_bfloat16 h = __float2bfloat16(v[j]);
        hv[j] = h;
        lv[j] = __float2bfloat16(v[j] - __bfloat162float(h));
    }
    *(uint4*)(hi + r * COLS + c) = *(uint4*)hv;
    *(uint4*)(lo + r * COLS + c) = *(uint4*)lv;

    if (T == 0) {
        __align__(16) uint32_t tv[8];
        #pragma unroll
        for (int j = 0; j < 8; ++j) tv[j] = f2tf32(v[j]);
        uint32_t* dst = (uint32_t*)g_Atf + r * COLS + c;
        *(uint4*)dst = *(uint4*)tv;
        *(uint4*)(dst + 4) = *(uint4*)(tv + 4);
    }
}

// ============================================================
// tgemm_tf32: scores GEMM, single-pass tf32 (mma m16n8k8).
// 128x256 CTA tile, 8 warps (2m x 4n), warp 64x64, K chunk 32 fp32,
// 3-stage cp.async. Epilogue: tanh(.+g_q)·Wl partial -> g_part (stride 4).
// ============================================================
#define SR4     144u
#define ATILE4  (128u*SR4)           // 18432
#define STG4    (ATILE4 + 256u*SR4)  // 55296
#define DSMTF   (3*STG4)             // 165888

__global__ __launch_bounds__(256)
void tgemm_tf32(const float* __restrict__ Wl)
{
    constexpr int NCT = 4, NST = KC/32;
    extern __shared__ __align__(16) char dsm[];
    const uint32_t sbase = s2u(dsm);

    const int tid = threadIdx.x;
    const int wid = tid >> 5, lane = tid & 31;
    const int ct = blockIdx.x % NCT, rt = blockIdx.x / NCT;
    const int row0 = rt * 128, col0 = ct * 256;
    const int wm = (wid & 1) * 64;
    const int wn = (wid >> 1) * 64;

    auto load_stage = [&](int s, int stg) {
        const uint32_t sb = sbase + (uint32_t)stg * STG4;
        const int kc = s * 32;
        #pragma unroll
        for (int j = 0; j < 4; ++j) {       // A: 1024 16B chunks
            int idx = tid + j*256;
            int r = idx >> 3, cu = idx & 7;
            CP16(sb + (uint32_t)(r*SR4 + cu*16),
                 g_Atf + (size_t)(row0 + r) * KC + kc + cu*4);
        }
        #pragma unroll
        for (int j = 0; j < 8; ++j) {       // B: 2048 chunks
            int idx = tid + j*256;
            int r = idx >> 3, cu = idx & 7;
            CP16(sb + ATILE4 + (uint32_t)(r*SR4 + cu*16),
                 g_WBtf + (size_t)(col0 + r) * KC + kc + cu*4);
        }
    };

    float acc[4][8][4];
    #pragma unroll
    for (int i = 0; i < 4; ++i)
        #pragma unroll
        for (int j = 0; j < 8; ++j)
            #pragma unroll
            for (int k = 0; k < 4; ++k) acc[i][j][k] = 0.f;

    // ldmatrix lane addressing (8x8 tiles of b32 via b16 x4)
    const int arow = wm + (lane & 7) + ((lane >> 3) & 1) * 8;
    const uint32_t akb = (uint32_t)(((lane >> 4) & 1) * 16);
    const int brow = wn + (lane & 7) + ((lane >> 4) & 1) * 8;
    const uint32_t bkb = (uint32_t)(((lane >> 3) & 1) * 16);

    load_stage(0, 0); CPCOMMIT();
    load_stage(1, 1); CPCOMMIT();

    for (int s = 0; s < NST; ++s) {
        if (s + 2 < NST) { load_stage(s + 2, (s + 2) % 3); CPCOMMIT(); CPWAIT2(); }
        else             { CPWAIT0(); }
        __syncthreads();

        const uint32_t sb = sbase + (uint32_t)(s % 3) * STG4;
        #pragma unroll
        for (int kq = 0; kq < 4; ++kq) {
            const uint32_t ko = (uint32_t)(kq * 32);
            uint32_t a[4][4], b[8][2];
            #pragma unroll
            for (int mi = 0; mi < 4; ++mi)
                ldsm4(a[mi], sb + (uint32_t)((arow + mi*16) * SR4) + ko + akb);
            #pragma unroll
            for (int ni = 0; ni < 8; ni += 2)
                ldsm4(&b[ni][0], sb + ATILE4 + (uint32_t)((brow + ni*8) * SR4) + ko + bkb);
            #pragma unroll
            for (int mi = 0; mi < 4; ++mi)
                #pragma unroll
                for (int ni = 0; ni < 8; ++ni)
                    mmatf32(acc[mi][ni], a[mi], b[ni]);
        }
        __syncthreads();
    }

    // epilogue: per-row partial of tanh(v + g_q)*Wl over these 256 cols
    const int gq4 = lane >> 2;
    const int q   = lane & 3;
    const int bIdx = row0 >> 11;

    float* red = (float*)dsm;      // [4 ngroups][128 rows]
    float rowsum[4][2];
    #pragma unroll
    for (int mi = 0; mi < 4; ++mi)
        #pragma unroll
        for (int hf = 0; hf < 2; ++hf) {
            float s = 0.f;
            #pragma unroll
            for (int ni = 0; ni < 8; ++ni) {
                int c = col0 + wn + ni*8 + q*2;
                float v0 = acc[mi][ni][hf*2+0] + g_q[bIdx*Hd + c];
                float v1 = acc[mi][ni][hf*2+1] + g_q[bIdx*Hd + c + 1];
                s += tanhf(v0) * Wl[c] + tanhf(v1) * Wl[c+1];
            }
            s += __shfl_xor_sync(0xffffffffu, s, 1);
            s += __shfl_xor_sync(0xffffffffu, s, 2);
            rowsum[mi][hf] = s;
        }
    if (q == 0) {
        #pragma unroll
        for (int mi = 0; mi < 4; ++mi)
            #pragma unroll
            for (int hf = 0; hf < 2; ++hf) {
                int lr = wm + mi*16 + gq4 + hf*8;
                red[(wid >> 1) * 128 + lr] = rowsum[mi][hf];
            }
    }
    __syncthreads();
    if (tid < 128) {
        float s = red[tid] + red[128 + tid] + red[256 + tid] + red[384 + tid];
        g_part[(size_t)(row0 + tid) * 4 + ct] = s;
    }
}

// ============================================================
// tgemm<EPI, NT, NSTG>: HMMA bf16-split GEMM (gx / gh).
// EPI1: gx (NT=192, NCT=2) — epi +qg2 + w·av -> g_GX
// EPI2: gh (NT=128, NCT=3) — epi +gbhh       -> g_GH
// ============================================================
template<int EPI, int NT, int NSTG>
__global__ __launch_bounds__(256)
void tgemm(const float* __restrict__ p0)
{
    constexpr int NCT  = (EPI==1) ? 2 : 3;
    constexpr int KTOT = (EPI==2) ? CSd : KC;
    constexpr int NST  = KTOT / 32;
    constexpr int BSTR = (EPI==2) ? CSd : KC;
    constexpr int AOFF = (EPI==2) ? KSd : 0;
    constexpr int NF   = NT / 32;
    constexpr int WNS  = NT / 4;
    constexpr uint32_t STAGEB = (uint32_t)(BOFF + NT*SROW*2);

    const __nv_bfloat16* Bh = (EPI==1) ? g_WFhi : g_WHhi;
    const __nv_bfloat16* Bl = (EPI==1) ? g_WFlo : g_WHlo;

    extern __shared__ __align__(16) char dsm[];
    const uint32_t sbase = s2u(dsm);

    const int tid = threadIdx.x;
    const int wid = tid >> 5, lane = tid & 31;
    const int ct = blockIdx.x % NCT, rt = blockIdx.x / NCT;
    const int row0 = rt * 128, col0 = ct * NT;
    const int wm = (wid & 1) * 64;
    const int wn = (wid >> 1) * WNS;

    auto load_stage = [&](int s, int stg) {
        const uint32_t sb = sbase + (uint32_t)stg * STAGEB;
        const int kc = s * 32;
        #pragma unroll
        for (int j = 0; j < 2; ++j) {
            int idx = tid + j*256;
            int r = idx >> 2, cu = idx & 3;
            size_t ao = (size_t)(row0 + r) * KC + AOFF + kc + cu*8;
            uint32_t sa = sb + (uint32_t)(r*SROW + cu*16);
            CP16(sa,         g_Ahi + ao);
            CP16(sa + ATILE, g_Alo + ao);
        }
        #pragma unroll
        for (int j = 0; j < NT/64; ++j) {
            int idx = tid + j*256;
            int r = idx >> 2, cu = idx & 3;
            size_t bo = (size_t)(col0 + r) * BSTR + kc + cu*8;
            uint32_t sa = sb + BOFF + (uint32_t)(r*SROW + cu*16);
            CP16(sa,                        Bh + bo);
            CP16(sa + (uint32_t)(NT*SROW), Bl + bo);
        }
    };

    float acc[4][NF][4];
    #pragma unroll
    for (int i = 0; i < 4; ++i)
        #pragma unroll
        for (int j = 0; j < NF; ++j)
            #pragma unroll
            for (int k = 0; k < 4; ++k) acc[i][j][k] = 0.f;

    const int arow = wm + (lane & 7) + ((lane >> 3) & 1) * 8;
    const uint32_t akb = (uint32_t)(((lane >> 4) & 1) * 16);
    const int brow = wn + (lane & 7) + ((lane >> 4) & 1) * 8;
    const uint32_t bkb = (uint32_t)(((lane >> 3) & 1) * 16);

    #pragma unroll
    for (int i = 0; i < NSTG-1; ++i) { load_stage(i, i); CPCOMMIT(); }

    for (int s = 0; s < NST; ++s) {
        if (s + NSTG - 1 < NST) {
            load_stage(s + NSTG - 1, (s + NSTG - 1) % NSTG);
            CPCOMMIT();
            if (NSTG == 3) CPWAIT2(); else CPWAIT1();
        } else {
            CPWAIT0();
        }
        __syncthreads();

        const uint32_t sb = sbase + (uint32_t)(s % NSTG) * STAGEB;
        #pragma unroll
        for (int kh = 0; kh < 2; ++kh) {
            const uint32_t ko = (uint32_t)(kh * 32);
            uint32_t ah[4][4], al[4][4], bh[NF][2], bl[NF][2];
            #pragma unroll
            for (int mi = 0; mi < 4; ++mi) {
                uint32_t ad = sb + (uint32_t)((arow + mi*16) * SROW) + ko + akb;
                ldsm4(ah[mi], ad);
                ldsm4(al[mi], ad + ATILE);
            }
            #pragma unroll
            for (int ni = 0; ni < NF; ni += 2) {
                uint32_t bd = sb + BOFF + (uint32_t)((brow + ni*8) * SROW) + ko + bkb;
                ldsm4(&bh[ni][0], bd);
                ldsm4(&bl[ni][0], bd + (uint32_t)(NT*SROW));
            }
            #pragma unroll
            for (int mi = 0; mi < 4; ++mi)
                #pragma unroll
                for (int ni = 0; ni < NF; ++ni) {
                    mma16816(acc[mi][ni], ah[mi], bh[ni]);
                    mma16816(acc[mi][ni], ah[mi], bl[ni]);
                    mma16816(acc[mi][ni], al[mi], bh[ni]);
                }
        }
        __syncthreads();
    }

    const int gq4 = lane >> 2;
    const int q   = lane & 3;
    const int bIdx = row0 >> 11;

    if (EPI == 1) {
        #pragma unroll
        for (int mi = 0; mi < 4; ++mi)
            #pragma unroll
            for (int hf = 0; hf < 2; ++hf) {
                int r = row0 + wm + mi*16 + gq4 + hf*8;
                float wr = p0[r];
                #pragma unroll
                for (int ni = 0; ni < NF; ++ni) {
                    int c = col0 + wn + ni*8 + q*2;
                    float2 v;
                    v.x = acc[mi][ni][hf*2+0] + g_qg2[bIdx*G3 + c  ] + wr * g_av[c  ];
                    v.y = acc[mi][ni][hf*2+1] + g_qg2[bIdx*G3 + c+1] + wr * g_av[c+1];
                    *(float2*)(g_GX + (size_t)r * G3 + c) = v;
                }
            }
    } else {
        #pragma unroll
        for (int mi = 0; mi < 4; ++mi)
            #pragma unroll
            for (int hf = 0; hf < 2; ++hf) {
                int r = row0 + wm + mi*16 + gq4 + hf*8;
                #pragma unroll
                for (int ni = 0; ni < NF; ++ni) {
                    int c = col0 + wn + ni*8 + q*2;
                    float2 v;
                    v.x = acc[mi][ni][hf*2+0] + p0[c  ];
                    v.y = acc[mi][ni][hf*2+1] + p0[c+1];
                    *(float2*)(g_GH + (size_t)r * G3 + c) = v;
                }
            }
    }
}

// ============================================================
// masked softmax from 4 fixed-order partials + bl (mask dtype autodetect)
// ============================================================
__global__ void softmax_k(const void* __restrict__ maskp, const float* __restrict__ bl,
                          float* __restrict__ wout)
{
    __shared__ float sv[MM];
    __shared__ float red[256];
    __shared__ unsigned int ured[256];
    const int b = blockIdx.x;
    const int tid = threadIdx.x;

    const unsigned char* mbp = (const unsigned char*)maskp;
    unsigned int orr = 0;
    for (int i = tid; i < BB*MM; i += 256)
        if (i & 3) orr |= mbp[i];
    ured[tid] = orr;
    __syncthreads();
    for (int s = 128; s; s >>= 1) { if (tid < s) ured[tid] |= ured[tid + s]; __syncthreads(); }
    const bool isI32 = (ured[0] == 0);
    __syncthreads();

    const float blv = bl[0];
    for (int m = tid; m < MM; m += 256) {
        bool pad = isI32 ? (((const int*)maskp)[b*MM + m] != 0)
                         : (mbp[b*MM + m] != 0);
        if (pad) sv[m] = -1e30f;
        else {
            const float* p = g_part + (size_t)(b*MM + m) * 4;
            sv[m] = (p[0] + p[1]) + (p[2] + p[3]) + blv;
        }
    }
    __syncthreads();

    float mx = -3.4e38f;
    for (int m = tid; m < MM; m += 256) mx = fmaxf(mx, sv[m]);
    red[tid] = mx;
    __syncthreads();
    for (int s = 128; s; s >>= 1) { if (tid < s) red[tid] = fmaxf(red[tid], red[tid + s]); __syncthreads(); }
    mx = red[0];
    __syncthreads();

    float sum = 0.f;
    for (int m = tid; m < MM; m += 256) { float e = expf(sv[m] - mx); sv[m] = e; sum += e; }
    red[tid] = sum;
    __syncthreads();
    for (int s = 128; s; s >>= 1) { if (tid < s) red[tid] += red[tid + s]; __syncthreads(); }
    float inv = 1.f / red[0];
    __syncthreads();

    for (int m = tid; m < MM; m += 256) wout[b*MM + m] = sv[m] * inv;
}

// ============================================================
// attns[b][k] = sum_m w[b][m] * memory[b][m][k]
// ============================================================
__global__ void attns_k(const float* __restrict__ memory,
                        const float* __restrict__ w,
                        float* __restrict__ out)
{
    __shared__ float ws[MM];
    const int b = blockIdx.x;
    const int k = blockIdx.y * 256 + threadIdx.x;
    for (int i = threadIdx.x; i < MM; i += 256) ws[i] = w[b*MM + i];
    __syncthreads();
    const float* mp = memory + (size_t)b * MM * KSd + k;
    float a0 = 0.f, a1 = 0.f, a2 = 0.f, a3 = 0.f;
    for (int m = 0; m < MM; m += 4) {
        a0 += ws[m+0] * mp[(size_t)(m+0) * KSd];
        a1 += ws[m+1] * mp[(size_t)(m+1) * KSd];
        a2 += ws[m+2] * mp[(size_t)(m+2) * KSd];
        a3 += ws[m+3] * mp[(size_t)(m+3) * KSd];
    }
    out[b*KSd + k] = (a0 + a1) + (a2 + a3);
}

// ============================================================
// GRU elementwise
// ============================================================
__global__ void gru_k(const float* __restrict__ coverage, float* __restrict__ outc)
{
    size_t idx = (size_t)blockIdx.x * 256 + threadIdx.x;
    int r = (int)(idx >> 7);
    int c = (int)(idx & 127);
    size_t gi = (size_t)r * G3 + c;
    float xr = g_GX[gi],       hr = g_GH[gi];
    float xz = g_GX[gi + 128], hz = g_GH[gi + 128];
    float xn = g_GX[gi + 256], hn = g_GH[gi + 256];
    float rg = 1.f / (1.f + expf(-(xr + hr)));
    float z  = 1.f / (1.f + expf(-(xz + hz)));
    float n  = tanhf(xn + rg * hn);
    outc[idx] = (1.f - z) * n + z * coverage[idx];
}

// ============================================================
extern "C" void kernel_launch(void* const* d_in, const int* in_sizes, int n_in,
                              void* d_out, int out_size)
{
    const float* query   = (const float*)d_in[0];
    const float* memory  = (const float*)d_in[1];
    const float* coverage= (const float*)d_in[2];
    const float* Wq  = (const float*)d_in[3];  const float* bq  = (const float*)d_in[4];
    const float* Wk  = (const float*)d_in[5];  const float* bk  = (const float*)d_in[6];
    const float* Wc  = (const float*)d_in[7];  const float* bc  = (const float*)d_in[8];
    const float* Wcc = (const float*)d_in[9];  const float* bcc = (const float*)d_in[10];
    const float* Wqc = (const float*)d_in[11]; const float* bqc = (const float*)d_in[12];
    const float* Wkc = (const float*)d_in[13]; const float* bkc = (const float*)d_in[14];
    const float* Wac = (const float*)d_in[15]; const float* bac = (const float*)d_in[16];
    const float* Wl  = (const float*)d_in[17]; const float* bl  = (const float*)d_in[18];
    const float* gwih= (const float*)d_in[19]; const float* gbih= (const float*)d_in[20];
    const float* gwhh= (const float*)d_in[21]; const float* gbhh= (const float*)d_in[22];
    const void*  maskp = d_in[23];

    float* out      = (float*)d_out;
    float* out_attn = out;
    float* out_w    = out + BB*KSd;
    float* out_cov  = out + BB*KSd + BB*MM;

    const int DSM1 = 3 * (BOFF + 192*SROW*2);   // 153600
    const int DSM2 = 2 * (BOFF + 128*SROW*2);   // 81920

    static int attr_done = 0;
    if (!attr_done) {
        cudaFuncSetAttribute((const void*)tgemm_tf32,    cudaFuncAttributeMaxDynamicSharedMemorySize, DSMTF);
        cudaFuncSetAttribute((const void*)tgemm<1,192,3>, cudaFuncAttributeMaxDynamicSharedMemorySize, DSM1);
        cudaFuncSetAttribute((const void*)tgemm<2,128,2>, cudaFuncAttributeMaxDynamicSharedMemorySize, DSM2);
        attr_done = 1;
    }

    // prep
    qprep<<<(BB*Hd)/8, 256>>>(query, Wq, bq, bk, bc, Wqc, bqc, bkc, bcc, bac);
    prep2<<<(33*G3*32 + 255)/256, 256>>>(gwih, gbih, Wac);
    wfuse_k<<<27, 256>>>(Wkc, Wcc, gwih);

    // operand conversions
    convsplit<0><<<36864, 256>>>(memory, coverage);   // A: bf16 hi/lo + tf32
    convsplit<1><<<576,   256>>>(Wk, Wc);             // [Wk|Wc] -> tf32
    convsplit<2><<<216,   256>>>(nullptr, nullptr);   // Wfuse -> bf16 hi/lo
    convsplit<3><<<24,    256>>>(gwhh, nullptr);      // gwhh -> bf16 hi/lo

    // scores (tf32 single-pass, 128x256 tiles) -> partials
    tgemm_tf32<<<(RR/128)*4, 256, DSMTF>>>(Wl);

    // softmax -> weights
    softmax_k<<<BB, 256>>>(maskp, bl, out_w);

    // attns
    attns_k<<<dim3(BB, KSd/256), 256>>>(memory, out_w, out_attn);

    // gx (128x192) / gh (128x128), bf16x3
    tgemm<1,192,3><<<(RR/128)*2, 256, DSM1>>>(out_w);
    tgemm<2,128,2><<<(RR/128)*3, 256, DSM2>>>(gbhh);

    // GRU elementwise -> new_coverage
    gru_k<<<(RR*CSd)/256, 256>>>(coverage, out_cov);
}

// round 11
// speedup vs baseline: 4.2388x; 1.1276x over previous
#include <cuda_runtime.h>
#include <math.h>
#include <stdint.h>

#define BB  32
#define MM  2048
#define QSd 1024
#define KSd 1024
#define Hd  1024
#define CSd 128
#define RR  (BB*MM)     // 65536 rows
#define G3  384
#define KC  1152        // concat K = KS + CS

// ---------------- scratch (static device globals) ----------------
static __device__ float g_q[BB*Hd];
static __device__ float g_qc[BB*Hd];
static __device__ float g_qg2[BB*G3];
static __device__ float g_av[G3];
static __device__ float g_part[(size_t)RR*4];
static __device__ float g_GX[(size_t)RR*G3];
static __device__ float g_GH[(size_t)RR*G3];
// tf32-rounded weight operands
static __device__ uint32_t g_WBtf[(size_t)1024*KC];   // [Wk|Wc]
static __device__ uint32_t g_WFtf[(size_t)G3*KC];     // wih @ [Wkc|Wcc]
static __device__ uint32_t g_WHtf[(size_t)G3*CSd];    // gwhh

// ---------------- PTX helpers (base ISA, sm_80+) ----------------
__device__ __forceinline__ uint32_t s2u(const void* p){
    uint32_t a;
    asm("{ .reg .u64 t; cvta.to.shared.u64 t, %1; cvt.u32.u64 %0, t; }" : "=r"(a) : "l"(p));
    return a;
}
__device__ __forceinline__ uint32_t f2tf32(float x){
    uint32_t r; asm("cvt.rna.tf32.f32 %0, %1;" : "=r"(r) : "f"(x)); return r;
}
__device__ __forceinline__ uint32_t u2tf32(uint32_t x){
    uint32_t r; asm("cvt.rna.tf32.f32 %0, %1;" : "=r"(r) : "f"(__uint_as_float(x))); return r;
}
#define CP16(dst, gsrc) \
    asm volatile("cp.async.cg.shared.global [%0], [%1], 16;" \
                 :: "r"(dst), "l"(__cvta_generic_to_global(gsrc)) : "memory")
#define CPCOMMIT() asm volatile("cp.async.commit_group;" ::: "memory")
#define CPWAIT2()  asm volatile("cp.async.wait_group 2;" ::: "memory")
#define CPWAIT0()  asm volatile("cp.async.wait_group 0;" ::: "memory")

__device__ __forceinline__ void ldsm4(uint32_t* r, uint32_t addr){
    asm volatile("ldmatrix.sync.aligned.m8n8.x4.shared.b16 {%0,%1,%2,%3}, [%4];"
        : "=r"(r[0]), "=r"(r[1]), "=r"(r[2]), "=r"(r[3]) : "r"(addr));
}
__device__ __forceinline__ void mmatf32(float* d, const uint32_t* a, const uint32_t* b){
    asm volatile("mma.sync.aligned.m16n8k8.row.col.f32.tf32.tf32.f32 "
        "{%0,%1,%2,%3}, {%4,%5,%6,%7}, {%8,%9}, {%0,%1,%2,%3};"
        : "+f"(d[0]), "+f"(d[1]), "+f"(d[2]), "+f"(d[3])
        : "r"(a[0]), "r"(a[1]), "r"(a[2]), "r"(a[3]), "r"(b[0]), "r"(b[1]));
}

#define SR4     144u
#define ATILE4  (128u*SR4)           // 18432

// ============================================================
// qprep: q / qc projections, biases folded. Warp per (b,h).
// ============================================================
__global__ void qprep(const float* __restrict__ query,
                      const float* __restrict__ Wq,  const float* __restrict__ bq,
                      const float* __restrict__ bk,  const float* __restrict__ bc,
                      const float* __restrict__ Wqc, const float* __restrict__ bqc,
                      const float* __restrict__ bkc, const float* __restrict__ bcc,
                      const float* __restrict__ bac)
{
    int gw   = (blockIdx.x * blockDim.x + threadIdx.x) >> 5;
    int lane = threadIdx.x & 31;
    if (gw >= BB*Hd) return;
    int b = gw >> 10, h = gw & 1023;
    const float* q  = query + (size_t)b * QSd;
    const float* w1 = Wq  + (size_t)h * QSd;
    const float* w2 = Wqc + (size_t)h * QSd;
    float a1 = 0.f, a2 = 0.f;
    for (int k = lane; k < QSd; k += 32) {
        float qv = q[k];
        a1 += qv * w1[k];
        a2 += qv * w2[k];
    }
    #pragma unroll
    for (int o = 16; o; o >>= 1) {
        a1 += __shfl_xor_sync(0xffffffffu, a1, o);
        a2 += __shfl_xor_sync(0xffffffffu, a2, o);
    }
    if (!lane) {
        g_q[gw]  = a1 + bq[h]  + bk[h]  + bc[h];
        g_qc[gw] = a2 + bqc[h] + bkc[h] + bcc[h] + bac[h];
    }
}

// ============================================================
// prep2: qg2[b][g] = g_qc[b]·wih[g] + bih[g] ; av[g] = Wac·wih[g]
// ============================================================
__global__ void prep2(const float* __restrict__ wih, const float* __restrict__ bih,
                      const float* __restrict__ Wac)
{
    int gw   = (blockIdx.x * blockDim.x + threadIdx.x) >> 5;
    int lane = threadIdx.x & 31;
    if (gw >= 33*G3) return;
    if (gw < 32*G3) {
        int b = gw / G3, g = gw % G3;
        const float* x  = g_qc + (size_t)b * Hd;
        const float* wr = wih  + (size_t)g * Hd;
        float a = 0.f;
        for (int h = lane; h < Hd; h += 32) a += x[h] * wr[h];
        #pragma unroll
        for (int o = 16; o; o >>= 1) a += __shfl_xor_sync(0xffffffffu, a, o);
        if (!lane) g_qg2[gw] = a + bih[g];
    } else {
        int g = gw - 32*G3;
        const float* wr = wih + (size_t)g * Hd;
        float a = 0.f;
        for (int h = lane; h < Hd; h += 32) a += Wac[h] * wr[h];
        #pragma unroll
        for (int o = 16; o; o >>= 1) a += __shfl_xor_sync(0xffffffffu, a, o);
        if (!lane) g_av[g] = a;
    }
}

// ============================================================
// wfuse_k: g_WFtf = tf32( wih @ [Wkc|Wcc] )  (fp32 SIMT, 27 blocks)
// ============================================================
__global__ __launch_bounds__(256)
void wfuse_k(const float* __restrict__ Wkc, const float* __restrict__ Wcc,
             const float* __restrict__ wih)
{
    __shared__ __align__(16) float as[8][132];
    __shared__ __align__(16) float bs[8][132];
    const int tid = threadIdx.x;
    const int tx = tid & 15, ty = tid >> 4;
    const int lr = tid >> 1, lk = (tid & 1) * 4;
    const int row0 = (blockIdx.x / 9) * 128;   // g
    const int col0 = (blockIdx.x % 9) * 128;   // k_out
    const int kk8 = tid >> 5, c4 = (tid & 31) * 4;

    float acc[8][8];
    #pragma unroll
    for (int i = 0; i < 8; ++i)
        #pragma unroll
        for (int j = 0; j < 8; ++j) acc[i][j] = 0.f;

    for (int k0 = 0; k0 < Hd; k0 += 8) {
        float4 av4 = *(const float4*)(wih + (size_t)(row0 + lr) * Hd + k0 + lk);
        float4 wv;
        if (col0 < KSd)
            wv = *(const float4*)(Wkc + (size_t)(k0 + kk8) * KSd + col0 + c4);
        else
            wv = *(const float4*)(Wcc + (size_t)(k0 + kk8) * CSd + (col0 - KSd) + c4);
        __syncthreads();
        as[lk+0][lr] = av4.x; as[lk+1][lr] = av4.y;
        as[lk+2][lr] = av4.z; as[lk+3][lr] = av4.w;
        *(float4*)&bs[kk8][c4] = wv;
        __syncthreads();
        #pragma unroll
        for (int kk = 0; kk < 8; ++kk) {
            float ar[8], br[8];
            #pragma unroll
            for (int i = 0; i < 4; ++i) { ar[i] = as[kk][ty*4+i]; ar[4+i] = as[kk][64+ty*4+i]; }
            #pragma unroll
            for (int j = 0; j < 4; ++j) { br[j] = bs[kk][tx*4+j]; br[4+j] = bs[kk][64+tx*4+j]; }
            #pragma unroll
            for (int i = 0; i < 8; ++i)
                #pragma unroll
                for (int j = 0; j < 8; ++j)
                    acc[i][j] += ar[i] * br[j];
        }
    }
    #pragma unroll
    for (int i = 0; i < 8; ++i) {
        int r = row0 + ((i < 4) ? (ty*4 + i) : (64 + ty*4 + i - 4));
        #pragma unroll
        for (int jh = 0; jh < 2; ++jh) {
            int cb = col0 + jh*64 + tx*4;
            __align__(16) uint32_t tv[4];
            #pragma unroll
            for (int j = 0; j < 4; ++j) tv[j] = f2tf32(acc[i][jh*4+j]);
            *(uint4*)(g_WFtf + (size_t)r * KC + cb) = *(uint4*)tv;
        }
    }
}

// ============================================================
// convW<T>: weights -> tf32.  T0: [Wk|Wc] -> g_WBtf.  T1: gwhh -> g_WHtf.
// ============================================================
template<int T>
__global__ void convW(const float* __restrict__ s0, const float* __restrict__ s1)
{
    constexpr int COLS  = (T==0) ? KC : CSd;
    constexpr int COLS0 = (T==0) ? KSd : CSd;
    constexpr long long ROWS = (T==0) ? 1024LL : (long long)G3;
    uint32_t* dst = (T==0) ? g_WBtf : g_WHtf;

    long long t = (long long)blockIdx.x * 256 + threadIdx.x;
    if (t >= ROWS * COLS / 8) return;
    long long e = t * 8;
    int c = (int)(e % COLS);
    long long r = e / COLS;

    float4 v0, v1;
    if (c < COLS0) {
        const float4* p = (const float4*)(s0 + r * COLS0 + c);
        v0 = p[0]; v1 = p[1];
    } else {
        const float4* p = (const float4*)(s1 + r * (COLS - COLS0) + (c - COLS0));
        v0 = p[0]; v1 = p[1];
    }
    float v[8] = {v0.x, v0.y, v0.z, v0.w, v1.x, v1.y, v1.z, v1.w};
    __align__(16) uint32_t tv[8];
    #pragma unroll
    for (int j = 0; j < 8; ++j) tv[j] = f2tf32(v[j]);
    *(uint4*)(dst + r * COLS + c) = *(uint4*)tv;
    *(uint4*)(dst + r * COLS + c + 4) = *(uint4*)(tv + 4);
}

// ============================================================
// tgemm32<EPI, NT, NSTG>: single-pass tf32 GEMM (mma m16n8k8).
// A loaded raw fp32 from [memory|coverage], rounded in-register (cvt.rna).
// 128 x NT CTA tile, 8 warps (2m x 4n), K chunk 32, NSTG-stage cp.async.
// EPI0: scores (NT=256, NCT=4) — epi tanh(.+g_q)·Wl -> g_part
// EPI1: gx     (NT=192, NCT=2) — epi +qg2 + w·av    -> g_GX
// EPI2: gh     (NT=128, NCT=3) — A=coverage, epi +gbhh -> g_GH
// ============================================================
template<int EPI, int NT, int NSTG>
__global__ __launch_bounds__(256)
void tgemm32(const float* __restrict__ A0, const float* __restrict__ A1,
             const float* __restrict__ p0)
{
    constexpr int NCT  = (EPI==0) ? 4 : (EPI==1) ? 2 : 3;
    constexpr int KTOT = (EPI==2) ? CSd : KC;
    constexpr int NST  = KTOT / 32;
    constexpr int BSTR = (EPI==2) ? CSd : KC;
    constexpr int NF   = NT / 32;
    constexpr int WNS  = NT / 4;
    constexpr uint32_t STAGEB = ATILE4 + (uint32_t)NT * SR4;

    const uint32_t* Btf = (EPI==0) ? g_WBtf : (EPI==1) ? g_WFtf : g_WHtf;

    extern __shared__ __align__(16) char dsm[];
    const uint32_t sbase = s2u(dsm);

    const int tid = threadIdx.x;
    const int wid = tid >> 5, lane = tid & 31;
    const int ct = blockIdx.x % NCT, rt = blockIdx.x / NCT;
    const int row0 = rt * 128, col0 = ct * NT;
    const int wm = (wid & 1) * 64;
    const int wn = (wid >> 1) * WNS;

    auto load_stage = [&](int s, int stg) {
        const uint32_t sb = sbase + (uint32_t)stg * STAGEB;
        const int kc = s * 32;
        #pragma unroll
        for (int j = 0; j < 4; ++j) {       // A: 1024 16B chunks (fp32)
            int idx = tid + j*256;
            int r = idx >> 3, cu = idx & 7;
            const float* src;
            if (EPI == 2) src = A0 + (size_t)(row0 + r) * CSd + kc + cu*4;
            else if (kc < KSd) src = A0 + (size_t)(row0 + r) * KSd + kc + cu*4;
            else src = A1 + (size_t)(row0 + r) * CSd + (kc - KSd) + cu*4;
            CP16(sb + (uint32_t)(r*SR4 + cu*16), src);
        }
        #pragma unroll
        for (int j = 0; j < NT/32; ++j) {   // B: NT*8 chunks (tf32)
            int idx = tid + j*256;
            int r = idx >> 3, cu = idx & 7;
            CP16(sb + ATILE4 + (uint32_t)(r*SR4 + cu*16),
                 Btf + (size_t)(col0 + r) * BSTR + kc + cu*4);
        }
    };

    float acc[4][NF][4];
    #pragma unroll
    for (int i = 0; i < 4; ++i)
        #pragma unroll
        for (int j = 0; j < NF; ++j)
            #pragma unroll
            for (int k = 0; k < 4; ++k) acc[i][j][k] = 0.f;

    const int arow = wm + (lane & 7) + ((lane >> 3) & 1) * 8;
    const uint32_t akb = (uint32_t)(((lane >> 4) & 1) * 16);
    const int brow = wn + (lane & 7) + ((lane >> 4) & 1) * 8;
    const uint32_t bkb = (uint32_t)(((lane >> 3) & 1) * 16);

    #pragma unroll
    for (int i = 0; i < NSTG-1 && i < NST; ++i) { load_stage(i, i); CPCOMMIT(); }

    for (int s = 0; s < NST; ++s) {
        if (s + NSTG - 1 < NST) {
            load_stage(s + NSTG - 1, (s + NSTG - 1) % NSTG);
            CPCOMMIT(); CPWAIT2();
        } else {
            CPWAIT0();
        }
        __syncthreads();

        const uint32_t sb = sbase + (uint32_t)(s % NSTG) * STAGEB;
        #pragma unroll
        for (int kq = 0; kq < 4; ++kq) {
            const uint32_t ko = (uint32_t)(kq * 32);
            uint32_t a[4][4], b[NF][2];
            #pragma unroll
            for (int mi = 0; mi < 4; ++mi) {
                ldsm4(a[mi], sb + (uint32_t)((arow + mi*16) * SR4) + ko + akb);
                #pragma unroll
                for (int j = 0; j < 4; ++j) a[mi][j] = u2tf32(a[mi][j]);
            }
            #pragma unroll
            for (int ni = 0; ni < NF; ni += 2)
                ldsm4(&b[ni][0], sb + ATILE4 + (uint32_t)((brow + ni*8) * SR4) + ko + bkb);
            #pragma unroll
            for (int mi = 0; mi < 4; ++mi)
                #pragma unroll
                for (int ni = 0; ni < NF; ++ni)
                    mmatf32(acc[mi][ni], a[mi], b[ni]);
        }
        __syncthreads();
    }

    // -------- epilogues --------
    const int gq4 = lane >> 2;
    const int q   = lane & 3;
    const int bIdx = row0 >> 11;

    if (EPI == 0) {
        float* red = (float*)dsm;      // [4 ngroups][128 rows]
        float rowsum[4][2];
        #pragma unroll
        for (int mi = 0; mi < 4; ++mi)
            #pragma unroll
            for (int hf = 0; hf < 2; ++hf) {
                float s = 0.f;
                #pragma unroll
                for (int ni = 0; ni < NF; ++ni) {
                    int c = col0 + wn + ni*8 + q*2;
                    float v0 = acc[mi][ni][hf*2+0] + g_q[bIdx*Hd + c];
                    float v1 = acc[mi][ni][hf*2+1] + g_q[bIdx*Hd + c + 1];
                    s += tanhf(v0) * p0[c] + tanhf(v1) * p0[c+1];
                }
                s += __shfl_xor_sync(0xffffffffu, s, 1);
                s += __shfl_xor_sync(0xffffffffu, s, 2);
                rowsum[mi][hf] = s;
            }
        if (q == 0) {
            #pragma unroll
            for (int mi = 0; mi < 4; ++mi)
                #pragma unroll
                for (int hf = 0; hf < 2; ++hf) {
                    int lr = wm + mi*16 + gq4 + hf*8;
                    red[(wid >> 1) * 128 + lr] = rowsum[mi][hf];
                }
        }
        __syncthreads();
        if (tid < 128) {
            float s = red[tid] + red[128 + tid] + red[256 + tid] + red[384 + tid];
            g_part[(size_t)(row0 + tid) * 4 + ct] = s;
        }
    } else if (EPI == 1) {
        #pragma unroll
        for (int mi = 0; mi < 4; ++mi)
            #pragma unroll
            for (int hf = 0; hf < 2; ++hf) {
                int r = row0 + wm + mi*16 + gq4 + hf*8;
                float wr = p0[r];
                #pragma unroll
                for (int ni = 0; ni < NF; ++ni) {
                    int c = col0 + wn + ni*8 + q*2;
                    float2 v;
                    v.x = acc[mi][ni][hf*2+0] + g_qg2[bIdx*G3 + c  ] + wr * g_av[c  ];
                    v.y = acc[mi][ni][hf*2+1] + g_qg2[bIdx*G3 + c+1] + wr * g_av[c+1];
                    *(float2*)(g_GX + (size_t)r * G3 + c) = v;
                }
            }
    } else {
        #pragma unroll
        for (int mi = 0; mi < 4; ++mi)
            #pragma unroll
            for (int hf = 0; hf < 2; ++hf) {
                int r = row0 + wm + mi*16 + gq4 + hf*8;
                #pragma unroll
                for (int ni = 0; ni < NF; ++ni) {
                    int c = col0 + wn + ni*8 + q*2;
                    float2 v;
                    v.x = acc[mi][ni][hf*2+0] + p0[c  ];
                    v.y = acc[mi][ni][hf*2+1] + p0[c+1];
                    *(float2*)(g_GH + (size_t)r * G3 + c) = v;
                }
            }
    }
}

// ============================================================
// masked softmax from 4 fixed-order partials + bl (mask dtype autodetect)
// ============================================================
__global__ void softmax_k(const void* __restrict__ maskp, const float* __restrict__ bl,
                          float* __restrict__ wout)
{
    __shared__ float sv[MM];
    __shared__ float red[256];
    __shared__ unsigned int ured[256];
    const int b = blockIdx.x;
    const int tid = threadIdx.x;

    const unsigned char* mbp = (const unsigned char*)maskp;
    unsigned int orr = 0;
    for (int i = tid; i < BB*MM; i += 256)
        if (i & 3) orr |= mbp[i];
    ured[tid] = orr;
    __syncthreads();
    for (int s = 128; s; s >>= 1) { if (tid < s) ured[tid] |= ured[tid + s]; __syncthreads(); }
    const bool isI32 = (ured[0] == 0);
    __syncthreads();

    const float blv = bl[0];
    for (int m = tid; m < MM; m += 256) {
        bool pad = isI32 ? (((const int*)maskp)[b*MM + m] != 0)
                         : (mbp[b*MM + m] != 0);
        if (pad) sv[m] = -1e30f;
        else {
            const float* p = g_part + (size_t)(b*MM + m) * 4;
            sv[m] = (p[0] + p[1]) + (p[2] + p[3]) + blv;
        }
    }
    __syncthreads();

    float mx = -3.4e38f;
    for (int m = tid; m < MM; m += 256) mx = fmaxf(mx, sv[m]);
    red[tid] = mx;
    __syncthreads();
    for (int s = 128; s; s >>= 1) { if (tid < s) red[tid] = fmaxf(red[tid], red[tid + s]); __syncthreads(); }
    mx = red[0];
    __syncthreads();

    float sum = 0.f;
    for (int m = tid; m < MM; m += 256) { float e = expf(sv[m] - mx); sv[m] = e; sum += e; }
    red[tid] = sum;
    __syncthreads();
    for (int s = 128; s; s >>= 1) { if (tid < s) red[tid] += red[tid + s]; __syncthreads(); }
    float inv = 1.f / red[0];
    __syncthreads();

    for (int m = tid; m < MM; m += 256) wout[b*MM + m] = sv[m] * inv;
}

// ============================================================
// attns[b][k] = sum_m w[b][m] * memory[b][m][k]
// ============================================================
__global__ void attns_k(const float* __restrict__ memory,
                        const float* __restrict__ w,
                        float* __restrict__ out)
{
    __shared__ float ws[MM];
    const int b = blockIdx.x;
    const int k = blockIdx.y * 256 + threadIdx.x;
    for (int i = threadIdx.x; i < MM; i += 256) ws[i] = w[b*MM + i];
    __syncthreads();
    const float* mp = memory + (size_t)b * MM * KSd + k;
    float a0 = 0.f, a1 = 0.f, a2 = 0.f, a3 = 0.f;
    for (int m = 0; m < MM; m += 4) {
        a0 += ws[m+0] * mp[(size_t)(m+0) * KSd];
        a1 += ws[m+1] * mp[(size_t)(m+1) * KSd];
        a2 += ws[m+2] * mp[(size_t)(m+2) * KSd];
        a3 += ws[m+3] * mp[(size_t)(m+3) * KSd];
    }
    out[b*KSd + k] = (a0 + a1) + (a2 + a3);
}

// ============================================================
// GRU elementwise
// ============================================================
__global__ void gru_k(const float* __restrict__ coverage, float* __restrict__ outc)
{
    size_t idx = (size_t)blockIdx.x * 256 + threadIdx.x;
    int r = (int)(idx >> 7);
    int c = (int)(idx & 127);
    size_t gi = (size_t)r * G3 + c;
    float xr = g_GX[gi],       hr = g_GH[gi];
    float xz = g_GX[gi + 128], hz = g_GH[gi + 128];
    float xn = g_GX[gi + 256], hn = g_GH[gi + 256];
    float rg = 1.f / (1.f + expf(-(xr + hr)));
    float z  = 1.f / (1.f + expf(-(xz + hz)));
    float n  = tanhf(xn + rg * hn);
    outc[idx] = (1.f - z) * n + z * coverage[idx];
}

// ============================================================
extern "C" void kernel_launch(void* const* d_in, const int* in_sizes, int n_in,
                              void* d_out, int out_size)
{
    const float* query   = (const float*)d_in[0];
    const float* memory  = (const float*)d_in[1];
    const float* coverage= (const float*)d_in[2];
    const float* Wq  = (const float*)d_in[3];  const float* bq  = (const float*)d_in[4];
    const float* Wk  = (const float*)d_in[5];  const float* bk  = (const float*)d_in[6];
    const float* Wc  = (const float*)d_in[7];  const float* bc  = (const float*)d_in[8];
    const float* Wcc = (const float*)d_in[9];  const float* bcc = (const float*)d_in[10];
    const float* Wqc = (const float*)d_in[11]; const float* bqc = (const float*)d_in[12];
    const float* Wkc = (const float*)d_in[13]; const float* bkc = (const float*)d_in[14];
    const float* Wac = (const float*)d_in[15]; const float* bac = (const float*)d_in[16];
    const float* Wl  = (const float*)d_in[17]; const float* bl  = (const float*)d_in[18];
    const float* gwih= (const float*)d_in[19]; const float* gbih= (const float*)d_in[20];
    const float* gwhh= (const float*)d_in[21]; const float* gbhh= (const float*)d_in[22];
    const void*  maskp = d_in[23];

    float* out      = (float*)d_out;
    float* out_attn = out;
    float* out_w    = out + BB*KSd;
    float* out_cov  = out + BB*KSd + BB*MM;

    const int DSM0 = 3 * (int)(ATILE4 + 256*SR4);   // 165888
    const int DSM1 = 3 * (int)(ATILE4 + 192*SR4);   // 138240
    const int DSM2 = 3 * (int)(ATILE4 + 128*SR4);   // 110592

    static int attr_done = 0;
    if (!attr_done) {
        cudaFuncSetAttribute((const void*)tgemm32<0,256,3>, cudaFuncAttributeMaxDynamicSharedMemorySize, DSM0);
        cudaFuncSetAttribute((const void*)tgemm32<1,192,3>, cudaFuncAttributeMaxDynamicSharedMemorySize, DSM1);
        cudaFuncSetAttribute((const void*)tgemm32<2,128,3>, cudaFuncAttributeMaxDynamicSharedMemorySize, DSM2);
        attr_done = 1;
    }

    // prep
    qprep<<<(BB*Hd)/8, 256>>>(query, Wq, bq, bk, bc, Wqc, bqc, bkc, bcc, bac);
    prep2<<<(33*G3*32 + 255)/256, 256>>>(gwih, gbih, Wac);
    wfuse_k<<<27, 256>>>(Wkc, Wcc, gwih);

    // weight conversions to tf32
    convW<0><<<576, 256>>>(Wk, Wc);       // [Wk|Wc]
    convW<1><<<24,  256>>>(gwhh, nullptr);

    // scores (tf32, 128x256 tiles) -> partials
    tgemm32<0,256,3><<<(RR/128)*4, 256, DSM0>>>(memory, coverage, Wl);

    // softmax -> weights
    softmax_k<<<BB, 256>>>(maskp, bl, out_w);

    // attns
    attns_k<<<dim3(BB, KSd/256), 256>>>(memory, out_w, out_attn);

    // gx (128x192) / gh (128x128), tf32
    tgemm32<1,192,3><<<(RR/128)*2, 256, DSM1>>>(memory, coverage, out_w);
    tgemm32<2,128,3><<<(RR/128)*3, 256, DSM2>>>(coverage, nullptr, gbhh);

    // GRU elementwise -> new_coverage
    gru_k<<<(RR*CSd)/256, 256>>>(coverage, out_cov);
}

// round 12
// speedup vs baseline: 6.0316x; 1.4229x over previous
#include <cuda_runtime.h>
#include <cuda_fp16.h>
#include <math.h>
#include <stdint.h>

#define BB  32
#define MM  2048
#define QSd 1024
#define KSd 1024
#define Hd  1024
#define CSd 128
#define RR  (BB*MM)     // 65536 rows
#define G3  384
#define KC  1152        // concat K = KS + CS

// ---------------- scratch (static device globals) ----------------
static __device__ float g_q[BB*Hd];
static __device__ float g_qc[BB*Hd];
static __device__ float g_qg2[BB*G3];
static __device__ float g_av[G3];
static __device__ float g_part[(size_t)RR*4];
static __device__ float g_GX[(size_t)RR*G3];
static __device__ float g_GH[(size_t)RR*G3];
// fp16 operands
static __device__ __half g_Af16[(size_t)RR*KC];      // [memory|coverage]
static __device__ __half g_WBh[(size_t)1024*KC];     // [Wk|Wc]
static __device__ __half g_WFh[(size_t)G3*KC];       // wih @ [Wkc|Wcc]
static __device__ __half g_WHh[(size_t)G3*CSd];      // gwhh

// ---------------- PTX helpers (base ISA, sm_80+) ----------------
__device__ __forceinline__ uint32_t s2u(const void* p){
    uint32_t a;
    asm("{ .reg .u64 t; cvta.to.shared.u64 t, %1; cvt.u32.u64 %0, t; }" : "=r"(a) : "l"(p));
    return a;
}
#define CP16(dst, gsrc) \
    asm volatile("cp.async.cg.shared.global [%0], [%1], 16;" \
                 :: "r"(dst), "l"(__cvta_generic_to_global(gsrc)) : "memory")
#define CPCOMMIT() asm volatile("cp.async.commit_group;" ::: "memory")
template<int N> __device__ __forceinline__ void cpwait(){
    asm volatile("cp.async.wait_group %0;" :: "n"(N) : "memory");
}
__device__ __forceinline__ void ldsm4(uint32_t* r, uint32_t addr){
    asm volatile("ldmatrix.sync.aligned.m8n8.x4.shared.b16 {%0,%1,%2,%3}, [%4];"
        : "=r"(r[0]), "=r"(r[1]), "=r"(r[2]), "=r"(r[3]) : "r"(addr));
}
__device__ __forceinline__ void mmaf16(float* d, const uint32_t* a, const uint32_t* b){
    asm volatile("mma.sync.aligned.m16n8k16.row.col.f32.f16.f16.f32 "
        "{%0,%1,%2,%3}, {%4,%5,%6,%7}, {%8,%9}, {%0,%1,%2,%3};"
        : "+f"(d[0]), "+f"(d[1]), "+f"(d[2]), "+f"(d[3])
        : "r"(a[0]), "r"(a[1]), "r"(a[2]), "r"(a[3]), "r"(b[0]), "r"(b[1]));
}

#define SROW   80
#define ATILE  (128*SROW)          // 10240 bytes (128 rows x 32 fp16 + pad)

// ============================================================
// qprep: q / qc projections, biases folded. Warp per (b,h).
// ============================================================
__global__ void qprep(const float* __restrict__ query,
                      const float* __restrict__ Wq,  const float* __restrict__ bq,
                      const float* __restrict__ bk,  const float* __restrict__ bc,
                      const float* __restrict__ Wqc, const float* __restrict__ bqc,
                      const float* __restrict__ bkc, const float* __restrict__ bcc,
                      const float* __restrict__ bac)
{
    int gw   = (blockIdx.x * blockDim.x + threadIdx.x) >> 5;
    int lane = threadIdx.x & 31;
    if (gw >= BB*Hd) return;
    int b = gw >> 10, h = gw & 1023;
    const float* q  = query + (size_t)b * QSd;
    const float* w1 = Wq  + (size_t)h * QSd;
    const float* w2 = Wqc + (size_t)h * QSd;
    float a1 = 0.f, a2 = 0.f;
    for (int k = lane; k < QSd; k += 32) {
        float qv = q[k];
        a1 += qv * w1[k];
        a2 += qv * w2[k];
    }
    #pragma unroll
    for (int o = 16; o; o >>= 1) {
        a1 += __shfl_xor_sync(0xffffffffu, a1, o);
        a2 += __shfl_xor_sync(0xffffffffu, a2, o);
    }
    if (!lane) {
        g_q[gw]  = a1 + bq[h]  + bk[h]  + bc[h];
        g_qc[gw] = a2 + bqc[h] + bkc[h] + bcc[h] + bac[h];
    }
}

// ============================================================
// prep2: qg2[b][g] = g_qc[b]·wih[g] + bih[g] ; av[g] = Wac·wih[g]
// ============================================================
__global__ void prep2(const float* __restrict__ wih, const float* __restrict__ bih,
                      const float* __restrict__ Wac)
{
    int gw   = (blockIdx.x * blockDim.x + threadIdx.x) >> 5;
    int lane = threadIdx.x & 31;
    if (gw >= 33*G3) return;
    if (gw < 32*G3) {
        int b = gw / G3, g = gw % G3;
        const float* x  = g_qc + (size_t)b * Hd;
        const float* wr = wih  + (size_t)g * Hd;
        float a = 0.f;
        for (int h = lane; h < Hd; h += 32) a += x[h] * wr[h];
        #pragma unroll
        for (int o = 16; o; o >>= 1) a += __shfl_xor_sync(0xffffffffu, a, o);
        if (!lane) g_qg2[gw] = a + bih[g];
    } else {
        int g = gw - 32*G3;
        const float* wr = wih + (size_t)g * Hd;
        float a = 0.f;
        for (int h = lane; h < Hd; h += 32) a += Wac[h] * wr[h];
        #pragma unroll
        for (int o = 16; o; o >>= 1) a += __shfl_xor_sync(0xffffffffu, a, o);
        if (!lane) g_av[g] = a;
    }
}

// ============================================================
// wfuse_k: g_WFh = fp16( wih @ [Wkc|Wcc] )  (fp32 SIMT, 27 blocks)
// ============================================================
__global__ __launch_bounds__(256)
void wfuse_k(const float* __restrict__ Wkc, const float* __restrict__ Wcc,
             const float* __restrict__ wih)
{
    __shared__ __align__(16) float as[8][132];
    __shared__ __align__(16) float bs[8][132];
    const int tid = threadIdx.x;
    const int tx = tid & 15, ty = tid >> 4;
    const int lr = tid >> 1, lk = (tid & 1) * 4;
    const int row0 = (blockIdx.x / 9) * 128;   // g
    const int col0 = (blockIdx.x % 9) * 128;   // k_out
    const int kk8 = tid >> 5, c4 = (tid & 31) * 4;

    float acc[8][8];
    #pragma unroll
    for (int i = 0; i < 8; ++i)
        #pragma unroll
        for (int j = 0; j < 8; ++j) acc[i][j] = 0.f;

    for (int k0 = 0; k0 < Hd; k0 += 8) {
        float4 av4 = *(const float4*)(wih + (size_t)(row0 + lr) * Hd + k0 + lk);
        float4 wv;
        if (col0 < KSd)
            wv = *(const float4*)(Wkc + (size_t)(k0 + kk8) * KSd + col0 + c4);
        else
            wv = *(const float4*)(Wcc + (size_t)(k0 + kk8) * CSd + (col0 - KSd) + c4);
        __syncthreads();
        as[lk+0][lr] = av4.x; as[lk+1][lr] = av4.y;
        as[lk+2][lr] = av4.z; as[lk+3][lr] = av4.w;
        *(float4*)&bs[kk8][c4] = wv;
        __syncthreads();
        #pragma unroll
        for (int kk = 0; kk < 8; ++kk) {
            float ar[8], br[8];
            #pragma unroll
            for (int i = 0; i < 4; ++i) { ar[i] = as[kk][ty*4+i]; ar[4+i] = as[kk][64+ty*4+i]; }
            #pragma unroll
            for (int j = 0; j < 4; ++j) { br[j] = bs[kk][tx*4+j]; br[4+j] = bs[kk][64+tx*4+j]; }
            #pragma unroll
            for (int i = 0; i < 8; ++i)
                #pragma unroll
                for (int j = 0; j < 8; ++j)
                    acc[i][j] += ar[i] * br[j];
        }
    }
    #pragma unroll
    for (int i = 0; i < 8; ++i) {
        int r = row0 + ((i < 4) ? (ty*4 + i) : (64 + ty*4 + i - 4));
        #pragma unroll
        for (int jh = 0; jh < 2; ++jh) {
            int cb = col0 + jh*64 + tx*4;
            __align__(8) __half hv[4];
            #pragma unroll
            for (int j = 0; j < 4; ++j) hv[j] = __float2half_rn(acc[i][jh*4+j]);
            *(uint2*)(g_WFh + (size_t)r * KC + cb) = *(uint2*)hv;
        }
    }
}

// ============================================================
// convA: fp32 [memory|coverage] -> g_Af16 (RR x KC), 8 elems/thread
// convW<T>: T0: [Wk|Wc] -> g_WBh.  T1: gwhh -> g_WHh.
// ============================================================
__global__ void convA(const float* __restrict__ s0, const float* __restrict__ s1)
{
    long long t = (long long)blockIdx.x * 256 + threadIdx.x;
    if (t >= (long long)RR * KC / 8) return;
    long long e = t * 8;
    int c = (int)(e % KC);
    long long r = e / KC;
    float4 v0, v1;
    if (c < KSd) {
        const float4* p = (const float4*)(s0 + r * KSd + c);
        v0 = p[0]; v1 = p[1];
    } else {
        const float4* p = (const float4*)(s1 + r * CSd + (c - KSd));
        v0 = p[0]; v1 = p[1];
    }
    float v[8] = {v0.x, v0.y, v0.z, v0.w, v1.x, v1.y, v1.z, v1.w};
    __align__(16) __half hv[8];
    #pragma unroll
    for (int j = 0; j < 8; ++j) hv[j] = __float2half_rn(v[j]);
    *(uint4*)(g_Af16 + r * KC + c) = *(uint4*)hv;
}

template<int T>
__global__ void convW(const float* __restrict__ s0, const float* __restrict__ s1)
{
    constexpr int COLS  = (T==0) ? KC : CSd;
    constexpr int COLS0 = (T==0) ? KSd : CSd;
    constexpr long long ROWS = (T==0) ? 1024LL : (long long)G3;
    __half* dst = (T==0) ? g_WBh : g_WHh;

    long long t = (long long)blockIdx.x * 256 + threadIdx.x;
    if (t >= ROWS * COLS / 8) return;
    long long e = t * 8;
    int c = (int)(e % COLS);
    long long r = e / COLS;
    float4 v0, v1;
    if (c < COLS0) {
        const float4* p = (const float4*)(s0 + r * COLS0 + c);
        v0 = p[0]; v1 = p[1];
    } else {
        const float4* p = (const float4*)(s1 + r * (COLS - COLS0) + (c - COLS0));
        v0 = p[0]; v1 = p[1];
    }
    float v[8] = {v0.x, v0.y, v0.z, v0.w, v1.x, v1.y, v1.z, v1.w};
    __align__(16) __half hv[8];
    #pragma unroll
    for (int j = 0; j < 8; ++j) hv[j] = __float2half_rn(v[j]);
    *(uint4*)(dst + r * COLS + c) = *(uint4*)hv;
}

// ============================================================
// tgemm16<EPI, NT, NSTG>: single-pass fp16 GEMM (mma m16n8k16).
// 128 x NT CTA tile, 8 warps (2m x 4n), K chunk 32, NSTG-stage cp.async.
// EPI0: scores (NT=256, NCT=4) — epi tanh(.+g_q)·Wl -> g_part
// EPI1: gx     (NT=192, NCT=2) — epi +qg2 + w·av    -> g_GX
// EPI2: gh     (NT=128, NCT=3) — A=coverage cols, epi +gbhh -> g_GH
// ============================================================
template<int EPI, int NT, int NSTG>
__global__ __launch_bounds__(256)
void tgemm16(const float* __restrict__ p0)
{
    constexpr int NCT  = (EPI==0) ? 4 : (EPI==1) ? 2 : 3;
    constexpr int KTOT = (EPI==2) ? CSd : KC;
    constexpr int NST  = KTOT / 32;
    constexpr int BSTR = (EPI==2) ? CSd : KC;
    constexpr int AOFF = (EPI==2) ? KSd : 0;
    constexpr int NF   = NT / 32;
    constexpr int WNS  = NT / 4;
    constexpr uint32_t STAGEB = (uint32_t)(ATILE + NT*SROW);

    const __half* Bp = (EPI==0) ? g_WBh : (EPI==1) ? g_WFh : g_WHh;

    extern __shared__ __align__(16) char dsm[];
    const uint32_t sbase = s2u(dsm);

    const int tid = threadIdx.x;
    const int wid = tid >> 5, lane = tid & 31;
    const int ct = blockIdx.x % NCT, rt = blockIdx.x / NCT;
    const int row0 = rt * 128, col0 = ct * NT;
    const int wm = (wid & 1) * 64;
    const int wn = (wid >> 1) * WNS;

    auto load_stage = [&](int s, int stg) {
        const uint32_t sb = sbase + (uint32_t)stg * STAGEB;
        const int kc = s * 32;
        #pragma unroll
        for (int j = 0; j < 2; ++j) {       // A: 512 16B chunks (fp16)
            int idx = tid + j*256;
            int r = idx >> 2, cu = idx & 3;
            CP16(sb + (uint32_t)(r*SROW + cu*16),
                 g_Af16 + (size_t)(row0 + r) * KC + AOFF + kc + cu*8);
        }
        #pragma unroll
        for (int j = 0; j < NT/64; ++j) {   // B: NT*4 chunks
            int idx = tid + j*256;
            int r = idx >> 2, cu = idx & 3;
            CP16(sb + (uint32_t)ATILE + (uint32_t)(r*SROW + cu*16),
                 Bp + (size_t)(col0 + r) * BSTR + kc + cu*8);
        }
    };

    float acc[4][NF][4];
    #pragma unroll
    for (int i = 0; i < 4; ++i)
        #pragma unroll
        for (int j = 0; j < NF; ++j)
            #pragma unroll
            for (int k = 0; k < 4; ++k) acc[i][j][k] = 0.f;

    const int arow = wm + (lane & 7) + ((lane >> 3) & 1) * 8;
    const uint32_t akb = (uint32_t)(((lane >> 4) & 1) * 16);
    const int brow = wn + (lane & 7) + ((lane >> 4) & 1) * 8;
    const uint32_t bkb = (uint32_t)(((lane >> 3) & 1) * 16);

    #pragma unroll
    for (int i = 0; i < NSTG-1 && i < NST; ++i) { load_stage(i, i); CPCOMMIT(); }

    for (int s = 0; s < NST; ++s) {
        if (s + NSTG - 1 < NST) {
            load_stage(s + NSTG - 1, (s + NSTG - 1) % NSTG);
            CPCOMMIT(); cpwait<NSTG-1>();
        } else {
            cpwait<0>();
        }
        __syncthreads();

        const uint32_t sb = sbase + (uint32_t)(s % NSTG) * STAGEB;
        #pragma unroll
        for (int kh = 0; kh < 2; ++kh) {
            const uint32_t ko = (uint32_t)(kh * 32);
            uint32_t a[4][4], b[NF][2];
            #pragma unroll
            for (int mi = 0; mi < 4; ++mi)
                ldsm4(a[mi], sb + (uint32_t)((arow + mi*16) * SROW) + ko + akb);
            #pragma unroll
            for (int ni = 0; ni < NF; ni += 2)
                ldsm4(&b[ni][0], sb + (uint32_t)ATILE + (uint32_t)((brow + ni*8) * SROW) + ko + bkb);
            #pragma unroll
            for (int mi = 0; mi < 4; ++mi)
                #pragma unroll
                for (int ni = 0; ni < NF; ++ni)
                    mmaf16(acc[mi][ni], a[mi], b[ni]);
        }
        __syncthreads();
    }

    // -------- epilogues --------
    const int gq4 = lane >> 2;
    const int q   = lane & 3;
    const int bIdx = row0 >> 11;

    if (EPI == 0) {
        float* red = (float*)dsm;      // [4 ngroups][128 rows]
        float rowsum[4][2];
        #pragma unroll
        for (int mi = 0; mi < 4; ++mi)
            #pragma unroll
            for (int hf = 0; hf < 2; ++hf) {
                float s = 0.f;
                #pragma unroll
                for (int ni = 0; ni < NF; ++ni) {
                    int c = col0 + wn + ni*8 + q*2;
                    float v0 = acc[mi][ni][hf*2+0] + g_q[bIdx*Hd + c];
                    float v1 = acc[mi][ni][hf*2+1] + g_q[bIdx*Hd + c + 1];
                    s += tanhf(v0) * p0[c] + tanhf(v1) * p0[c+1];
                }
                s += __shfl_xor_sync(0xffffffffu, s, 1);
                s += __shfl_xor_sync(0xffffffffu, s, 2);
                rowsum[mi][hf] = s;
            }
        if (q == 0) {
            #pragma unroll
            for (int mi = 0; mi < 4; ++mi)
                #pragma unroll
                for (int hf = 0; hf < 2; ++hf) {
                    int lr = wm + mi*16 + gq4 + hf*8;
                    red[(wid >> 1) * 128 + lr] = rowsum[mi][hf];
                }
        }
        __syncthreads();
        if (tid < 128) {
            float s = red[tid] + red[128 + tid] + red[256 + tid] + red[384 + tid];
            g_part[(size_t)(row0 + tid) * 4 + ct] = s;
        }
    } else if (EPI == 1) {
        #pragma unroll
        for (int mi = 0; mi < 4; ++mi)
            #pragma unroll
            for (int hf = 0; hf < 2; ++hf) {
                int r = row0 + wm + mi*16 + gq4 + hf*8;
                float wr = p0[r];
                #pragma unroll
                for (int ni = 0; ni < NF; ++ni) {
                    int c = col0 + wn + ni*8 + q*2;
                    float2 v;
                    v.x = acc[mi][ni][hf*2+0] + g_qg2[bIdx*G3 + c  ] + wr * g_av[c  ];
                    v.y = acc[mi][ni][hf*2+1] + g_qg2[bIdx*G3 + c+1] + wr * g_av[c+1];
                    *(float2*)(g_GX + (size_t)r * G3 + c) = v;
                }
            }
    } else {
        #pragma unroll
        for (int mi = 0; mi < 4; ++mi)
            #pragma unroll
            for (int hf = 0; hf < 2; ++hf) {
                int r = row0 + wm + mi*16 + gq4 + hf*8;
                #pragma unroll
                for (int ni = 0; ni < NF; ++ni) {
                    int c = col0 + wn + ni*8 + q*2;
                    float2 v;
                    v.x = acc[mi][ni][hf*2+0] + p0[c  ];
                    v.y = acc[mi][ni][hf*2+1] + p0[c+1];
                    *(float2*)(g_GH + (size_t)r * G3 + c) = v;
                }
            }
    }
}

// ============================================================
// masked softmax from 4 fixed-order partials + bl (mask dtype autodetect)
// ============================================================
__global__ void softmax_k(const void* __restrict__ maskp, const float* __restrict__ bl,
                          float* __restrict__ wout)
{
    __shared__ float sv[MM];
    __shared__ float red[256];
    __shared__ unsigned int ured[256];
    const int b = blockIdx.x;
    const int tid = threadIdx.x;

    const unsigned char* mbp = (const unsigned char*)maskp;
    unsigned int orr = 0;
    for (int i = tid; i < BB*MM; i += 256)
        if (i & 3) orr |= mbp[i];
    ured[tid] = orr;
    __syncthreads();
    for (int s = 128; s; s >>= 1) { if (tid < s) ured[tid] |= ured[tid + s]; __syncthreads(); }
    const bool isI32 = (ured[0] == 0);
    __syncthreads();

    const float blv = bl[0];
    for (int m = tid; m < MM; m += 256) {
        bool pad = isI32 ? (((const int*)maskp)[b*MM + m] != 0)
                         : (mbp[b*MM + m] != 0);
        if (pad) sv[m] = -1e30f;
        else {
            const float* p = g_part + (size_t)(b*MM + m) * 4;
            sv[m] = (p[0] + p[1]) + (p[2] + p[3]) + blv;
        }
    }
    __syncthreads();

    float mx = -3.4e38f;
    for (int m = tid; m < MM; m += 256) mx = fmaxf(mx, sv[m]);
    red[tid] = mx;
    __syncthreads();
    for (int s = 128; s; s >>= 1) { if (tid < s) red[tid] = fmaxf(red[tid], red[tid + s]); __syncthreads(); }
    mx = red[0];
    __syncthreads();

    float sum = 0.f;
    for (int m = tid; m < MM; m += 256) { float e = expf(sv[m] - mx); sv[m] = e; sum += e; }
    red[tid] = sum;
    __syncthreads();
    for (int s = 128; s; s >>= 1) { if (tid < s) red[tid] += red[tid + s]; __syncthreads(); }
    float inv = 1.f / red[0];
    __syncthreads();

    for (int m = tid; m < MM; m += 256) wout[b*MM + m] = sv[m] * inv;
}

// ============================================================
// attns[b][k] = sum_m w[b][m] * memory[b][m][k]
// ============================================================
__global__ void attns_k(const float* __restrict__ memory,
                        const float* __restrict__ w,
                        float* __restrict__ out)
{
    __shared__ float ws[MM];
    const int b = blockIdx.x;
    const int k = blockIdx.y * 256 + threadIdx.x;
    for (int i = threadIdx.x; i < MM; i += 256) ws[i] = w[b*MM + i];
    __syncthreads();
    const float* mp = memory + (size_t)b * MM * KSd + k;
    float a0 = 0.f, a1 = 0.f, a2 = 0.f, a3 = 0.f;
    for (int m = 0; m < MM; m += 4) {
        a0 += ws[m+0] * mp[(size_t)(m+0) * KSd];
        a1 += ws[m+1] * mp[(size_t)(m+1) * KSd];
        a2 += ws[m+2] * mp[(size_t)(m+2) * KSd];
        a3 += ws[m+3] * mp[(size_t)(m+3) * KSd];
    }
    out[b*KSd + k] = (a0 + a1) + (a2 + a3);
}

// ============================================================
// GRU elementwise
// ============================================================
__global__ void gru_k(const float* __restrict__ coverage, float* __restrict__ outc)
{
    size_t idx = (size_t)blockIdx.x * 256 + threadIdx.x;
    int r = (int)(idx >> 7);
    int c = (int)(idx & 127);
    size_t gi = (size_t)r * G3 + c;
    float xr = g_GX[gi],       hr = g_GH[gi];
    float xz = g_GX[gi + 128], hz = g_GH[gi + 128];
    float xn = g_GX[gi + 256], hn = g_GH[gi + 256];
    float rg = 1.f / (1.f + expf(-(xr + hr)));
    float z  = 1.f / (1.f + expf(-(xz + hz)));
    float n  = tanhf(xn + rg * hn);
    outc[idx] = (1.f - z) * n + z * coverage[idx];
}

// ============================================================
extern "C" void kernel_launch(void* const* d_in, const int* in_sizes, int n_in,
                              void* d_out, int out_size)
{
    const float* query   = (const float*)d_in[0];
    const float* memory  = (const float*)d_in[1];
    const float* coverage= (const float*)d_in[2];
    const float* Wq  = (const float*)d_in[3];  const float* bq  = (const float*)d_in[4];
    const float* Wk  = (const float*)d_in[5];  const float* bk  = (const float*)d_in[6];
    const float* Wc  = (const float*)d_in[7];  const float* bc  = (const float*)d_in[8];
    const float* Wcc = (const float*)d_in[9];  const float* bcc = (const float*)d_in[10];
    const float* Wqc = (const float*)d_in[11]; const float* bqc = (const float*)d_in[12];
    const float* Wkc = (const float*)d_in[13]; const float* bkc = (const float*)d_in[14];
    const float* Wac = (const float*)d_in[15]; const float* bac = (const float*)d_in[16];
    const float* Wl  = (const float*)d_in[17]; const float* bl  = (const float*)d_in[18];
    const float* gwih= (const float*)d_in[19]; const float* gbih= (const float*)d_in[20];
    const float* gwhh= (const float*)d_in[21]; const float* gbhh= (const float*)d_in[22];
    const void*  maskp = d_in[23];

    float* out      = (float*)d_out;
    float* out_attn = out;
    float* out_w    = out + BB*KSd;
    float* out_cov  = out + BB*KSd + BB*MM;

    const int DSM0 = 4 * (ATILE + 256*SROW);   // 122880
    const int DSM1 = 4 * (ATILE + 192*SROW);   // 102400
    const int DSM2 = 3 * (ATILE + 128*SROW);   // 61440

    static int attr_done = 0;
    if (!attr_done) {
        cudaFuncSetAttribute((const void*)tgemm16<0,256,4>, cudaFuncAttributeMaxDynamicSharedMemorySize, DSM0);
        cudaFuncSetAttribute((const void*)tgemm16<1,192,4>, cudaFuncAttributeMaxDynamicSharedMemorySize, DSM1);
        cudaFuncSetAttribute((const void*)tgemm16<2,128,3>, cudaFuncAttributeMaxDynamicSharedMemorySize, DSM2);
        attr_done = 1;
    }

    // prep
    qprep<<<(BB*Hd)/8, 256>>>(query, Wq, bq, bk, bc, Wqc, bqc, bkc, bcc, bac);
    prep2<<<(33*G3*32 + 255)/256, 256>>>(gwih, gbih, Wac);
    wfuse_k<<<27, 256>>>(Wkc, Wcc, gwih);

    // fp16 conversions
    convA<<<36864, 256>>>(memory, coverage);
    convW<0><<<576, 256>>>(Wk, Wc);
    convW<1><<<24,  256>>>(gwhh, nullptr);

    // scores (fp16, 128x256 tiles) -> partials
    tgemm16<0,256,4><<<(RR/128)*4, 256, DSM0>>>(Wl);

    // softmax -> weights
    softmax_k<<<BB, 256>>>(maskp, bl, out_w);

    // attns
    attns_k<<<dim3(BB, KSd/256), 256>>>(memory, out_w, out_attn);

    // gx (128x192) / gh (128x128), fp16
    tgemm16<1,192,4><<<(RR/128)*2, 256, DSM1>>>(out_w);
    tgemm16<2,128,3><<<(RR/128)*3, 256, DSM2>>>(gbhh);

    // GRU elementwise -> new_coverage
    gru_k<<<(RR*CSd)/256, 256>>>(coverage, out_cov);
}

// round 15
// speedup vs baseline: 7.5427x; 1.2505x over previous
#include <cuda_runtime.h>
#include <cuda_fp16.h>
#include <math.h>
#include <stdint.h>

#define BB  32
#define MM  2048
#define QSd 1024
#define KSd 1024
#define Hd  1024
#define CSd 128
#define RR  (BB*MM)     // 65536 rows
#define G3  384
#define KC  1152        // concat K = KS + CS

// ---------------- scratch (static device globals) ----------------
static __device__ float g_q[BB*Hd];
static __device__ float g_qc[BB*Hd];
static __device__ float g_qg2[BB*G3];
static __device__ float g_av[G3];
static __device__ float g_part[(size_t)RR*4];
static __device__ float g_GX[(size_t)RR*G3];
static __device__ float g_GH[(size_t)RR*G3];
static __device__ float g_Wfp[8][(size_t)G3*KC];     // wfuse split-K partials
static __device__ int   g_isI32;
// fp16 operands
static __device__ __half g_Af16[(size_t)RR*KC];      // [memory|coverage]
static __device__ __half g_WBh[(size_t)1024*KC];     // [Wk|Wc]
static __device__ __half g_WFh[(size_t)G3*KC];       // wih @ [Wkc|Wcc]
static __device__ __half g_WHh[(size_t)G3*CSd];      // gwhh

// ---------------- PTX helpers (base ISA, sm_80+) ----------------
__device__ __forceinline__ uint32_t s2u(const void* p){
    uint32_t a;
    asm("{ .reg .u64 t; cvta.to.shared.u64 t, %1; cvt.u32.u64 %0, t; }" : "=r"(a) : "l"(p));
    return a;
}
#define CP16(dst, gsrc) \
    asm volatile("cp.async.cg.shared.global [%0], [%1], 16;" \
                 :: "r"(dst), "l"(__cvta_generic_to_global(gsrc)) : "memory")
#define CPCOMMIT() asm volatile("cp.async.commit_group;" ::: "memory")
template<int N> __device__ __forceinline__ void cpwait(){
    asm volatile("cp.async.wait_group %0;" :: "n"(N) : "memory");
}
__device__ __forceinline__ void ldsm4(uint32_t* r, uint32_t addr){
    asm volatile("ldmatrix.sync.aligned.m8n8.x4.shared.b16 {%0,%1,%2,%3}, [%4];"
        : "=r"(r[0]), "=r"(r[1]), "=r"(r[2]), "=r"(r[3]) : "r"(addr));
}
__device__ __forceinline__ void mmaf16(float* d, const uint32_t* a, const uint32_t* b){
    asm volatile("mma.sync.aligned.m16n8k16.row.col.f32.f16.f16.f32 "
        "{%0,%1,%2,%3}, {%4,%5,%6,%7}, {%8,%9}, {%0,%1,%2,%3};"
        : "+f"(d[0]), "+f"(d[1]), "+f"(d[2]), "+f"(d[3])
        : "r"(a[0]), "r"(a[1]), "r"(a[2]), "r"(a[3]), "r"(b[0]), "r"(b[1]));
}

#define SROW   80
#define ATILE  (128*SROW)          // 10240 bytes

// ============================================================
// mask_detect: one block scans mask; bytes at i%4!=0 all zero => int32
// ============================================================
__global__ void mask_detect(const void* __restrict__ maskp)
{
    __shared__ unsigned int ured[1024];
    const unsigned char* mbp = (const unsigned char*)maskp;
    unsigned int orr = 0;
    for (int i = threadIdx.x; i < BB*MM; i += 1024)
        if (i & 3) orr |= mbp[i];
    ured[threadIdx.x] = orr;
    __syncthreads();
    for (int s = 512; s; s >>= 1) {
        if (threadIdx.x < s) ured[threadIdx.x] |= ured[threadIdx.x + s];
        __syncthreads();
    }
    if (!threadIdx.x) g_isI32 = (ured[0] == 0) ? 1 : 0;
}

// ============================================================
// qprep: q / qc projections, biases folded. Warp per (b,h).
// ============================================================
__global__ void qprep(const float* __restrict__ query,
                      const float* __restrict__ Wq,  const float* __restrict__ bq,
                      const float* __restrict__ bk,  const float* __restrict__ bc,
                      const float* __restrict__ Wqc, const float* __restrict__ bqc,
                      const float* __restrict__ bkc, const float* __restrict__ bcc,
                      const float* __restrict__ bac)
{
    int gw   = (blockIdx.x * blockDim.x + threadIdx.x) >> 5;
    int lane = threadIdx.x & 31;
    if (gw >= BB*Hd) return;
    int b = gw >> 10, h = gw & 1023;
    const float* q  = query + (size_t)b * QSd;
    const float* w1 = Wq  + (size_t)h * QSd;
    const float* w2 = Wqc + (size_t)h * QSd;
    float a1 = 0.f, a2 = 0.f;
    for (int k = lane; k < QSd; k += 32) {
        float qv = q[k];
        a1 += qv * w1[k];
        a2 += qv * w2[k];
    }
    #pragma unroll
    for (int o = 16; o; o >>= 1) {
        a1 += __shfl_xor_sync(0xffffffffu, a1, o);
        a2 += __shfl_xor_sync(0xffffffffu, a2, o);
    }
    if (!lane) {
        g_q[gw]  = a1 + bq[h]  + bk[h]  + bc[h];
        g_qc[gw] = a2 + bqc[h] + bkc[h] + bcc[h] + bac[h];
    }
}

// ============================================================
// prep2: qg2[b][g] = g_qc[b]·wih[g] + bih[g] ; av[g] = Wac·wih[g]
// ============================================================
__global__ void prep2(const float* __restrict__ wih, const float* __restrict__ bih,
                      const float* __restrict__ Wac)
{
    int gw   = (blockIdx.x * blockDim.x + threadIdx.x) >> 5;
    int lane = threadIdx.x & 31;
    if (gw >= 33*G3) return;
    if (gw < 32*G3) {
        int b = gw / G3, g = gw % G3;
        const float* x  = g_qc + (size_t)b * Hd;
        const float* wr = wih  + (size_t)g * Hd;
        float a = 0.f;
        for (int h = lane; h < Hd; h += 32) a += x[h] * wr[h];
        #pragma unroll
        for (int o = 16; o; o >>= 1) a += __shfl_xor_sync(0xffffffffu, a, o);
        if (!lane) g_qg2[gw] = a + bih[g];
    } else {
        int g = gw - 32*G3;
        const float* wr = wih + (size_t)g * Hd;
        float a = 0.f;
        for (int h = lane; h < Hd; h += 32) a += Wac[h] * wr[h];
        #pragma unroll
        for (int o = 16; o; o >>= 1) a += __shfl_xor_sync(0xffffffffu, a, o);
        if (!lane) g_av[g] = a;
    }
}

// ============================================================
// wfuse_part: split-K partials of wih @ [Wkc|Wcc].
// 216 blocks: slice = bid/27 (K range 128), tile = bid%27 (3x9 of 128x128).
// ============================================================
__global__ __launch_bounds__(256)
void wfuse_part(const float* __restrict__ Wkc, const float* __restrict__ Wcc,
                const float* __restrict__ wih)
{
    __shared__ __align__(16) float as[8][132];
    __shared__ __align__(16) float bs[8][132];
    const int tid = threadIdx.x;
    const int tx = tid & 15, ty = tid >> 4;
    const int lr = tid >> 1, lk = (tid & 1) * 4;
    const int slice = blockIdx.x / 27;
    const int t27   = blockIdx.x % 27;
    const int row0 = (t27 / 9) * 128;   // g
    const int col0 = (t27 % 9) * 128;   // k_out
    const int ks   = slice * 128;
    const int kk8 = tid >> 5, c4 = (tid & 31) * 4;

    float acc[8][8];
    #pragma unroll
    for (int i = 0; i < 8; ++i)
        #pragma unroll
        for (int j = 0; j < 8; ++j) acc[i][j] = 0.f;

    for (int k0 = ks; k0 < ks + 128; k0 += 8) {
        float4 av4 = *(const float4*)(wih + (size_t)(row0 + lr) * Hd + k0 + lk);
        float4 wv;
        if (col0 < KSd)
            wv = *(const float4*)(Wkc + (size_t)(k0 + kk8) * KSd + col0 + c4);
        else
            wv = *(const float4*)(Wcc + (size_t)(k0 + kk8) * CSd + (col0 - KSd) + c4);
        __syncthreads();
        as[lk+0][lr] = av4.x; as[lk+1][lr] = av4.y;
        as[lk+2][lr] = av4.z; as[lk+3][lr] = av4.w;
        *(float4*)&bs[kk8][c4] = wv;
        __syncthreads();
        #pragma unroll
        for (int kk = 0; kk < 8; ++kk) {
            float ar[8], br[8];
            #pragma unroll
            for (int i = 0; i < 4; ++i) { ar[i] = as[kk][ty*4+i]; ar[4+i] = as[kk][64+ty*4+i]; }
            #pragma unroll
            for (int j = 0; j < 4; ++j) { br[j] = bs[kk][tx*4+j]; br[4+j] = bs[kk][64+tx*4+j]; }
            #pragma unroll
            for (int i = 0; i < 8; ++i)
                #pragma unroll
                for (int j = 0; j < 8; ++j)
                    acc[i][j] += ar[i] * br[j];
        }
    }
    float* dst = g_Wfp[slice];
    #pragma unroll
    for (int i = 0; i < 8; ++i) {
        int r = row0 + ((i < 4) ? (ty*4 + i) : (64 + ty*4 + i - 4));
        #pragma unroll
        for (int jh = 0; jh < 2; ++jh) {
            int cb = col0 + jh*64 + tx*4;
            float4 v; v.x = acc[i][jh*4+0]; v.y = acc[i][jh*4+1];
            v.z = acc[i][jh*4+2]; v.w = acc[i][jh*4+3];
            *(float4*)(dst + (size_t)r * KC + cb) = v;
        }
    }
}

// ============================================================
// wfuse_reduce: sum 8 partial slices (fixed order) -> fp16 g_WFh
// ============================================================
__global__ void wfuse_reduce()
{
    int base = (blockIdx.x * 256 + threadIdx.x) * 4;
    if (base >= G3*KC) return;
    float4 s = *(const float4*)(g_Wfp[0] + base);
    #pragma unroll
    for (int p = 1; p < 8; ++p) {
        float4 v = *(const float4*)(g_Wfp[p] + base);
        s.x += v.x; s.y += v.y; s.z += v.z; s.w += v.w;
    }
    __align__(8) __half hv[4];
    hv[0] = __float2half_rn(s.x); hv[1] = __float2half_rn(s.y);
    hv[2] = __float2half_rn(s.z); hv[3] = __float2half_rn(s.w);
    *(uint2*)(g_WFh + base) = *(uint2*)hv;
}

// ============================================================
// conv_all: merged fp32->fp16 conversions.
//   bid [0,576)            : [Wk|Wc] -> g_WBh
//   bid [576,600)          : gwhh    -> g_WHh
//   bid [600,600+36864)    : [memory|coverage] -> g_Af16
// ============================================================
__global__ void conv_all(const float* __restrict__ Wk, const float* __restrict__ Wc,
                         const float* __restrict__ gwhh,
                         const float* __restrict__ memory, const float* __restrict__ coverage)
{
    int bid = blockIdx.x;
    if (bid < 576) {
        long long t = (long long)bid * 256 + threadIdx.x;
        long long e = t * 8;
        int c = (int)(e % KC);
        long long r = e / KC;
        float4 v0, v1;
        if (c < KSd) { const float4* p = (const float4*)(Wk + r * KSd + c); v0 = p[0]; v1 = p[1]; }
        else         { const float4* p = (const float4*)(Wc + r * CSd + (c - KSd)); v0 = p[0]; v1 = p[1]; }
        float v[8] = {v0.x,v0.y,v0.z,v0.w,v1.x,v1.y,v1.z,v1.w};
        __align__(16) __half hv[8];
        #pragma unroll
        for (int j = 0; j < 8; ++j) hv[j] = __float2half_rn(v[j]);
        *(uint4*)(g_WBh + r * KC + c) = *(uint4*)hv;
    } else if (bid < 600) {
        long long t = (long long)(bid - 576) * 256 + threadIdx.x;
        long long e = t * 8;
        const float4* p = (const float4*)(gwhh + e);
        float4 v0 = p[0], v1 = p[1];
        float v[8] = {v0.x,v0.y,v0.z,v0.w,v1.x,v1.y,v1.z,v1.w};
        __align__(16) __half hv[8];
        #pragma unroll
        for (int j = 0; j < 8; ++j) hv[j] = __float2half_rn(v[j]);
        *(uint4*)(g_WHh + e) = *(uint4*)hv;
    } else {
        long long t = (long long)(bid - 600) * 256 + threadIdx.x;
        long long e = t * 8;
        int c = (int)(e % KC);
        long long r = e / KC;
        float4 v0, v1;
        if (c < KSd) { const float4* p = (const float4*)(memory + r * KSd + c); v0 = p[0]; v1 = p[1]; }
        else         { const float4* p = (const float4*)(coverage + r * CSd + (c - KSd)); v0 = p[0]; v1 = p[1]; }
        float v[8] = {v0.x,v0.y,v0.z,v0.w,v1.x,v1.y,v1.z,v1.w};
        __align__(16) __half hv[8];
        #pragma unroll
        for (int j = 0; j < 8; ++j) hv[j] = __float2half_rn(v[j]);
        *(uint4*)(g_Af16 + r * KC + c) = *(uint4*)hv;
    }
}

// ============================================================
// scores_k: fp16 GEMM 128x256, NSTG=4, epi tanh(.+g_q)·Wl -> g_part
// ============================================================
#define NT0   256
#define STG0  (uint32_t)(ATILE + NT0*SROW)   // 30720
#define DSM0  (4 * (int)STG0)                // 122880

__global__ __launch_bounds__(256)
void scores_k(const float* __restrict__ Wl)
{
    constexpr int NST = KC/32, NF = 8;
    extern __shared__ __align__(16) char dsm[];
    const uint32_t sbase = s2u(dsm);

    const int tid = threadIdx.x;
    const int wid = tid >> 5, lane = tid & 31;
    const int ct = blockIdx.x & 3, rt = blockIdx.x >> 2;
    const int row0 = rt * 128, col0 = ct * NT0;
    const int wm = (wid & 1) * 64;
    const int wn = (wid >> 1) * 64;

    auto load_stage = [&](int s, int stg) {
        const uint32_t sb = sbase + (uint32_t)stg * STG0;
        const int kc = s * 32;
        #pragma unroll
        for (int j = 0; j < 2; ++j) {
            int idx = tid + j*256;
            int r = idx >> 2, cu = idx & 3;
            CP16(sb + (uint32_t)(r*SROW + cu*16),
                 g_Af16 + (size_t)(row0 + r) * KC + kc + cu*8);
        }
        #pragma unroll
        for (int j = 0; j < 4; ++j) {
            int idx = tid + j*256;
            int r = idx >> 2, cu = idx & 3;
            CP16(sb + (uint32_t)ATILE + (uint32_t)(r*SROW + cu*16),
                 g_WBh + (size_t)(col0 + r) * KC + kc + cu*8);
        }
    };

    float acc[4][NF][4];
    #pragma unroll
    for (int i = 0; i < 4; ++i)
        #pragma unroll
        for (int j = 0; j < NF; ++j)
            #pragma unroll
            for (int k = 0; k < 4; ++k) acc[i][j][k] = 0.f;

    const int arow = wm + (lane & 7) + ((lane >> 3) & 1) * 8;
    const uint32_t akb = (uint32_t)(((lane >> 4) & 1) * 16);
    const int brow = wn + (lane & 7) + ((lane >> 4) & 1) * 8;
    const uint32_t bkb = (uint32_t)(((lane >> 3) & 1) * 16);

    #pragma unroll
    for (int i = 0; i < 3; ++i) { load_stage(i, i); CPCOMMIT(); }

    for (int s = 0; s < NST; ++s) {
        if (s + 3 < NST) { load_stage(s + 3, (s + 3) & 3); CPCOMMIT(); cpwait<3>(); }
        else             { cpwait<0>(); }
        __syncthreads();
        const uint32_t sb = sbase + (uint32_t)(s & 3) * STG0;
        #pragma unroll
        for (int kh = 0; kh < 2; ++kh) {
            const uint32_t ko = (uint32_t)(kh * 32);
            uint32_t a[4][4], b[NF][2];
            #pragma unroll
            for (int mi = 0; mi < 4; ++mi)
                ldsm4(a[mi], sb + (uint32_t)((arow + mi*16) * SROW) + ko + akb);
            #pragma unroll
            for (int ni = 0; ni < NF; ni += 2)
                ldsm4(&b[ni][0], sb + (uint32_t)ATILE + (uint32_t)((brow + ni*8) * SROW) + ko + bkb);
            #pragma unroll
            for (int mi = 0; mi < 4; ++mi)
                #pragma unroll
                for (int ni = 0; ni < NF; ++ni)
                    mmaf16(acc[mi][ni], a[mi], b[ni]);
        }
        __syncthreads();
    }

    const int gq4 = lane >> 2;
    const int q   = lane & 3;
    const int bIdx = row0 >> 11;

    float* red = (float*)dsm;
    float rowsum[4][2];
    #pragma unroll
    for (int mi = 0; mi < 4; ++mi)
        #pragma unroll
        for (int hf = 0; hf < 2; ++hf) {
            float s = 0.f;
            #pragma unroll
            for (int ni = 0; ni < NF; ++ni) {
                int c = col0 + wn + ni*8 + q*2;
                float v0 = acc[mi][ni][hf*2+0] + g_q[bIdx*Hd + c];
                float v1 = acc[mi][ni][hf*2+1] + g_q[bIdx*Hd + c + 1];
                s += tanhf(v0) * Wl[c] + tanhf(v1) * Wl[c+1];
            }
            s += __shfl_xor_sync(0xffffffffu, s, 1);
            s += __shfl_xor_sync(0xffffffffu, s, 2);
            rowsum[mi][hf] = s;
        }
    if (q == 0) {
        #pragma unroll
        for (int mi = 0; mi < 4; ++mi)
            #pragma unroll
            for (int hf = 0; hf < 2; ++hf) {
                int lr = wm + mi*16 + gq4 + hf*8;
                red[(wid >> 1) * 128 + lr] = rowsum[mi][hf];
            }
    }
    __syncthreads();
    if (tid < 128) {
        float s = red[tid] + red[128 + tid] + red[256 + tid] + red[384 + tid];
        g_part[(size_t)(row0 + tid) * 4 + ct] = s;
    }
}

// ============================================================
// postk: merged attns + gx + gh (one launch after softmax).
//   bid [0,128)           : attns (b=bid>>2, k window (bid&3)*256)
//   bid [128,128+1024)    : gx tile (NT=192, NCT=2)
//   bid [1152,1152+1024)  : gh tile (NT=192, NCT=2, K=128)
// ============================================================
#define NT1   192
#define STG1  (uint32_t)(ATILE + NT1*SROW)   // 25600
#define DSMP  (4 * (int)STG1)                // 102400

__global__ __launch_bounds__(256)
void postk(const float* __restrict__ memory, const float* __restrict__ w,
           float* __restrict__ out_attn, const float* __restrict__ gbhh)
{
    extern __shared__ __align__(16) char dsm[];
    const int tid = threadIdx.x;
    int bid = blockIdx.x;

    if (bid < 128) {
        // ---- attns ----
        float* ws = (float*)dsm;
        const int b = bid >> 2;
        const int k = (bid & 3) * 256 + tid;
        for (int i = tid; i < MM; i += 256) ws[i] = w[b*MM + i];
        __syncthreads();
        const float* mp = memory + (size_t)b * MM * KSd + k;
        float a0 = 0.f, a1 = 0.f, a2 = 0.f, a3 = 0.f;
        for (int m = 0; m < MM; m += 4) {
            a0 += ws[m+0] * mp[(size_t)(m+0) * KSd];
            a1 += ws[m+1] * mp[(size_t)(m+1) * KSd];
            a2 += ws[m+2] * mp[(size_t)(m+2) * KSd];
            a3 += ws[m+3] * mp[(size_t)(m+3) * KSd];
        }
        out_attn[b*KSd + k] = (a0 + a1) + (a2 + a3);
        return;
    }
    bid -= 128;
    const bool isGX = bid < 1024;
    if (!isGX) bid -= 1024;

    const __half* Bp = isGX ? g_WFh : g_WHh;
    const int BSTR = isGX ? KC : CSd;
    const int AOFF = isGX ? 0 : KSd;
    const int NST  = isGX ? (KC/32) : (CSd/32);

    const uint32_t sbase = s2u(dsm);
    const int wid = tid >> 5, lane = tid & 31;
    const int ct = bid & 1, rt = bid >> 1;
    const int row0 = rt * 128, col0 = ct * NT1;
    const int wm = (wid & 1) * 64;
    const int wn = (wid >> 1) * 48;

    auto load_stage = [&](int s, int stg) {
        const uint32_t sb = sbase + (uint32_t)stg * STG1;
        const int kc = s * 32;
        #pragma unroll
        for (int j = 0; j < 2; ++j) {
            int idx = tid + j*256;
            int r = idx >> 2, cu = idx & 3;
            CP16(sb + (uint32_t)(r*SROW + cu*16),
                 g_Af16 + (size_t)(row0 + r) * KC + AOFF + kc + cu*8);
        }
        #pragma unroll
        for (int j = 0; j < 3; ++j) {
            int idx = tid + j*256;
            int r = idx >> 2, cu = idx & 3;
            CP16(sb + (uint32_t)ATILE + (uint32_t)(r*SROW + cu*16),
                 Bp + (size_t)(col0 + r) * BSTR + kc + cu*8);
        }
    };

    float acc[4][6][4];
    #pragma unroll
    for (int i = 0; i < 4; ++i)
        #pragma unroll
        for (int j = 0; j < 6; ++j)
            #pragma unroll
            for (int k = 0; k < 4; ++k) acc[i][j][k] = 0.f;

    const int arow = wm + (lane & 7) + ((lane >> 3) & 1) * 8;
    const uint32_t akb = (uint32_t)(((lane >> 4) & 1) * 16);
    const int brow = wn + (lane & 7) + ((lane >> 4) & 1) * 8;
    const uint32_t bkb = (uint32_t)(((lane >> 3) & 1) * 16);

    for (int i = 0; i < 3; ++i) { load_stage(i, i); CPCOMMIT(); }

    for (int s = 0; s < NST; ++s) {
        if (s + 3 < NST) { load_stage(s + 3, (s + 3) & 3); CPCOMMIT(); cpwait<3>(); }
        else             { cpwait<0>(); }
        __syncthreads();
        const uint32_t sb = sbase + (uint32_t)(s & 3) * STG1;
        #pragma unroll
        for (int kh = 0; kh < 2; ++kh) {
            const uint32_t ko = (uint32_t)(kh * 32);
            uint32_t a[4][4], b[6][2];
            #pragma unroll
            for (int mi = 0; mi < 4; ++mi)
                ldsm4(a[mi], sb + (uint32_t)((arow + mi*16) * SROW) + ko + akb);
            #pragma unroll
            for (int ni = 0; ni < 6; ni += 2)
                ldsm4(&b[ni][0], sb + (uint32_t)ATILE + (uint32_t)((brow + ni*8) * SROW) + ko + bkb);
            #pragma unroll
            for (int mi = 0; mi < 4; ++mi)
                #pragma unroll
                for (int ni = 0; ni < 6; ++ni)
                    mmaf16(acc[mi][ni], a[mi], b[ni]);
        }
        __syncthreads();
    }

    const int gq4 = lane >> 2;
    const int q   = lane & 3;
    const int bIdx = row0 >> 11;

    if (isGX) {
        #pragma unroll
        for (int mi = 0; mi < 4; ++mi)
            #pragma unroll
            for (int hf = 0; hf < 2; ++hf) {
                int r = row0 + wm + mi*16 + gq4 + hf*8;
                float wr = w[r];
                #pragma unroll
                for (int ni = 0; ni < 6; ++ni) {
                    int c = col0 + wn + ni*8 + q*2;
                    float2 v;
                    v.x = acc[mi][ni][hf*2+0] + g_qg2[bIdx*G3 + c  ] + wr * g_av[c  ];
                    v.y = acc[mi][ni][hf*2+1] + g_qg2[bIdx*G3 + c+1] + wr * g_av[c+1];
                    *(float2*)(g_GX + (size_t)r * G3 + c) = v;
                }
            }
    } else {
        #pragma unroll
        for (int mi = 0; mi < 4; ++mi)
            #pragma unroll
            for (int hf = 0; hf < 2; ++hf) {
                int r = row0 + wm + mi*16 + gq4 + hf*8;
                #pragma unroll
                for (int ni = 0; ni < 6; ++ni) {
                    int c = col0 + wn + ni*8 + q*2;
                    float2 v;
                    v.x = acc[mi][ni][hf*2+0] + gbhh[c  ];
                    v.y = acc[mi][ni][hf*2+1] + gbhh[c+1];
                    *(float2*)(g_GH + (size_t)r * G3 + c) = v;
                }
            }
    }
}

// ============================================================
// masked softmax from 4 fixed-order partials + bl (flag-based dtype)
// ============================================================
__global__ void softmax_k(const void* __restrict__ maskp, const float* __restrict__ bl,
                          float* __restrict__ wout)
{
    __shared__ float sv[MM];
    __shared__ float red[256];
    const int b = blockIdx.x;
    const int tid = threadIdx.x;
    const bool isI32 = (g_isI32 != 0);
    const unsigned char* mbp = (const unsigned char*)maskp;

    const float blv = bl[0];
    for (int m = tid; m < MM; m += 256) {
        bool pad = isI32 ? (((const int*)maskp)[b*MM + m] != 0)
                         : (mbp[b*MM + m] != 0);
        if (pad) sv[m] = -1e30f;
        else {
            const float* p = g_part + (size_t)(b*MM + m) * 4;
            sv[m] = (p[0] + p[1]) + (p[2] + p[3]) + blv;
        }
    }
    __syncthreads();

    float mx = -3.4e38f;
    for (int m = tid; m < MM; m += 256) mx = fmaxf(mx, sv[m]);
    red[tid] = mx;
    __syncthreads();
    for (int s = 128; s; s >>= 1) { if (tid < s) red[tid] = fmaxf(red[tid], red[tid + s]); __syncthreads(); }
    mx = red[0];
    __syncthreads();

    float sum = 0.f;
    for (int m = tid; m < MM; m += 256) { float e = expf(sv[m] - mx); sv[m] = e; sum += e; }
    red[tid] = sum;
    __syncthreads();
    for (int s = 128; s; s >>= 1) { if (tid < s) red[tid] += red[tid + s]; __syncthreads(); }
    float inv = 1.f / red[0];
    __syncthreads();

    for (int m = tid; m < MM; m += 256) wout[b*MM + m] = sv[m] * inv;
}

// ============================================================
// GRU elementwise
// ============================================================
__global__ void gru_k(const float* __restrict__ coverage, float* __restrict__ outc)
{
    size_t idx = (size_t)blockIdx.x * 256 + threadIdx.x;
    int r = (int)(idx >> 7);
    int c = (int)(idx & 127);
    size_t gi = (size_t)r * G3 + c;
    float xr = g_GX[gi],       hr = g_GH[gi];
    float xz = g_GX[gi + 128], hz = g_GH[gi + 128];
    float xn = g_GX[gi + 256], hn = g_GH[gi + 256];
    float rg = 1.f / (1.f + expf(-(xr + hr)));
    float z  = 1.f / (1.f + expf(-(xz + hz)));
    float n  = tanhf(xn + rg * hn);
    outc[idx] = (1.f - z) * n + z * coverage[idx];
}

// ============================================================
extern "C" void kernel_launch(void* const* d_in, const int* in_sizes, int n_in,
                              void* d_out, int out_size)
{
    const float* query   = (const float*)d_in[0];
    const float* memory  = (const float*)d_in[1];
    const float* coverage= (const float*)d_in[2];
    const float* Wq  = (const float*)d_in[3];  const float* bq  = (const float*)d_in[4];
    const float* Wk  = (const float*)d_in[5];  const float* bk  = (const float*)d_in[6];
    const float* Wc  = (const float*)d_in[7];  const float* bc  = (const float*)d_in[8];
    const float* Wcc = (const float*)d_in[9];  const float* bcc = (const float*)d_in[10];
    const float* Wqc = (const float*)d_in[11]; const float* bqc = (const float*)d_in[12];
    const float* Wkc = (const float*)d_in[13]; const float* bkc = (const float*)d_in[14];
    const float* Wac = (const float*)d_in[15]; const float* bac = (const float*)d_in[16];
    const float* Wl  = (const float*)d_in[17]; const float* bl  = (const float*)d_in[18];
    const float* gwih= (const float*)d_in[19]; const float* gbih= (const float*)d_in[20];
    const float* gwhh= (const float*)d_in[21]; const float* gbhh= (const float*)d_in[22];
    const void*  maskp = d_in[23];

    float* out      = (float*)d_out;
    float* out_attn = out;
    float* out_w    = out + BB*KSd;
    float* out_cov  = out + BB*KSd + BB*MM;

    static int attr_done = 0;
    if (!attr_done) {
        cudaFuncSetAttribute((const void*)scores_k, cudaFuncAttributeMaxDynamicSharedMemorySize, DSM0);
        cudaFuncSetAttribute((const void*)postk,    cudaFuncAttributeMaxDynamicSharedMemorySize, DSMP);
        attr_done = 1;
    }

    // prep
    mask_detect<<<1, 1024>>>(maskp);
    qprep<<<(BB*Hd)/8, 256>>>(query, Wq, bq, bk, bc, Wqc, bqc, bkc, bcc, bac);
    wfuse_part<<<216, 256>>>(Wkc, Wcc, gwih);
    conv_all<<<600 + 36864, 256>>>(Wk, Wc, gwhh, memory, coverage);
    prep2<<<(33*G3*32 + 255)/256, 256>>>(gwih, gbih, Wac);
    wfuse_reduce<<<432, 256>>>();

    // scores (fp16, 128x256 tiles) -> partials
    scores_k<<<(RR/128)*4, 256, DSM0>>>(Wl);

    // softmax -> weights
    softmax_k<<<BB, 256>>>(maskp, bl, out_w);

    // attns + gx + gh merged
    postk<<<128 + 2*(RR/128)*2, 256, DSMP>>>(memory, out_w, out_attn, gbhh);

    // GRU elementwise -> new_coverage
    gru_k<<<(RR*CSd)/256, 256>>>(coverage, out_cov);
}